// round 2
// baseline (speedup 1.0000x reference)
#include <cuda_runtime.h>
#include <cstdint>

#define B_DIM 2
#define S_DIM 1024
#define E_DIM 1024
#define MH    16
#define DH    64
#define E3    3072

// Scratch (no cudaMalloc allowed): qkv activations + per-head attention output
__device__ float g_qkv[B_DIM * S_DIM * E3];        // [B*S, 3E]
__device__ float g_headout[B_DIM * S_DIM * E_DIM]; // [B*S, E]

// ---------------------------------------------------------------------------
// SGEMM:  C[M,N] = A[M,K] @ W[N,K]^T   (fp32, 128x128x8 tile, 8x8 microtile)
// ---------------------------------------------------------------------------
__global__ __launch_bounds__(256) void sgemm_nt(
    const float* __restrict__ A, const float* __restrict__ W,
    float* __restrict__ C, int Mn, int Nn, int Kn)
{
    const int BM = 128, BN = 128, BK = 8;
    __shared__ float As[BK][BM];
    __shared__ float Bs[BK][BN];

    int tid  = threadIdx.x;          // 0..255
    int tx   = tid & 15;             // 16 cols of microtiles
    int ty   = tid >> 4;             // 16 rows of microtiles
    int row0 = blockIdx.y * BM;
    int col0 = blockIdx.x * BN;

    int lr = tid >> 1;               // 0..127
    int lc = (tid & 1) * 4;          // 0 or 4
    const float* Ag = A + (size_t)(row0 + lr) * Kn + lc;
    const float* Wg = W + (size_t)(col0 + lr) * Kn + lc;

    float acc[8][8];
#pragma unroll
    for (int i = 0; i < 8; i++)
#pragma unroll
        for (int j = 0; j < 8; j++) acc[i][j] = 0.0f;

    for (int k0 = 0; k0 < Kn; k0 += BK) {
        float4 av = *(const float4*)(Ag + k0);
        float4 wv = *(const float4*)(Wg + k0);
        As[lc + 0][lr] = av.x; As[lc + 1][lr] = av.y;
        As[lc + 2][lr] = av.z; As[lc + 3][lr] = av.w;
        Bs[lc + 0][lr] = wv.x; Bs[lc + 1][lr] = wv.y;
        Bs[lc + 2][lr] = wv.z; Bs[lc + 3][lr] = wv.w;
        __syncthreads();

#pragma unroll
        for (int k = 0; k < BK; k++) {
            float4 a0 = *(const float4*)&As[k][ty * 8];
            float4 a1 = *(const float4*)&As[k][ty * 8 + 4];
            float4 b0 = *(const float4*)&Bs[k][tx * 8];
            float4 b1 = *(const float4*)&Bs[k][tx * 8 + 4];
            float a[8] = {a0.x, a0.y, a0.z, a0.w, a1.x, a1.y, a1.z, a1.w};
            float b[8] = {b0.x, b0.y, b0.z, b0.w, b1.x, b1.y, b1.z, b1.w};
#pragma unroll
            for (int i = 0; i < 8; i++)
#pragma unroll
                for (int j = 0; j < 8; j++)
                    acc[i][j] = fmaf(a[i], b[j], acc[i][j]);
        }
        __syncthreads();
    }

#pragma unroll
    for (int i = 0; i < 8; i++) {
        float* crow = C + (size_t)(row0 + ty * 8 + i) * Nn + col0 + tx * 8;
        *(float4*)(crow)     = make_float4(acc[i][0], acc[i][1], acc[i][2], acc[i][3]);
        *(float4*)(crow + 4) = make_float4(acc[i][4], acc[i][5], acc[i][6], acc[i][7]);
    }
}

// ---------------------------------------------------------------------------
// Fused attention: per (b, head, 64-query block)
//   - online softmax over key tiles of 64
//   - writes sigmoid(att) side output (exact zeros above causal diag / masked)
//   - accumulates P@V into head-major output [B,S,E]
//   - masks are int32 (harness converts jnp bool -> int32)
// ---------------------------------------------------------------------------
__global__ __launch_bounds__(256) void flash_kernel(
    const float* __restrict__ qkv,
    const int* __restrict__ mask_head,
    const int* __restrict__ mask_child,
    float* __restrict__ arc,
    float* __restrict__ headout)
{
    extern __shared__ float sm[];
    const int PAD = 65;
    float* Qs = sm;
    float* Ks = Qs + 64 * PAD;
    float* Vs = Ks + 64 * PAD;
    float* Ps = Vs + 64 * PAD;

    int tid = threadIdx.x;
    int tx = tid & 15, ty = tid >> 4;
    int bh = blockIdx.y;             // b*16 + h
    int b = bh >> 4, h = bh & 15;
    int qi0 = blockIdx.x * 64;

    const int* maskp =
        ((h < 8) ? mask_head : mask_child) + (size_t)b * S_DIM * S_DIM;
    const float* qb = qkv + (size_t)b * S_DIM * E3 + h * DH;
    const float* kb = qb + E_DIM;
    const float* vb = qb + 2 * E_DIM;
    float* arcb = arc + ((size_t)bh * S_DIM + qi0) * S_DIM;

    // Load Q tile, pre-scaled by 1/d (ref scales by d^-0.5 twice => 1/64)
    {
        int r = tid >> 4;
        int c = (tid & 15) << 2;
#pragma unroll
        for (int rr = 0; rr < 64; rr += 16) {
            float4 v = *(const float4*)(qb + (size_t)(qi0 + r + rr) * E3 + c);
            float* d = Qs + (r + rr) * PAD + c;
            const float sc = 1.0f / 64.0f;
            d[0] = v.x * sc; d[1] = v.y * sc; d[2] = v.z * sc; d[3] = v.w * sc;
        }
    }

    float m_[4], l_[4], acc[4][4];
#pragma unroll
    for (int i = 0; i < 4; i++) {
        m_[i] = -1e30f; l_[i] = 0.0f;
#pragma unroll
        for (int j = 0; j < 4; j++) acc[i][j] = 0.0f;
    }
    int r0 = ty * 4, c0 = tx * 4;
    int lastTile = qi0 >> 6;

    for (int kj = 0; kj < S_DIM / 64; kj++) {
        int j0 = kj * 64;
        if (kj > lastTile) {
            // fully above causal diagonal: sigmoid(-inf) = 0 exactly
            float4 z = make_float4(0.f, 0.f, 0.f, 0.f);
#pragma unroll
            for (int i = 0; i < 4; i++)
                *(float4*)(arcb + (size_t)(r0 + i) * S_DIM + j0 + c0) = z;
            continue;
        }

        __syncthreads();   // protect Ks/Vs from previous PV readers
        {
            int r = tid >> 4;
            int c = (tid & 15) << 2;
#pragma unroll
            for (int rr = 0; rr < 64; rr += 16) {
                float4 kv = *(const float4*)(kb + (size_t)(j0 + r + rr) * E3 + c);
                float4 vv = *(const float4*)(vb + (size_t)(j0 + r + rr) * E3 + c);
                float* kd = Ks + (r + rr) * PAD + c;
                kd[0] = kv.x; kd[1] = kv.y; kd[2] = kv.z; kd[3] = kv.w;
                float* vd = Vs + (r + rr) * PAD + c;
                vd[0] = vv.x; vd[1] = vv.y; vd[2] = vv.z; vd[3] = vv.w;
            }
        }
        __syncthreads();

        // S = Q @ K^T  (4x4 microtile per thread)
        float s[4][4];
#pragma unroll
        for (int i = 0; i < 4; i++)
#pragma unroll
            for (int j = 0; j < 4; j++) s[i][j] = 0.0f;
#pragma unroll 8
        for (int k = 0; k < 64; k++) {
            float a0 = Qs[(r0 + 0) * PAD + k];
            float a1 = Qs[(r0 + 1) * PAD + k];
            float a2 = Qs[(r0 + 2) * PAD + k];
            float a3 = Qs[(r0 + 3) * PAD + k];
            float b0 = Ks[(c0 + 0) * PAD + k];
            float b1 = Ks[(c0 + 1) * PAD + k];
            float b2 = Ks[(c0 + 2) * PAD + k];
            float b3 = Ks[(c0 + 3) * PAD + k];
            s[0][0] = fmaf(a0, b0, s[0][0]); s[0][1] = fmaf(a0, b1, s[0][1]);
            s[0][2] = fmaf(a0, b2, s[0][2]); s[0][3] = fmaf(a0, b3, s[0][3]);
            s[1][0] = fmaf(a1, b0, s[1][0]); s[1][1] = fmaf(a1, b1, s[1][1]);
            s[1][2] = fmaf(a1, b2, s[1][2]); s[1][3] = fmaf(a1, b3, s[1][3]);
            s[2][0] = fmaf(a2, b0, s[2][0]); s[2][1] = fmaf(a2, b1, s[2][1]);
            s[2][2] = fmaf(a2, b2, s[2][2]); s[2][3] = fmaf(a2, b3, s[2][3]);
            s[3][0] = fmaf(a3, b0, s[3][0]); s[3][1] = fmaf(a3, b1, s[3][1]);
            s[3][2] = fmaf(a3, b2, s[3][2]); s[3][3] = fmaf(a3, b3, s[3][3]);
        }

        // mask (causal + tag mask, int32), arc side-output, row max
        float mt[4];
#pragma unroll
        for (int i = 0; i < 4; i++) {
            int ig = qi0 + r0 + i;
            int4 mk = *(const int4*)(maskp + (size_t)ig * S_DIM + j0 + c0);
            int mm[4] = {mk.x, mk.y, mk.z, mk.w};
#pragma unroll
            for (int j = 0; j < 4; j++) {
                int jg = j0 + c0 + j;
                bool valid = (jg <= ig) && (mm[j] != 0);
                if (!valid) s[i][j] = -1e30f;
            }
            float4 sg;
            sg.x = 1.0f / (1.0f + __expf(-s[i][0]));
            sg.y = 1.0f / (1.0f + __expf(-s[i][1]));
            sg.z = 1.0f / (1.0f + __expf(-s[i][2]));
            sg.w = 1.0f / (1.0f + __expf(-s[i][3]));
            *(float4*)(arcb + (size_t)(r0 + i) * S_DIM + j0 + c0) = sg;
            mt[i] = fmaxf(fmaxf(s[i][0], s[i][1]), fmaxf(s[i][2], s[i][3]));
        }
        // row-max across the 16 lanes sharing the same row group
#pragma unroll
        for (int off = 8; off >= 1; off >>= 1) {
#pragma unroll
            for (int i = 0; i < 4; i++)
                mt[i] = fmaxf(mt[i], __shfl_xor_sync(0xffffffffu, mt[i], off));
        }

        // online softmax update + write P to smem
#pragma unroll
        for (int i = 0; i < 4; i++) {
            float mn = fmaxf(m_[i], mt[i]);
            float sc = __expf(m_[i] - mn);
            float rs = 0.0f;
#pragma unroll
            for (int j = 0; j < 4; j++) {
                float p = __expf(s[i][j] - mn);
                Ps[(r0 + i) * PAD + c0 + j] = p;
                rs += p;
            }
#pragma unroll
            for (int off = 8; off >= 1; off >>= 1)
                rs += __shfl_xor_sync(0xffffffffu, rs, off);
            l_[i] = l_[i] * sc + rs;
            m_[i] = mn;
            acc[i][0] *= sc; acc[i][1] *= sc; acc[i][2] *= sc; acc[i][3] *= sc;
        }
        __syncthreads();   // Ps visible

        // acc += P @ V
#pragma unroll 8
        for (int k = 0; k < 64; k++) {
            float p0 = Ps[(r0 + 0) * PAD + k];
            float p1 = Ps[(r0 + 1) * PAD + k];
            float p2 = Ps[(r0 + 2) * PAD + k];
            float p3 = Ps[(r0 + 3) * PAD + k];
            float v0 = Vs[k * PAD + c0 + 0];
            float v1 = Vs[k * PAD + c0 + 1];
            float v2 = Vs[k * PAD + c0 + 2];
            float v3 = Vs[k * PAD + c0 + 3];
            acc[0][0] = fmaf(p0, v0, acc[0][0]); acc[0][1] = fmaf(p0, v1, acc[0][1]);
            acc[0][2] = fmaf(p0, v2, acc[0][2]); acc[0][3] = fmaf(p0, v3, acc[0][3]);
            acc[1][0] = fmaf(p1, v0, acc[1][0]); acc[1][1] = fmaf(p1, v1, acc[1][1]);
            acc[1][2] = fmaf(p1, v2, acc[1][2]); acc[1][3] = fmaf(p1, v3, acc[1][3]);
            acc[2][0] = fmaf(p2, v0, acc[2][0]); acc[2][1] = fmaf(p2, v1, acc[2][1]);
            acc[2][2] = fmaf(p2, v2, acc[2][2]); acc[2][3] = fmaf(p2, v3, acc[2][3]);
            acc[3][0] = fmaf(p3, v0, acc[3][0]); acc[3][1] = fmaf(p3, v1, acc[3][1]);
            acc[3][2] = fmaf(p3, v2, acc[3][2]); acc[3][3] = fmaf(p3, v3, acc[3][3]);
        }
    }

    // epilogue: O = acc / l, stored head-major into [B,S,E]
#pragma unroll
    for (int i = 0; i < 4; i++) {
        float inv = (l_[i] > 0.0f) ? (1.0f / l_[i]) : 0.0f;
        float4 o = make_float4(acc[i][0] * inv, acc[i][1] * inv,
                               acc[i][2] * inv, acc[i][3] * inv);
        *(float4*)(headout + ((size_t)b * S_DIM + qi0 + r0 + i) * E_DIM + h * DH + c0) = o;
    }
}

// ---------------------------------------------------------------------------
extern "C" void kernel_launch(void* const* d_in, const int* in_sizes, int n_in,
                              void* d_out, int out_size)
{
    const float* x       = (const float*)d_in[0];
    const float* w_qkv   = (const float*)d_in[1];
    const float* w_proj  = (const float*)d_in[2];
    const int* mask_head  = (const int*)d_in[3];
    const int* mask_child = (const int*)d_in[4];

    float* out = (float*)d_out;                               // [B,S,E]
    float* arc = out + (size_t)B_DIM * S_DIM * E_DIM;         // [B,M,H,S,S]

    float* qkvbuf = nullptr;
    float* hout   = nullptr;
    cudaGetSymbolAddress((void**)&qkvbuf, g_qkv);
    cudaGetSymbolAddress((void**)&hout, g_headout);

    // 1) qkv = x @ w_qkv^T   [2048 x 3072 x 1024]
    {
        dim3 grid(E3 / 128, (B_DIM * S_DIM) / 128);
        sgemm_nt<<<grid, 256>>>(x, w_qkv, qkvbuf, B_DIM * S_DIM, E3, E_DIM);
    }

    // 2) fused attention + sigmoid side output
    {
        size_t smem = 4u * 64u * 65u * sizeof(float);  // 66,560 B
        cudaFuncSetAttribute(flash_kernel,
                             cudaFuncAttributeMaxDynamicSharedMemorySize, (int)smem);
        dim3 grid(S_DIM / 64, B_DIM * MH);
        flash_kernel<<<grid, 256, smem>>>(qkvbuf, mask_head, mask_child, arc, hout);
    }

    // 3) out = headout @ w_proj^T   [2048 x 1024 x 1024]
    {
        dim3 grid(E_DIM / 128, (B_DIM * S_DIM) / 128);
        sgemm_nt<<<grid, 256>>>(hout, w_proj, out, B_DIM * S_DIM, E_DIM, E_DIM);
    }
}

// round 4
// speedup vs baseline: 1.4597x; 1.4597x over previous
#include <cuda_runtime.h>
#include <cuda_bf16.h>
#include <cstdint>

#define B_DIM 2
#define S_DIM 1024
#define E_DIM 1024
#define MH    16
#define DH    64
#define E3    3072

// Scratch (no cudaMalloc allowed)
__device__ float g_qkv[B_DIM * S_DIM * E3];        // [B*S, 3E]
__device__ float g_headout[B_DIM * S_DIM * E_DIM]; // [B*S, E]

__device__ __forceinline__ uint32_t pack_bf2(__nv_bfloat16 lo, __nv_bfloat16 hi) {
    return (uint32_t)__bfloat16_as_ushort(lo) | ((uint32_t)__bfloat16_as_ushort(hi) << 16);
}

__device__ __forceinline__ void mma16816(float* d, const uint32_t* a,
                                         uint32_t b0, uint32_t b1) {
    asm volatile(
        "mma.sync.aligned.m16n8k16.row.col.f32.bf16.bf16.f32 "
        "{%0,%1,%2,%3}, {%4,%5,%6,%7}, {%8,%9}, {%0,%1,%2,%3};"
        : "+f"(d[0]), "+f"(d[1]), "+f"(d[2]), "+f"(d[3])
        : "r"(a[0]), "r"(a[1]), "r"(a[2]), "r"(a[3]), "r"(b0), "r"(b1));
}

// Split one float4 into hi/lo bf16 pairs and store 8B each
__device__ __forceinline__ void split_store(float4 v, char* hi, char* lo) {
    __nv_bfloat16 h0 = __float2bfloat16(v.x);
    __nv_bfloat16 h1 = __float2bfloat16(v.y);
    __nv_bfloat16 h2 = __float2bfloat16(v.z);
    __nv_bfloat16 h3 = __float2bfloat16(v.w);
    __nv_bfloat16 l0 = __float2bfloat16(v.x - __bfloat162float(h0));
    __nv_bfloat16 l1 = __float2bfloat16(v.y - __bfloat162float(h1));
    __nv_bfloat16 l2 = __float2bfloat16(v.z - __bfloat162float(h2));
    __nv_bfloat16 l3 = __float2bfloat16(v.w - __bfloat162float(h3));
    *(uint2*)hi = make_uint2(pack_bf2(h0, h1), pack_bf2(h2, h3));
    *(uint2*)lo = make_uint2(pack_bf2(l0, l1), pack_bf2(l2, l3));
}

// ---------------------------------------------------------------------------
// HMMA GEMM: C[M,N] = A[M,K] @ W[N,K]^T  (fp32 via 2-term bf16 split)
// CTA 128x128, 8 warps (4x2), warp tile 32x64, K chunk 64.
// SMEM rows padded to 144 bytes (72 bf16) -> conflict-free fragment loads.
// ---------------------------------------------------------------------------
#define RSTR 144
#define TSZ  (128 * RSTR)

__global__ __launch_bounds__(256) void gemm_mma(
    const float* __restrict__ A, const float* __restrict__ W,
    float* __restrict__ C, int Nn, int Kn)
{
    extern __shared__ char smem[];
    char* Ah = smem;
    char* Al = smem + TSZ;
    char* Bh = smem + 2 * TSZ;
    char* Bl = smem + 3 * TSZ;

    int tid = threadIdx.x;
    int lane = tid & 31, wid = tid >> 5;
    int wm = wid >> 1, wn = wid & 1;          // warp grid 4x2
    int g = lane >> 2, t = lane & 3;
    int row0 = blockIdx.y * 128;
    int col0 = blockIdx.x * 128;

    float acc[2][8][4];
#pragma unroll
    for (int mt = 0; mt < 2; mt++)
#pragma unroll
        for (int j = 0; j < 8; j++)
#pragma unroll
            for (int q = 0; q < 4; q++) acc[mt][j][q] = 0.0f;

    int r  = tid >> 1;            // 0..127
    int ch = (tid & 1) * 32;      // 0 or 32
    const float* Ag = A + (size_t)(row0 + r) * Kn + ch;
    const float* Wg = W + (size_t)(col0 + r) * Kn + ch;

    int nChunks = Kn >> 6;
    for (int c = 0; c < nChunks; c++) {
        // -------- fill SMEM (convert fp32 -> bf16 hi/lo) --------
#pragma unroll
        for (int i = 0; i < 8; i++) {
            int cc = ch + i * 4;
            int off = r * RSTR + cc * 2;
            split_store(*(const float4*)(Ag + c * 64 + i * 4), Ah + off, Al + off);
            split_store(*(const float4*)(Wg + c * 64 + i * 4), Bh + off, Bl + off);
        }
        __syncthreads();

        // -------- compute: 4 k16 steps --------
#pragma unroll
        for (int ks = 0; ks < 4; ks++) {
            int kb = (ks * 16 + t * 2) * 2;   // byte offset of this thread's k pair

            uint32_t ah[2][4], al[2][4];
#pragma unroll
            for (int mt = 0; mt < 2; mt++) {
                int ar = wm * 32 + mt * 16 + g;
                const char* ba = Ah + ar * RSTR + kb;
                ah[mt][0] = *(const uint32_t*)(ba);
                ah[mt][1] = *(const uint32_t*)(ba + 8 * RSTR);
                ah[mt][2] = *(const uint32_t*)(ba + 16);
                ah[mt][3] = *(const uint32_t*)(ba + 8 * RSTR + 16);
                const char* bl_ = Al + ar * RSTR + kb;
                al[mt][0] = *(const uint32_t*)(bl_);
                al[mt][1] = *(const uint32_t*)(bl_ + 8 * RSTR);
                al[mt][2] = *(const uint32_t*)(bl_ + 16);
                al[mt][3] = *(const uint32_t*)(bl_ + 8 * RSTR + 16);
            }
#pragma unroll
            for (int j = 0; j < 8; j++) {
                int br = wn * 64 + j * 8 + g;
                const char* bb = Bh + br * RSTR + kb;
                uint32_t bh0 = *(const uint32_t*)(bb);
                uint32_t bh1 = *(const uint32_t*)(bb + 16);
                const char* bc = Bl + br * RSTR + kb;
                uint32_t bl0 = *(const uint32_t*)(bc);
                uint32_t bl1 = *(const uint32_t*)(bc + 16);

                mma16816(acc[0][j], ah[0], bh0, bh1);
                mma16816(acc[1][j], ah[1], bh0, bh1);
                mma16816(acc[0][j], ah[0], bl0, bl1);
                mma16816(acc[1][j], ah[1], bl0, bl1);
                mma16816(acc[0][j], al[0], bh0, bh1);
                mma16816(acc[1][j], al[1], bh0, bh1);
            }
        }
        __syncthreads();
    }

    // -------- epilogue --------
#pragma unroll
    for (int mt = 0; mt < 2; mt++) {
        int rr = row0 + wm * 32 + mt * 16 + g;
#pragma unroll
        for (int j = 0; j < 8; j++) {
            int cc = col0 + wn * 64 + j * 8 + t * 2;
            *(float2*)(C + (size_t)rr * Nn + cc) =
                make_float2(acc[mt][j][0], acc[mt][j][1]);
            *(float2*)(C + (size_t)(rr + 8) * Nn + cc) =
                make_float2(acc[mt][j][2], acc[mt][j][3]);
        }
    }
}

// ---------------------------------------------------------------------------
// Fused attention (unchanged from R2 passing version)
// ---------------------------------------------------------------------------
__global__ __launch_bounds__(256) void flash_kernel(
    const float* __restrict__ qkv,
    const int* __restrict__ mask_head,
    const int* __restrict__ mask_child,
    float* __restrict__ arc,
    float* __restrict__ headout)
{
    extern __shared__ float sm[];
    const int PAD = 65;
    float* Qs = sm;
    float* Ks = Qs + 64 * PAD;
    float* Vs = Ks + 64 * PAD;
    float* Ps = Vs + 64 * PAD;

    int tid = threadIdx.x;
    int tx = tid & 15, ty = tid >> 4;
    int bh = blockIdx.y;
    int b = bh >> 4, h = bh & 15;
    int qi0 = blockIdx.x * 64;

    const int* maskp =
        ((h < 8) ? mask_head : mask_child) + (size_t)b * S_DIM * S_DIM;
    const float* qb = qkv + (size_t)b * S_DIM * E3 + h * DH;
    const float* kb = qb + E_DIM;
    const float* vb = qb + 2 * E_DIM;
    float* arcb = arc + ((size_t)bh * S_DIM + qi0) * S_DIM;

    {
        int r = tid >> 4;
        int c = (tid & 15) << 2;
#pragma unroll
        for (int rr = 0; rr < 64; rr += 16) {
            float4 v = *(const float4*)(qb + (size_t)(qi0 + r + rr) * E3 + c);
            float* d = Qs + (r + rr) * PAD + c;
            const float sc = 1.0f / 64.0f;
            d[0] = v.x * sc; d[1] = v.y * sc; d[2] = v.z * sc; d[3] = v.w * sc;
        }
    }

    float m_[4], l_[4], acc[4][4];
#pragma unroll
    for (int i = 0; i < 4; i++) {
        m_[i] = -1e30f; l_[i] = 0.0f;
#pragma unroll
        for (int j = 0; j < 4; j++) acc[i][j] = 0.0f;
    }
    int r0 = ty * 4, c0 = tx * 4;
    int lastTile = qi0 >> 6;

    for (int kj = 0; kj < S_DIM / 64; kj++) {
        int j0 = kj * 64;
        if (kj > lastTile) {
            float4 z = make_float4(0.f, 0.f, 0.f, 0.f);
#pragma unroll
            for (int i = 0; i < 4; i++)
                *(float4*)(arcb + (size_t)(r0 + i) * S_DIM + j0 + c0) = z;
            continue;
        }

        __syncthreads();
        {
            int r = tid >> 4;
            int c = (tid & 15) << 2;
#pragma unroll
            for (int rr = 0; rr < 64; rr += 16) {
                float4 kv = *(const float4*)(kb + (size_t)(j0 + r + rr) * E3 + c);
                float4 vv = *(const float4*)(vb + (size_t)(j0 + r + rr) * E3 + c);
                float* kd = Ks + (r + rr) * PAD + c;
                kd[0] = kv.x; kd[1] = kv.y; kd[2] = kv.z; kd[3] = kv.w;
                float* vd = Vs + (r + rr) * PAD + c;
                vd[0] = vv.x; vd[1] = vv.y; vd[2] = vv.z; vd[3] = vv.w;
            }
        }
        __syncthreads();

        float s[4][4];
#pragma unroll
        for (int i = 0; i < 4; i++)
#pragma unroll
            for (int j = 0; j < 4; j++) s[i][j] = 0.0f;
#pragma unroll 8
        for (int k = 0; k < 64; k++) {
            float a0 = Qs[(r0 + 0) * PAD + k];
            float a1 = Qs[(r0 + 1) * PAD + k];
            float a2 = Qs[(r0 + 2) * PAD + k];
            float a3 = Qs[(r0 + 3) * PAD + k];
            float b0 = Ks[(c0 + 0) * PAD + k];
            float b1 = Ks[(c0 + 1) * PAD + k];
            float b2 = Ks[(c0 + 2) * PAD + k];
            float b3 = Ks[(c0 + 3) * PAD + k];
            s[0][0] = fmaf(a0, b0, s[0][0]); s[0][1] = fmaf(a0, b1, s[0][1]);
            s[0][2] = fmaf(a0, b2, s[0][2]); s[0][3] = fmaf(a0, b3, s[0][3]);
            s[1][0] = fmaf(a1, b0, s[1][0]); s[1][1] = fmaf(a1, b1, s[1][1]);
            s[1][2] = fmaf(a1, b2, s[1][2]); s[1][3] = fmaf(a1, b3, s[1][3]);
            s[2][0] = fmaf(a2, b0, s[2][0]); s[2][1] = fmaf(a2, b1, s[2][1]);
            s[2][2] = fmaf(a2, b2, s[2][2]); s[2][3] = fmaf(a2, b3, s[2][3]);
            s[3][0] = fmaf(a3, b0, s[3][0]); s[3][1] = fmaf(a3, b1, s[3][1]);
            s[3][2] = fmaf(a3, b2, s[3][2]); s[3][3] = fmaf(a3, b3, s[3][3]);
        }

        float mt[4];
#pragma unroll
        for (int i = 0; i < 4; i++) {
            int ig = qi0 + r0 + i;
            int4 mk = *(const int4*)(maskp + (size_t)ig * S_DIM + j0 + c0);
            int mm[4] = {mk.x, mk.y, mk.z, mk.w};
#pragma unroll
            for (int j = 0; j < 4; j++) {
                int jg = j0 + c0 + j;
                bool valid = (jg <= ig) && (mm[j] != 0);
                if (!valid) s[i][j] = -1e30f;
            }
            float4 sg;
            sg.x = 1.0f / (1.0f + __expf(-s[i][0]));
            sg.y = 1.0f / (1.0f + __expf(-s[i][1]));
            sg.z = 1.0f / (1.0f + __expf(-s[i][2]));
            sg.w = 1.0f / (1.0f + __expf(-s[i][3]));
            *(float4*)(arcb + (size_t)(r0 + i) * S_DIM + j0 + c0) = sg;
            mt[i] = fmaxf(fmaxf(s[i][0], s[i][1]), fmaxf(s[i][2], s[i][3]));
        }
#pragma unroll
        for (int off = 8; off >= 1; off >>= 1) {
#pragma unroll
            for (int i = 0; i < 4; i++)
                mt[i] = fmaxf(mt[i], __shfl_xor_sync(0xffffffffu, mt[i], off));
        }

#pragma unroll
        for (int i = 0; i < 4; i++) {
            float mn = fmaxf(m_[i], mt[i]);
            float sc = __expf(m_[i] - mn);
            float rs = 0.0f;
#pragma unroll
            for (int j = 0; j < 4; j++) {
                float p = __expf(s[i][j] - mn);
                Ps[(r0 + i) * PAD + c0 + j] = p;
                rs += p;
            }
#pragma unroll
            for (int off = 8; off >= 1; off >>= 1)
                rs += __shfl_xor_sync(0xffffffffu, rs, off);
            l_[i] = l_[i] * sc + rs;
            m_[i] = mn;
            acc[i][0] *= sc; acc[i][1] *= sc; acc[i][2] *= sc; acc[i][3] *= sc;
        }
        __syncthreads();

#pragma unroll 8
        for (int k = 0; k < 64; k++) {
            float p0 = Ps[(r0 + 0) * PAD + k];
            float p1 = Ps[(r0 + 1) * PAD + k];
            float p2 = Ps[(r0 + 2) * PAD + k];
            float p3 = Ps[(r0 + 3) * PAD + k];
            float v0 = Vs[k * PAD + c0 + 0];
            float v1 = Vs[k * PAD + c0 + 1];
            float v2 = Vs[k * PAD + c0 + 2];
            float v3 = Vs[k * PAD + c0 + 3];
            acc[0][0] = fmaf(p0, v0, acc[0][0]); acc[0][1] = fmaf(p0, v1, acc[0][1]);
            acc[0][2] = fmaf(p0, v2, acc[0][2]); acc[0][3] = fmaf(p0, v3, acc[0][3]);
            acc[1][0] = fmaf(p1, v0, acc[1][0]); acc[1][1] = fmaf(p1, v1, acc[1][1]);
            acc[1][2] = fmaf(p1, v2, acc[1][2]); acc[1][3] = fmaf(p1, v3, acc[1][3]);
            acc[2][0] = fmaf(p2, v0, acc[2][0]); acc[2][1] = fmaf(p2, v1, acc[2][1]);
            acc[2][2] = fmaf(p2, v2, acc[2][2]); acc[2][3] = fmaf(p2, v3, acc[2][3]);
            acc[3][0] = fmaf(p3, v0, acc[3][0]); acc[3][1] = fmaf(p3, v1, acc[3][1]);
            acc[3][2] = fmaf(p3, v2, acc[3][2]); acc[3][3] = fmaf(p3, v3, acc[3][3]);
        }
    }

#pragma unroll
    for (int i = 0; i < 4; i++) {
        float inv = (l_[i] > 0.0f) ? (1.0f / l_[i]) : 0.0f;
        float4 o = make_float4(acc[i][0] * inv, acc[i][1] * inv,
                               acc[i][2] * inv, acc[i][3] * inv);
        *(float4*)(headout + ((size_t)b * S_DIM + qi0 + r0 + i) * E_DIM + h * DH + c0) = o;
    }
}

// ---------------------------------------------------------------------------
extern "C" void kernel_launch(void* const* d_in, const int* in_sizes, int n_in,
                              void* d_out, int out_size)
{
    const float* x       = (const float*)d_in[0];
    const float* w_qkv   = (const float*)d_in[1];
    const float* w_proj  = (const float*)d_in[2];
    const int* mask_head  = (const int*)d_in[3];
    const int* mask_child = (const int*)d_in[4];

    float* out = (float*)d_out;
    float* arc = out + (size_t)B_DIM * S_DIM * E_DIM;

    float* qkvbuf = nullptr;
    float* hout   = nullptr;
    cudaGetSymbolAddress((void**)&qkvbuf, g_qkv);
    cudaGetSymbolAddress((void**)&hout, g_headout);

    const int gemm_smem = 4 * TSZ;   // 73728
    cudaFuncSetAttribute(gemm_mma,
                         cudaFuncAttributeMaxDynamicSharedMemorySize, gemm_smem);
    cudaFuncSetAttribute(flash_kernel,
                         cudaFuncAttributeMaxDynamicSharedMemorySize,
                         (int)(4u * 64u * 65u * sizeof(float)));

    // 1) qkv = x @ w_qkv^T   [2048 x 3072 x 1024]
    {
        dim3 grid(E3 / 128, (B_DIM * S_DIM) / 128);
        gemm_mma<<<grid, 256, gemm_smem>>>(x, w_qkv, qkvbuf, E3, E_DIM);
    }

    // 2) fused attention + sigmoid side output
    {
        size_t smem = 4u * 64u * 65u * sizeof(float);
        dim3 grid(S_DIM / 64, B_DIM * MH);
        flash_kernel<<<grid, 256, smem>>>(qkvbuf, mask_head, mask_child, arc, hout);
    }

    // 3) out = headout @ w_proj^T   [2048 x 1024 x 1024]
    {
        dim3 grid(E_DIM / 128, (B_DIM * S_DIM) / 128);
        gemm_mma<<<grid, 256, gemm_smem>>>(hout, w_proj, out, E_DIM, E_DIM);
    }
}

// round 5
// speedup vs baseline: 1.4871x; 1.0187x over previous
#include <cuda_runtime.h>
#include <cuda_bf16.h>
#include <cstdint>

#define B_DIM 2
#define S_DIM 1024
#define E_DIM 1024
#define MH    16
#define DH    64
#define E3    3072

// Scratch (no cudaMalloc allowed)
__device__ float g_qkv[B_DIM * S_DIM * E3];        // [B*S, 3E]
__device__ float g_headout[B_DIM * S_DIM * E_DIM]; // [B*S, E]

__device__ __forceinline__ uint32_t pack_bf2(__nv_bfloat16 lo, __nv_bfloat16 hi) {
    return (uint32_t)__bfloat16_as_ushort(lo) | ((uint32_t)__bfloat16_as_ushort(hi) << 16);
}

__device__ __forceinline__ void mma16816(float* d, const uint32_t* a,
                                         uint32_t b0, uint32_t b1) {
    asm volatile(
        "mma.sync.aligned.m16n8k16.row.col.f32.bf16.bf16.f32 "
        "{%0,%1,%2,%3}, {%4,%5,%6,%7}, {%8,%9}, {%0,%1,%2,%3};"
        : "+f"(d[0]), "+f"(d[1]), "+f"(d[2]), "+f"(d[3])
        : "r"(a[0]), "r"(a[1]), "r"(a[2]), "r"(a[3]), "r"(b0), "r"(b1));
}

// Split one float4 into hi/lo bf16 pairs and store 8B each
__device__ __forceinline__ void split_store(float4 v, char* hi, char* lo) {
    __nv_bfloat16 h0 = __float2bfloat16(v.x);
    __nv_bfloat16 h1 = __float2bfloat16(v.y);
    __nv_bfloat16 h2 = __float2bfloat16(v.z);
    __nv_bfloat16 h3 = __float2bfloat16(v.w);
    __nv_bfloat16 l0 = __float2bfloat16(v.x - __bfloat162float(h0));
    __nv_bfloat16 l1 = __float2bfloat16(v.y - __bfloat162float(h1));
    __nv_bfloat16 l2 = __float2bfloat16(v.z - __bfloat162float(h2));
    __nv_bfloat16 l3 = __float2bfloat16(v.w - __bfloat162float(h3));
    *(uint2*)hi = make_uint2(pack_bf2(h0, h1), pack_bf2(h2, h3));
    *(uint2*)lo = make_uint2(pack_bf2(l0, l1), pack_bf2(l2, l3));
}

// ---------------------------------------------------------------------------
// HMMA GEMM: C[M,N] = A[M,K] @ W[N,K]^T  (fp32 via 2-term bf16 split)
// CTA 128x128, 8 warps (4x2), warp tile 32x64, K chunk 64.
// Double-buffered SMEM stages; register prefetch of next chunk overlaps MMA.
// ---------------------------------------------------------------------------
#define RSTR  144
#define TSZ   (128 * RSTR)
#define STAGE (4 * TSZ)     /* 73728 per stage */

__global__ __launch_bounds__(256, 1) void gemm_mma(
    const float* __restrict__ A, const float* __restrict__ W,
    float* __restrict__ C, int Nn, int Kn)
{
    extern __shared__ char smem[];

    int tid = threadIdx.x;
    int lane = tid & 31, wid = tid >> 5;
    int wm = wid >> 1, wn = wid & 1;          // warp grid 4x2
    int g = lane >> 2, t = lane & 3;
    int row0 = blockIdx.y * 128;
    int col0 = blockIdx.x * 128;

    float acc[2][8][4];
#pragma unroll
    for (int mt = 0; mt < 2; mt++)
#pragma unroll
        for (int j = 0; j < 8; j++)
#pragma unroll
            for (int q = 0; q < 4; q++) acc[mt][j][q] = 0.0f;

    int r  = tid >> 1;            // 0..127
    int ch = (tid & 1) * 32;      // 0 or 32
    const float* Ag = A + (size_t)(row0 + r) * Kn + ch;
    const float* Wg = W + (size_t)(col0 + r) * Kn + ch;
    int soff = r * RSTR + ch * 2;  // this thread's SMEM byte offset base

    float4 pa[8], pw[8];
    // prologue: load + store chunk 0 into stage 0
#pragma unroll
    for (int i = 0; i < 8; i++) {
        pa[i] = *(const float4*)(Ag + i * 4);
        pw[i] = *(const float4*)(Wg + i * 4);
    }
    {
        char* b0 = smem;
#pragma unroll
        for (int i = 0; i < 8; i++) {
            int off = soff + i * 8;
            split_store(pa[i], b0 + off, b0 + TSZ + off);
            split_store(pw[i], b0 + 2 * TSZ + off, b0 + 3 * TSZ + off);
        }
    }
    __syncthreads();

    int nChunks = Kn >> 6;
    for (int c = 0; c < nChunks; c++) {
        int s = c & 1;

        // prefetch chunk c+1 (LDGs in flight during MMA phase)
        if (c + 1 < nChunks) {
#pragma unroll
            for (int i = 0; i < 8; i++) {
                pa[i] = *(const float4*)(Ag + (c + 1) * 64 + i * 4);
                pw[i] = *(const float4*)(Wg + (c + 1) * 64 + i * 4);
            }
        }

        const char* Ah = smem + s * STAGE;
        const char* Al = Ah + TSZ;
        const char* Bh = Ah + 2 * TSZ;
        const char* Bl = Ah + 3 * TSZ;

        // -------- compute: 4 k16 steps --------
#pragma unroll
        for (int ks = 0; ks < 4; ks++) {
            int kb = (ks * 16 + t * 2) * 2;

            uint32_t ah[2][4], al[2][4];
#pragma unroll
            for (int mt = 0; mt < 2; mt++) {
                int ar = wm * 32 + mt * 16 + g;
                const char* ba = Ah + ar * RSTR + kb;
                ah[mt][0] = *(const uint32_t*)(ba);
                ah[mt][1] = *(const uint32_t*)(ba + 8 * RSTR);
                ah[mt][2] = *(const uint32_t*)(ba + 16);
                ah[mt][3] = *(const uint32_t*)(ba + 8 * RSTR + 16);
                const char* bl_ = Al + ar * RSTR + kb;
                al[mt][0] = *(const uint32_t*)(bl_);
                al[mt][1] = *(const uint32_t*)(bl_ + 8 * RSTR);
                al[mt][2] = *(const uint32_t*)(bl_ + 16);
                al[mt][3] = *(const uint32_t*)(bl_ + 8 * RSTR + 16);
            }
#pragma unroll
            for (int j = 0; j < 8; j++) {
                int br = wn * 64 + j * 8 + g;
                const char* bb = Bh + br * RSTR + kb;
                uint32_t bh0 = *(const uint32_t*)(bb);
                uint32_t bh1 = *(const uint32_t*)(bb + 16);
                const char* bc = Bl + br * RSTR + kb;
                uint32_t bl0 = *(const uint32_t*)(bc);
                uint32_t bl1 = *(const uint32_t*)(bc + 16);

                mma16816(acc[0][j], ah[0], bh0, bh1);
                mma16816(acc[1][j], ah[1], bh0, bh1);
                mma16816(acc[0][j], ah[0], bl0, bl1);
                mma16816(acc[1][j], ah[1], bl0, bl1);
                mma16816(acc[0][j], al[0], bh0, bh1);
                mma16816(acc[1][j], al[1], bh0, bh1);
            }
        }

        // convert + store chunk c+1 into the other stage
        if (c + 1 < nChunks) {
            char* nb = smem + (s ^ 1) * STAGE;
#pragma unroll
            for (int i = 0; i < 8; i++) {
                int off = soff + i * 8;
                split_store(pa[i], nb + off, nb + TSZ + off);
                split_store(pw[i], nb + 2 * TSZ + off, nb + 3 * TSZ + off);
            }
        }
        __syncthreads();
    }

    // -------- epilogue --------
#pragma unroll
    for (int mt = 0; mt < 2; mt++) {
        int rr = row0 + wm * 32 + mt * 16 + g;
#pragma unroll
        for (int j = 0; j < 8; j++) {
            int cc = col0 + wn * 64 + j * 8 + t * 2;
            *(float2*)(C + (size_t)rr * Nn + cc) =
                make_float2(acc[mt][j][0], acc[mt][j][1]);
            *(float2*)(C + (size_t)(rr + 8) * Nn + cc) =
                make_float2(acc[mt][j][2], acc[mt][j][3]);
        }
    }
}

// ---------------------------------------------------------------------------
// Fused attention (unchanged from R2/R4 passing version)
// ---------------------------------------------------------------------------
__global__ __launch_bounds__(256) void flash_kernel(
    const float* __restrict__ qkv,
    const int* __restrict__ mask_head,
    const int* __restrict__ mask_child,
    float* __restrict__ arc,
    float* __restrict__ headout)
{
    extern __shared__ float sm[];
    const int PAD = 65;
    float* Qs = sm;
    float* Ks = Qs + 64 * PAD;
    float* Vs = Ks + 64 * PAD;
    float* Ps = Vs + 64 * PAD;

    int tid = threadIdx.x;
    int tx = tid & 15, ty = tid >> 4;
    int bh = blockIdx.y;
    int b = bh >> 4, h = bh & 15;
    int qi0 = blockIdx.x * 64;

    const int* maskp =
        ((h < 8) ? mask_head : mask_child) + (size_t)b * S_DIM * S_DIM;
    const float* qb = qkv + (size_t)b * S_DIM * E3 + h * DH;
    const float* kb = qb + E_DIM;
    const float* vb = qb + 2 * E_DIM;
    float* arcb = arc + ((size_t)bh * S_DIM + qi0) * S_DIM;

    {
        int r = tid >> 4;
        int c = (tid & 15) << 2;
#pragma unroll
        for (int rr = 0; rr < 64; rr += 16) {
            float4 v = *(const float4*)(qb + (size_t)(qi0 + r + rr) * E3 + c);
            float* d = Qs + (r + rr) * PAD + c;
            const float sc = 1.0f / 64.0f;
            d[0] = v.x * sc; d[1] = v.y * sc; d[2] = v.z * sc; d[3] = v.w * sc;
        }
    }

    float m_[4], l_[4], acc[4][4];
#pragma unroll
    for (int i = 0; i < 4; i++) {
        m_[i] = -1e30f; l_[i] = 0.0f;
#pragma unroll
        for (int j = 0; j < 4; j++) acc[i][j] = 0.0f;
    }
    int r0 = ty * 4, c0 = tx * 4;
    int lastTile = qi0 >> 6;

    for (int kj = 0; kj < S_DIM / 64; kj++) {
        int j0 = kj * 64;
        if (kj > lastTile) {
            float4 z = make_float4(0.f, 0.f, 0.f, 0.f);
#pragma unroll
            for (int i = 0; i < 4; i++)
                *(float4*)(arcb + (size_t)(r0 + i) * S_DIM + j0 + c0) = z;
            continue;
        }

        __syncthreads();
        {
            int r = tid >> 4;
            int c = (tid & 15) << 2;
#pragma unroll
            for (int rr = 0; rr < 64; rr += 16) {
                float4 kv = *(const float4*)(kb + (size_t)(j0 + r + rr) * E3 + c);
                float4 vv = *(const float4*)(vb + (size_t)(j0 + r + rr) * E3 + c);
                float* kd = Ks + (r + rr) * PAD + c;
                kd[0] = kv.x; kd[1] = kv.y; kd[2] = kv.z; kd[3] = kv.w;
                float* vd = Vs + (r + rr) * PAD + c;
                vd[0] = vv.x; vd[1] = vv.y; vd[2] = vv.z; vd[3] = vv.w;
            }
        }
        __syncthreads();

        float s[4][4];
#pragma unroll
        for (int i = 0; i < 4; i++)
#pragma unroll
            for (int j = 0; j < 4; j++) s[i][j] = 0.0f;
#pragma unroll 8
        for (int k = 0; k < 64; k++) {
            float a0 = Qs[(r0 + 0) * PAD + k];
            float a1 = Qs[(r0 + 1) * PAD + k];
            float a2 = Qs[(r0 + 2) * PAD + k];
            float a3 = Qs[(r0 + 3) * PAD + k];
            float b0 = Ks[(c0 + 0) * PAD + k];
            float b1 = Ks[(c0 + 1) * PAD + k];
            float b2 = Ks[(c0 + 2) * PAD + k];
            float b3 = Ks[(c0 + 3) * PAD + k];
            s[0][0] = fmaf(a0, b0, s[0][0]); s[0][1] = fmaf(a0, b1, s[0][1]);
            s[0][2] = fmaf(a0, b2, s[0][2]); s[0][3] = fmaf(a0, b3, s[0][3]);
            s[1][0] = fmaf(a1, b0, s[1][0]); s[1][1] = fmaf(a1, b1, s[1][1]);
            s[1][2] = fmaf(a1, b2, s[1][2]); s[1][3] = fmaf(a1, b3, s[1][3]);
            s[2][0] = fmaf(a2, b0, s[2][0]); s[2][1] = fmaf(a2, b1, s[2][1]);
            s[2][2] = fmaf(a2, b2, s[2][2]); s[2][3] = fmaf(a2, b3, s[2][3]);
            s[3][0] = fmaf(a3, b0, s[3][0]); s[3][1] = fmaf(a3, b1, s[3][1]);
            s[3][2] = fmaf(a3, b2, s[3][2]); s[3][3] = fmaf(a3, b3, s[3][3]);
        }

        float mt[4];
#pragma unroll
        for (int i = 0; i < 4; i++) {
            int ig = qi0 + r0 + i;
            int4 mk = *(const int4*)(maskp + (size_t)ig * S_DIM + j0 + c0);
            int mm[4] = {mk.x, mk.y, mk.z, mk.w};
#pragma unroll
            for (int j = 0; j < 4; j++) {
                int jg = j0 + c0 + j;
                bool valid = (jg <= ig) && (mm[j] != 0);
                if (!valid) s[i][j] = -1e30f;
            }
            float4 sg;
            sg.x = 1.0f / (1.0f + __expf(-s[i][0]));
            sg.y = 1.0f / (1.0f + __expf(-s[i][1]));
            sg.z = 1.0f / (1.0f + __expf(-s[i][2]));
            sg.w = 1.0f / (1.0f + __expf(-s[i][3]));
            *(float4*)(arcb + (size_t)(r0 + i) * S_DIM + j0 + c0) = sg;
            mt[i] = fmaxf(fmaxf(s[i][0], s[i][1]), fmaxf(s[i][2], s[i][3]));
        }
#pragma unroll
        for (int off = 8; off >= 1; off >>= 1) {
#pragma unroll
            for (int i = 0; i < 4; i++)
                mt[i] = fmaxf(mt[i], __shfl_xor_sync(0xffffffffu, mt[i], off));
        }

#pragma unroll
        for (int i = 0; i < 4; i++) {
            float mn = fmaxf(m_[i], mt[i]);
            float sc = __expf(m_[i] - mn);
            float rs = 0.0f;
#pragma unroll
            for (int j = 0; j < 4; j++) {
                float p = __expf(s[i][j] - mn);
                Ps[(r0 + i) * PAD + c0 + j] = p;
                rs += p;
            }
#pragma unroll
            for (int off = 8; off >= 1; off >>= 1)
                rs += __shfl_xor_sync(0xffffffffu, rs, off);
            l_[i] = l_[i] * sc + rs;
            m_[i] = mn;
            acc[i][0] *= sc; acc[i][1] *= sc; acc[i][2] *= sc; acc[i][3] *= sc;
        }
        __syncthreads();

#pragma unroll 8
        for (int k = 0; k < 64; k++) {
            float p0 = Ps[(r0 + 0) * PAD + k];
            float p1 = Ps[(r0 + 1) * PAD + k];
            float p2 = Ps[(r0 + 2) * PAD + k];
            float p3 = Ps[(r0 + 3) * PAD + k];
            float v0 = Vs[k * PAD + c0 + 0];
            float v1 = Vs[k * PAD + c0 + 1];
            float v2 = Vs[k * PAD + c0 + 2];
            float v3 = Vs[k * PAD + c0 + 3];
            acc[0][0] = fmaf(p0, v0, acc[0][0]); acc[0][1] = fmaf(p0, v1, acc[0][1]);
            acc[0][2] = fmaf(p0, v2, acc[0][2]); acc[0][3] = fmaf(p0, v3, acc[0][3]);
            acc[1][0] = fmaf(p1, v0, acc[1][0]); acc[1][1] = fmaf(p1, v1, acc[1][1]);
            acc[1][2] = fmaf(p1, v2, acc[1][2]); acc[1][3] = fmaf(p1, v3, acc[1][3]);
            acc[2][0] = fmaf(p2, v0, acc[2][0]); acc[2][1] = fmaf(p2, v1, acc[2][1]);
            acc[2][2] = fmaf(p2, v2, acc[2][2]); acc[2][3] = fmaf(p2, v3, acc[2][3]);
            acc[3][0] = fmaf(p3, v0, acc[3][0]); acc[3][1] = fmaf(p3, v1, acc[3][1]);
            acc[3][2] = fmaf(p3, v2, acc[3][2]); acc[3][3] = fmaf(p3, v3, acc[3][3]);
        }
    }

#pragma unroll
    for (int i = 0; i < 4; i++) {
        float inv = (l_[i] > 0.0f) ? (1.0f / l_[i]) : 0.0f;
        float4 o = make_float4(acc[i][0] * inv, acc[i][1] * inv,
                               acc[i][2] * inv, acc[i][3] * inv);
        *(float4*)(headout + ((size_t)b * S_DIM + qi0 + r0 + i) * E_DIM + h * DH + c0) = o;
    }
}

// ---------------------------------------------------------------------------
extern "C" void kernel_launch(void* const* d_in, const int* in_sizes, int n_in,
                              void* d_out, int out_size)
{
    const float* x       = (const float*)d_in[0];
    const float* w_qkv   = (const float*)d_in[1];
    const float* w_proj  = (const float*)d_in[2];
    const int* mask_head  = (const int*)d_in[3];
    const int* mask_child = (const int*)d_in[4];

    float* out = (float*)d_out;
    float* arc = out + (size_t)B_DIM * S_DIM * E_DIM;

    float* qkvbuf = nullptr;
    float* hout   = nullptr;
    cudaGetSymbolAddress((void**)&qkvbuf, g_qkv);
    cudaGetSymbolAddress((void**)&hout, g_headout);

    const int gemm_smem = 2 * STAGE;   // 147456
    cudaFuncSetAttribute(gemm_mma,
                         cudaFuncAttributeMaxDynamicSharedMemorySize, gemm_smem);
    cudaFuncSetAttribute(flash_kernel,
                         cudaFuncAttributeMaxDynamicSharedMemorySize,
                         (int)(4u * 64u * 65u * sizeof(float)));

    // 1) qkv = x @ w_qkv^T   [2048 x 3072 x 1024]
    {
        dim3 grid(E3 / 128, (B_DIM * S_DIM) / 128);
        gemm_mma<<<grid, 256, gemm_smem>>>(x, w_qkv, qkvbuf, E3, E_DIM);
    }

    // 2) fused attention + sigmoid side output
    {
        size_t smem = 4u * 64u * 65u * sizeof(float);
        dim3 grid(S_DIM / 64, B_DIM * MH);
        flash_kernel<<<grid, 256, smem>>>(qkvbuf, mask_head, mask_child, arc, hout);
    }

    // 3) out = headout @ w_proj^T   [2048 x 1024 x 1024]
    {
        dim3 grid(E_DIM / 128, (B_DIM * S_DIM) / 128);
        gemm_mma<<<grid, 256, gemm_smem>>>(hout, w_proj, out, E_DIM, E_DIM);
    }
}

// round 6
// speedup vs baseline: 1.5362x; 1.0331x over previous
#include <cuda_runtime.h>
#include <cuda_bf16.h>
#include <cstdint>

#define B_DIM 2
#define S_DIM 1024
#define E_DIM 1024
#define MH    16
#define DH    64
#define E3    3072

// Scratch (no cudaMalloc allowed)
__device__ float g_qkv[B_DIM * S_DIM * E3];        // [B*S, 3E]
__device__ float g_headout[B_DIM * S_DIM * E_DIM]; // [B*S, E]

__device__ __forceinline__ uint32_t smem_u32(const void* p) {
    uint32_t a;
    asm("{ .reg .u64 t; cvta.to.shared.u64 t, %1; cvt.u32.u64 %0, t; }"
        : "=r"(a) : "l"(p));
    return a;
}

__device__ __forceinline__ uint32_t pack_bf2(__nv_bfloat16 lo, __nv_bfloat16 hi) {
    return (uint32_t)__bfloat16_as_ushort(lo) | ((uint32_t)__bfloat16_as_ushort(hi) << 16);
}

__device__ __forceinline__ void mma16816(float* d, const uint32_t* a,
                                         uint32_t b0, uint32_t b1) {
    asm volatile(
        "mma.sync.aligned.m16n8k16.row.col.f32.bf16.bf16.f32 "
        "{%0,%1,%2,%3}, {%4,%5,%6,%7}, {%8,%9}, {%0,%1,%2,%3};"
        : "+f"(d[0]), "+f"(d[1]), "+f"(d[2]), "+f"(d[3])
        : "r"(a[0]), "r"(a[1]), "r"(a[2]), "r"(a[3]), "r"(b0), "r"(b1));
}

__device__ __forceinline__ void ldsm4(uint32_t* d, uint32_t addr) {
    asm volatile("ldmatrix.sync.aligned.m8n8.x4.shared.b16 {%0,%1,%2,%3}, [%4];"
        : "=r"(d[0]), "=r"(d[1]), "=r"(d[2]), "=r"(d[3]) : "r"(addr));
}

// Split one float4 into hi/lo bf16 pairs and store 8B each
__device__ __forceinline__ void split_store(float4 v, char* hi, char* lo) {
    __nv_bfloat16 h0 = __float2bfloat16(v.x);
    __nv_bfloat16 h1 = __float2bfloat16(v.y);
    __nv_bfloat16 h2 = __float2bfloat16(v.z);
    __nv_bfloat16 h3 = __float2bfloat16(v.w);
    __nv_bfloat16 l0 = __float2bfloat16(v.x - __bfloat162float(h0));
    __nv_bfloat16 l1 = __float2bfloat16(v.y - __bfloat162float(h1));
    __nv_bfloat16 l2 = __float2bfloat16(v.z - __bfloat162float(h2));
    __nv_bfloat16 l3 = __float2bfloat16(v.w - __bfloat162float(h3));
    *(uint2*)hi = make_uint2(pack_bf2(h0, h1), pack_bf2(h2, h3));
    *(uint2*)lo = make_uint2(pack_bf2(l0, l1), pack_bf2(l2, l3));
}

// ---------------------------------------------------------------------------
// HMMA GEMM: C[M,N] = A[M,K] @ W[N,K]^T  (fp32 via 2-term bf16 split)
// CTA 128x128, 8 warps (4x2), warp tile 32x64, K chunk 64.
// Double-buffered SMEM; ldmatrix.x4 fragment loads.
// ---------------------------------------------------------------------------
#define RSTR  144
#define TSZ   (128 * RSTR)
#define STAGE (4 * TSZ)     /* 73728 per stage */

__global__ __launch_bounds__(256, 1) void gemm_mma(
    const float* __restrict__ A, const float* __restrict__ W,
    float* __restrict__ C, int Nn, int Kn)
{
    extern __shared__ char smem[];
    uint32_t sb = smem_u32(smem);

    int tid = threadIdx.x;
    int lane = tid & 31, wid = tid >> 5;
    int wm = wid >> 1, wn = wid & 1;          // warp grid 4x2
    int g = lane >> 2, t = lane & 3;
    int row0 = blockIdx.y * 128;
    int col0 = blockIdx.x * 128;

    // ldmatrix per-lane offsets
    int qm = lane >> 3, rm = lane & 7;
    // A x4: m0 rows+0 k+0 | m1 rows+8 k+0 | m2 rows+0 k+16B | m3 rows+8 k+16B
    uint32_t aOff = (uint32_t)(((qm & 1) * 8 + rm) * RSTR + (qm >> 1) * 16);
    // B x4: m0 n+0 k+0 | m1 n+0 k+16B | m2 n+8 k+0 | m3 n+8 k+16B
    uint32_t bOff = (uint32_t)(((qm >> 1) * 8 + rm) * RSTR + (qm & 1) * 16);

    float acc[2][8][4];
#pragma unroll
    for (int mt = 0; mt < 2; mt++)
#pragma unroll
        for (int j = 0; j < 8; j++)
#pragma unroll
            for (int q = 0; q < 4; q++) acc[mt][j][q] = 0.0f;

    int r  = tid >> 1;            // 0..127
    int ch = (tid & 1) * 32;      // 0 or 32
    const float* Ag = A + (size_t)(row0 + r) * Kn + ch;
    const float* Wg = W + (size_t)(col0 + r) * Kn + ch;
    int soff = r * RSTR + ch * 2;  // this thread's SMEM byte offset base

    float4 pa[8], pw[8];
    // prologue: load + store chunk 0 into stage 0
#pragma unroll
    for (int i = 0; i < 8; i++) {
        pa[i] = *(const float4*)(Ag + i * 4);
        pw[i] = *(const float4*)(Wg + i * 4);
    }
    {
        char* b0 = smem;
#pragma unroll
        for (int i = 0; i < 8; i++) {
            int off = soff + i * 8;
            split_store(pa[i], b0 + off, b0 + TSZ + off);
            split_store(pw[i], b0 + 2 * TSZ + off, b0 + 3 * TSZ + off);
        }
    }
    __syncthreads();

    uint32_t aRow0 = (uint32_t)((wm * 32) * RSTR);
    uint32_t bRow0 = (uint32_t)((wn * 64) * RSTR);

    int nChunks = Kn >> 6;
    for (int c = 0; c < nChunks; c++) {
        int s = c & 1;

        // prefetch chunk c+1 (LDGs in flight during MMA phase)
        if (c + 1 < nChunks) {
#pragma unroll
            for (int i = 0; i < 8; i++) {
                pa[i] = *(const float4*)(Ag + (c + 1) * 64 + i * 4);
                pw[i] = *(const float4*)(Wg + (c + 1) * 64 + i * 4);
            }
        }

        uint32_t stg = sb + (uint32_t)(s * STAGE);

        // -------- compute: 4 k16 steps --------
#pragma unroll
        for (int ks = 0; ks < 4; ks++) {
            uint32_t kb0 = (uint32_t)(ks * 32);

            uint32_t ah[2][4], al[2][4];
            ldsm4(ah[0], stg + aRow0 + kb0 + aOff);
            ldsm4(ah[1], stg + aRow0 + 16 * RSTR + kb0 + aOff);
            ldsm4(al[0], stg + TSZ + aRow0 + kb0 + aOff);
            ldsm4(al[1], stg + TSZ + aRow0 + 16 * RSTR + kb0 + aOff);

#pragma unroll
            for (int jj = 0; jj < 4; jj++) {
                uint32_t bh[4], bl[4];
                uint32_t bbase = stg + bRow0 + (uint32_t)(jj * 16 * RSTR) + kb0 + bOff;
                ldsm4(bh, bbase + 2 * TSZ);
                ldsm4(bl, bbase + 3 * TSZ);
                int j0 = jj * 2, j1 = jj * 2 + 1;

                mma16816(acc[0][j0], ah[0], bh[0], bh[1]);
                mma16816(acc[1][j0], ah[1], bh[0], bh[1]);
                mma16816(acc[0][j0], ah[0], bl[0], bl[1]);
                mma16816(acc[1][j0], ah[1], bl[0], bl[1]);
                mma16816(acc[0][j0], al[0], bh[0], bh[1]);
                mma16816(acc[1][j0], al[1], bh[0], bh[1]);

                mma16816(acc[0][j1], ah[0], bh[2], bh[3]);
                mma16816(acc[1][j1], ah[1], bh[2], bh[3]);
                mma16816(acc[0][j1], ah[0], bl[2], bl[3]);
                mma16816(acc[1][j1], ah[1], bl[2], bl[3]);
                mma16816(acc[0][j1], al[0], bh[2], bh[3]);
                mma16816(acc[1][j1], al[1], bh[2], bh[3]);
            }
        }

        // convert + store chunk c+1 into the other stage
        if (c + 1 < nChunks) {
            char* nb = smem + (s ^ 1) * STAGE;
#pragma unroll
            for (int i = 0; i < 8; i++) {
                int off = soff + i * 8;
                split_store(pa[i], nb + off, nb + TSZ + off);
                split_store(pw[i], nb + 2 * TSZ + off, nb + 3 * TSZ + off);
            }
        }
        __syncthreads();
    }

    // -------- epilogue --------
#pragma unroll
    for (int mt = 0; mt < 2; mt++) {
        int rr = row0 + wm * 32 + mt * 16 + g;
#pragma unroll
        for (int j = 0; j < 8; j++) {
            int cc = col0 + wn * 64 + j * 8 + t * 2;
            *(float2*)(C + (size_t)rr * Nn + cc) =
                make_float2(acc[mt][j][0], acc[mt][j][1]);
            *(float2*)(C + (size_t)(rr + 8) * Nn + cc) =
                make_float2(acc[mt][j][2], acc[mt][j][3]);
        }
    }
}

// ---------------------------------------------------------------------------
// Fused attention (unchanged from R2/R4 passing version)
// ---------------------------------------------------------------------------
__global__ __launch_bounds__(256) void flash_kernel(
    const float* __restrict__ qkv,
    const int* __restrict__ mask_head,
    const int* __restrict__ mask_child,
    float* __restrict__ arc,
    float* __restrict__ headout)
{
    extern __shared__ float sm[];
    const int PAD = 65;
    float* Qs = sm;
    float* Ks = Qs + 64 * PAD;
    float* Vs = Ks + 64 * PAD;
    float* Ps = Vs + 64 * PAD;

    int tid = threadIdx.x;
    int tx = tid & 15, ty = tid >> 4;
    int bh = blockIdx.y;
    int b = bh >> 4, h = bh & 15;
    int qi0 = blockIdx.x * 64;

    const int* maskp =
        ((h < 8) ? mask_head : mask_child) + (size_t)b * S_DIM * S_DIM;
    const float* qb = qkv + (size_t)b * S_DIM * E3 + h * DH;
    const float* kb = qb + E_DIM;
    const float* vb = qb + 2 * E_DIM;
    float* arcb = arc + ((size_t)bh * S_DIM + qi0) * S_DIM;

    {
        int r = tid >> 4;
        int c = (tid & 15) << 2;
#pragma unroll
        for (int rr = 0; rr < 64; rr += 16) {
            float4 v = *(const float4*)(qb + (size_t)(qi0 + r + rr) * E3 + c);
            float* d = Qs + (r + rr) * PAD + c;
            const float sc = 1.0f / 64.0f;
            d[0] = v.x * sc; d[1] = v.y * sc; d[2] = v.z * sc; d[3] = v.w * sc;
        }
    }

    float m_[4], l_[4], acc[4][4];
#pragma unroll
    for (int i = 0; i < 4; i++) {
        m_[i] = -1e30f; l_[i] = 0.0f;
#pragma unroll
        for (int j = 0; j < 4; j++) acc[i][j] = 0.0f;
    }
    int r0 = ty * 4, c0 = tx * 4;
    int lastTile = qi0 >> 6;

    for (int kj = 0; kj < S_DIM / 64; kj++) {
        int j0 = kj * 64;
        if (kj > lastTile) {
            float4 z = make_float4(0.f, 0.f, 0.f, 0.f);
#pragma unroll
            for (int i = 0; i < 4; i++)
                *(float4*)(arcb + (size_t)(r0 + i) * S_DIM + j0 + c0) = z;
            continue;
        }

        __syncthreads();
        {
            int r = tid >> 4;
            int c = (tid & 15) << 2;
#pragma unroll
            for (int rr = 0; rr < 64; rr += 16) {
                float4 kv = *(const float4*)(kb + (size_t)(j0 + r + rr) * E3 + c);
                float4 vv = *(const float4*)(vb + (size_t)(j0 + r + rr) * E3 + c);
                float* kd = Ks + (r + rr) * PAD + c;
                kd[0] = kv.x; kd[1] = kv.y; kd[2] = kv.z; kd[3] = kv.w;
                float* vd = Vs + (r + rr) * PAD + c;
                vd[0] = vv.x; vd[1] = vv.y; vd[2] = vv.z; vd[3] = vv.w;
            }
        }
        __syncthreads();

        float s[4][4];
#pragma unroll
        for (int i = 0; i < 4; i++)
#pragma unroll
            for (int j = 0; j < 4; j++) s[i][j] = 0.0f;
#pragma unroll 8
        for (int k = 0; k < 64; k++) {
            float a0 = Qs[(r0 + 0) * PAD + k];
            float a1 = Qs[(r0 + 1) * PAD + k];
            float a2 = Qs[(r0 + 2) * PAD + k];
            float a3 = Qs[(r0 + 3) * PAD + k];
            float b0 = Ks[(c0 + 0) * PAD + k];
            float b1 = Ks[(c0 + 1) * PAD + k];
            float b2 = Ks[(c0 + 2) * PAD + k];
            float b3 = Ks[(c0 + 3) * PAD + k];
            s[0][0] = fmaf(a0, b0, s[0][0]); s[0][1] = fmaf(a0, b1, s[0][1]);
            s[0][2] = fmaf(a0, b2, s[0][2]); s[0][3] = fmaf(a0, b3, s[0][3]);
            s[1][0] = fmaf(a1, b0, s[1][0]); s[1][1] = fmaf(a1, b1, s[1][1]);
            s[1][2] = fmaf(a1, b2, s[1][2]); s[1][3] = fmaf(a1, b3, s[1][3]);
            s[2][0] = fmaf(a2, b0, s[2][0]); s[2][1] = fmaf(a2, b1, s[2][1]);
            s[2][2] = fmaf(a2, b2, s[2][2]); s[2][3] = fmaf(a2, b3, s[2][3]);
            s[3][0] = fmaf(a3, b0, s[3][0]); s[3][1] = fmaf(a3, b1, s[3][1]);
            s[3][2] = fmaf(a3, b2, s[3][2]); s[3][3] = fmaf(a3, b3, s[3][3]);
        }

        float mt[4];
#pragma unroll
        for (int i = 0; i < 4; i++) {
            int ig = qi0 + r0 + i;
            int4 mk = *(const int4*)(maskp + (size_t)ig * S_DIM + j0 + c0);
            int mm[4] = {mk.x, mk.y, mk.z, mk.w};
#pragma unroll
            for (int j = 0; j < 4; j++) {
                int jg = j0 + c0 + j;
                bool valid = (jg <= ig) && (mm[j] != 0);
                if (!valid) s[i][j] = -1e30f;
            }
            float4 sg;
            sg.x = 1.0f / (1.0f + __expf(-s[i][0]));
            sg.y = 1.0f / (1.0f + __expf(-s[i][1]));
            sg.z = 1.0f / (1.0f + __expf(-s[i][2]));
            sg.w = 1.0f / (1.0f + __expf(-s[i][3]));
            *(float4*)(arcb + (size_t)(r0 + i) * S_DIM + j0 + c0) = sg;
            mt[i] = fmaxf(fmaxf(s[i][0], s[i][1]), fmaxf(s[i][2], s[i][3]));
        }
#pragma unroll
        for (int off = 8; off >= 1; off >>= 1) {
#pragma unroll
            for (int i = 0; i < 4; i++)
                mt[i] = fmaxf(mt[i], __shfl_xor_sync(0xffffffffu, mt[i], off));
        }

#pragma unroll
        for (int i = 0; i < 4; i++) {
            float mn = fmaxf(m_[i], mt[i]);
            float sc = __expf(m_[i] - mn);
            float rs = 0.0f;
#pragma unroll
            for (int j = 0; j < 4; j++) {
                float p = __expf(s[i][j] - mn);
                Ps[(r0 + i) * PAD + c0 + j] = p;
                rs += p;
            }
#pragma unroll
            for (int off = 8; off >= 1; off >>= 1)
                rs += __shfl_xor_sync(0xffffffffu, rs, off);
            l_[i] = l_[i] * sc + rs;
            m_[i] = mn;
            acc[i][0] *= sc; acc[i][1] *= sc; acc[i][2] *= sc; acc[i][3] *= sc;
        }
        __syncthreads();

#pragma unroll 8
        for (int k = 0; k < 64; k++) {
            float p0 = Ps[(r0 + 0) * PAD + k];
            float p1 = Ps[(r0 + 1) * PAD + k];
            float p2 = Ps[(r0 + 2) * PAD + k];
            float p3 = Ps[(r0 + 3) * PAD + k];
            float v0 = Vs[k * PAD + c0 + 0];
            float v1 = Vs[k * PAD + c0 + 1];
            float v2 = Vs[k * PAD + c0 + 2];
            float v3 = Vs[k * PAD + c0 + 3];
            acc[0][0] = fmaf(p0, v0, acc[0][0]); acc[0][1] = fmaf(p0, v1, acc[0][1]);
            acc[0][2] = fmaf(p0, v2, acc[0][2]); acc[0][3] = fmaf(p0, v3, acc[0][3]);
            acc[1][0] = fmaf(p1, v0, acc[1][0]); acc[1][1] = fmaf(p1, v1, acc[1][1]);
            acc[1][2] = fmaf(p1, v2, acc[1][2]); acc[1][3] = fmaf(p1, v3, acc[1][3]);
            acc[2][0] = fmaf(p2, v0, acc[2][0]); acc[2][1] = fmaf(p2, v1, acc[2][1]);
            acc[2][2] = fmaf(p2, v2, acc[2][2]); acc[2][3] = fmaf(p2, v3, acc[2][3]);
            acc[3][0] = fmaf(p3, v0, acc[3][0]); acc[3][1] = fmaf(p3, v1, acc[3][1]);
            acc[3][2] = fmaf(p3, v2, acc[3][2]); acc[3][3] = fmaf(p3, v3, acc[3][3]);
        }
    }

#pragma unroll
    for (int i = 0; i < 4; i++) {
        float inv = (l_[i] > 0.0f) ? (1.0f / l_[i]) : 0.0f;
        float4 o = make_float4(acc[i][0] * inv, acc[i][1] * inv,
                               acc[i][2] * inv, acc[i][3] * inv);
        *(float4*)(headout + ((size_t)b * S_DIM + qi0 + r0 + i) * E_DIM + h * DH + c0) = o;
    }
}

// ---------------------------------------------------------------------------
extern "C" void kernel_launch(void* const* d_in, const int* in_sizes, int n_in,
                              void* d_out, int out_size)
{
    const float* x       = (const float*)d_in[0];
    const float* w_qkv   = (const float*)d_in[1];
    const float* w_proj  = (const float*)d_in[2];
    const int* mask_head  = (const int*)d_in[3];
    const int* mask_child = (const int*)d_in[4];

    float* out = (float*)d_out;
    float* arc = out + (size_t)B_DIM * S_DIM * E_DIM;

    float* qkvbuf = nullptr;
    float* hout   = nullptr;
    cudaGetSymbolAddress((void**)&qkvbuf, g_qkv);
    cudaGetSymbolAddress((void**)&hout, g_headout);

    const int gemm_smem = 2 * STAGE;   // 147456
    cudaFuncSetAttribute(gemm_mma,
                         cudaFuncAttributeMaxDynamicSharedMemorySize, gemm_smem);
    cudaFuncSetAttribute(flash_kernel,
                         cudaFuncAttributeMaxDynamicSharedMemorySize,
                         (int)(4u * 64u * 65u * sizeof(float)));

    // 1) qkv = x @ w_qkv^T   [2048 x 3072 x 1024]
    {
        dim3 grid(E3 / 128, (B_DIM * S_DIM) / 128);
        gemm_mma<<<grid, 256, gemm_smem>>>(x, w_qkv, qkvbuf, E3, E_DIM);
    }

    // 2) fused attention + sigmoid side output
    {
        size_t smem = 4u * 64u * 65u * sizeof(float);
        dim3 grid(S_DIM / 64, B_DIM * MH);
        flash_kernel<<<grid, 256, smem>>>(qkvbuf, mask_head, mask_child, arc, hout);
    }

    // 3) out = headout @ w_proj^T   [2048 x 1024 x 1024]
    {
        dim3 grid(E_DIM / 128, (B_DIM * S_DIM) / 128);
        gemm_mma<<<grid, 256, gemm_smem>>>(hout, w_proj, out, E_DIM, E_DIM);
    }
}

// round 7
// speedup vs baseline: 1.5779x; 1.0271x over previous
#include <cuda_runtime.h>
#include <cuda_bf16.h>
#include <cstdint>

#define B_DIM 2
#define S_DIM 1024
#define E_DIM 1024
#define MH    16
#define DH    64
#define E3    3072

// Scratch (no cudaMalloc allowed)
__device__ float g_qkv[B_DIM * S_DIM * E3];        // [B*S, 3E]
__device__ float g_headout[B_DIM * S_DIM * E_DIM]; // [B*S, E]

__device__ __forceinline__ uint32_t smem_u32(const void* p) {
    uint32_t a;
    asm("{ .reg .u64 t; cvta.to.shared.u64 t, %1; cvt.u32.u64 %0, t; }"
        : "=r"(a) : "l"(p));
    return a;
}

__device__ __forceinline__ uint32_t pack_bf2(__nv_bfloat16 lo, __nv_bfloat16 hi) {
    return (uint32_t)__bfloat16_as_ushort(lo) | ((uint32_t)__bfloat16_as_ushort(hi) << 16);
}

__device__ __forceinline__ void mma16816(float* d, const uint32_t* a,
                                         uint32_t b0, uint32_t b1) {
    asm volatile(
        "mma.sync.aligned.m16n8k16.row.col.f32.bf16.bf16.f32 "
        "{%0,%1,%2,%3}, {%4,%5,%6,%7}, {%8,%9}, {%0,%1,%2,%3};"
        : "+f"(d[0]), "+f"(d[1]), "+f"(d[2]), "+f"(d[3])
        : "r"(a[0]), "r"(a[1]), "r"(a[2]), "r"(a[3]), "r"(b0), "r"(b1));
}

__device__ __forceinline__ void ldsm4(uint32_t* d, uint32_t addr) {
    asm volatile("ldmatrix.sync.aligned.m8n8.x4.shared.b16 {%0,%1,%2,%3}, [%4];"
        : "=r"(d[0]), "=r"(d[1]), "=r"(d[2]), "=r"(d[3]) : "r"(addr));
}

// Split one float4 into hi/lo bf16 pairs and store 8B each
__device__ __forceinline__ void split_store(float4 v, char* hi, char* lo) {
    __nv_bfloat16 h0 = __float2bfloat16(v.x);
    __nv_bfloat16 h1 = __float2bfloat16(v.y);
    __nv_bfloat16 h2 = __float2bfloat16(v.z);
    __nv_bfloat16 h3 = __float2bfloat16(v.w);
    __nv_bfloat16 l0 = __float2bfloat16(v.x - __bfloat162float(h0));
    __nv_bfloat16 l1 = __float2bfloat16(v.y - __bfloat162float(h1));
    __nv_bfloat16 l2 = __float2bfloat16(v.z - __bfloat162float(h2));
    __nv_bfloat16 l3 = __float2bfloat16(v.w - __bfloat162float(h3));
    *(uint2*)hi = make_uint2(pack_bf2(h0, h1), pack_bf2(h2, h3));
    *(uint2*)lo = make_uint2(pack_bf2(l0, l1), pack_bf2(l2, l3));
}

// ---------------------------------------------------------------------------
// HMMA GEMM: C[M,N] = A[M,K] @ W[N,K]^T  (fp32 via 2-term bf16 split)
// CTA 128x128, 8 warps (4x2), warp tile 32x64, K chunk 64.
// Single SMEM stage, 2 CTAs/SM for cross-CTA load/MMA overlap.
// ---------------------------------------------------------------------------
#define RSTR  144
#define TSZ   (128 * RSTR)
#define STAGE (4 * TSZ)     /* 73728 */

__global__ __launch_bounds__(256, 2) void gemm_mma(
    const float* __restrict__ A, const float* __restrict__ W,
    float* __restrict__ C, int Nn, int Kn)
{
    extern __shared__ char smem[];
    uint32_t sb = smem_u32(smem);

    int tid = threadIdx.x;
    int lane = tid & 31, wid = tid >> 5;
    int wm = wid >> 1, wn = wid & 1;          // warp grid 4x2
    int g = lane >> 2, t = lane & 3;
    int row0 = blockIdx.y * 128;
    int col0 = blockIdx.x * 128;

    // ldmatrix per-lane offsets
    int qm = lane >> 3, rm = lane & 7;
    uint32_t aOff = (uint32_t)(((qm & 1) * 8 + rm) * RSTR + (qm >> 1) * 16);
    uint32_t bOff = (uint32_t)(((qm >> 1) * 8 + rm) * RSTR + (qm & 1) * 16);

    float acc[2][8][4];
#pragma unroll
    for (int mt = 0; mt < 2; mt++)
#pragma unroll
        for (int j = 0; j < 8; j++)
#pragma unroll
            for (int q = 0; q < 4; q++) acc[mt][j][q] = 0.0f;

    int r  = tid >> 1;            // 0..127
    int ch = (tid & 1) * 32;      // 0 or 32
    const float* Ag = A + (size_t)(row0 + r) * Kn + ch;
    const float* Wg = W + (size_t)(col0 + r) * Kn + ch;
    int soff = r * RSTR + ch * 2;

    uint32_t aRow0 = (uint32_t)((wm * 32) * RSTR);
    uint32_t bRow0 = (uint32_t)((wn * 64) * RSTR);

    int nChunks = Kn >> 6;
    for (int c = 0; c < nChunks; c++) {
        // -------- fill SMEM (convert fp32 -> bf16 hi/lo) --------
#pragma unroll
        for (int i = 0; i < 8; i++) {
            int off = soff + i * 8;
            split_store(*(const float4*)(Ag + c * 64 + i * 4),
                        smem + off, smem + TSZ + off);
            split_store(*(const float4*)(Wg + c * 64 + i * 4),
                        smem + 2 * TSZ + off, smem + 3 * TSZ + off);
        }
        __syncthreads();

        // -------- compute: 4 k16 steps --------
#pragma unroll
        for (int ks = 0; ks < 4; ks++) {
            uint32_t kb0 = (uint32_t)(ks * 32);

            uint32_t ah[2][4], al[2][4];
            ldsm4(ah[0], sb + aRow0 + kb0 + aOff);
            ldsm4(ah[1], sb + aRow0 + 16 * RSTR + kb0 + aOff);
            ldsm4(al[0], sb + TSZ + aRow0 + kb0 + aOff);
            ldsm4(al[1], sb + TSZ + aRow0 + 16 * RSTR + kb0 + aOff);

            uint32_t bh[4][4], bl[4][4];
#pragma unroll
            for (int jj = 0; jj < 4; jj++) {
                uint32_t bbase = sb + bRow0 + (uint32_t)(jj * 16 * RSTR) + kb0 + bOff;
                ldsm4(bh[jj], bbase + 2 * TSZ);
                ldsm4(bl[jj], bbase + 3 * TSZ);
            }

            // product-major: hh x16, hl x16, lh x16 (same per-acc order as before)
#pragma unroll
            for (int jj = 0; jj < 4; jj++) {
                int j0 = jj * 2, j1 = jj * 2 + 1;
                mma16816(acc[0][j0], ah[0], bh[jj][0], bh[jj][1]);
                mma16816(acc[1][j0], ah[1], bh[jj][0], bh[jj][1]);
                mma16816(acc[0][j1], ah[0], bh[jj][2], bh[jj][3]);
                mma16816(acc[1][j1], ah[1], bh[jj][2], bh[jj][3]);
            }
#pragma unroll
            for (int jj = 0; jj < 4; jj++) {
                int j0 = jj * 2, j1 = jj * 2 + 1;
                mma16816(acc[0][j0], ah[0], bl[jj][0], bl[jj][1]);
                mma16816(acc[1][j0], ah[1], bl[jj][0], bl[jj][1]);
                mma16816(acc[0][j1], ah[0], bl[jj][2], bl[jj][3]);
                mma16816(acc[1][j1], ah[1], bl[jj][2], bl[jj][3]);
            }
#pragma unroll
            for (int jj = 0; jj < 4; jj++) {
                int j0 = jj * 2, j1 = jj * 2 + 1;
                mma16816(acc[0][j0], al[0], bh[jj][0], bh[jj][1]);
                mma16816(acc[1][j0], al[1], bh[jj][0], bh[jj][1]);
                mma16816(acc[0][j1], al[0], bh[jj][2], bh[jj][3]);
                mma16816(acc[1][j1], al[1], bh[jj][2], bh[jj][3]);
            }
        }
        __syncthreads();
    }

    // -------- epilogue --------
#pragma unroll
    for (int mt = 0; mt < 2; mt++) {
        int rr = row0 + wm * 32 + mt * 16 + g;
#pragma unroll
        for (int j = 0; j < 8; j++) {
            int cc = col0 + wn * 64 + j * 8 + t * 2;
            *(float2*)(C + (size_t)rr * Nn + cc) =
                make_float2(acc[mt][j][0], acc[mt][j][1]);
            *(float2*)(C + (size_t)(rr + 8) * Nn + cc) =
                make_float2(acc[mt][j][2], acc[mt][j][3]);
        }
    }
}

// ---------------------------------------------------------------------------
// Fused attention (unchanged from R2/R4 passing version)
// ---------------------------------------------------------------------------
__global__ __launch_bounds__(256) void flash_kernel(
    const float* __restrict__ qkv,
    const int* __restrict__ mask_head,
    const int* __restrict__ mask_child,
    float* __restrict__ arc,
    float* __restrict__ headout)
{
    extern __shared__ float sm[];
    const int PAD = 65;
    float* Qs = sm;
    float* Ks = Qs + 64 * PAD;
    float* Vs = Ks + 64 * PAD;
    float* Ps = Vs + 64 * PAD;

    int tid = threadIdx.x;
    int tx = tid & 15, ty = tid >> 4;
    int bh = blockIdx.y;
    int b = bh >> 4, h = bh & 15;
    int qi0 = blockIdx.x * 64;

    const int* maskp =
        ((h < 8) ? mask_head : mask_child) + (size_t)b * S_DIM * S_DIM;
    const float* qb = qkv + (size_t)b * S_DIM * E3 + h * DH;
    const float* kb = qb + E_DIM;
    const float* vb = qb + 2 * E_DIM;
    float* arcb = arc + ((size_t)bh * S_DIM + qi0) * S_DIM;

    {
        int r = tid >> 4;
        int c = (tid & 15) << 2;
#pragma unroll
        for (int rr = 0; rr < 64; rr += 16) {
            float4 v = *(const float4*)(qb + (size_t)(qi0 + r + rr) * E3 + c);
            float* d = Qs + (r + rr) * PAD + c;
            const float sc = 1.0f / 64.0f;
            d[0] = v.x * sc; d[1] = v.y * sc; d[2] = v.z * sc; d[3] = v.w * sc;
        }
    }

    float m_[4], l_[4], acc[4][4];
#pragma unroll
    for (int i = 0; i < 4; i++) {
        m_[i] = -1e30f; l_[i] = 0.0f;
#pragma unroll
        for (int j = 0; j < 4; j++) acc[i][j] = 0.0f;
    }
    int r0 = ty * 4, c0 = tx * 4;
    int lastTile = qi0 >> 6;

    for (int kj = 0; kj < S_DIM / 64; kj++) {
        int j0 = kj * 64;
        if (kj > lastTile) {
            float4 z = make_float4(0.f, 0.f, 0.f, 0.f);
#pragma unroll
            for (int i = 0; i < 4; i++)
                *(float4*)(arcb + (size_t)(r0 + i) * S_DIM + j0 + c0) = z;
            continue;
        }

        __syncthreads();
        {
            int r = tid >> 4;
            int c = (tid & 15) << 2;
#pragma unroll
            for (int rr = 0; rr < 64; rr += 16) {
                float4 kv = *(const float4*)(kb + (size_t)(j0 + r + rr) * E3 + c);
                float4 vv = *(const float4*)(vb + (size_t)(j0 + r + rr) * E3 + c);
                float* kd = Ks + (r + rr) * PAD + c;
                kd[0] = kv.x; kd[1] = kv.y; kd[2] = kv.z; kd[3] = kv.w;
                float* vd = Vs + (r + rr) * PAD + c;
                vd[0] = vv.x; vd[1] = vv.y; vd[2] = vv.z; vd[3] = vv.w;
            }
        }
        __syncthreads();

        float s[4][4];
#pragma unroll
        for (int i = 0; i < 4; i++)
#pragma unroll
            for (int j = 0; j < 4; j++) s[i][j] = 0.0f;
#pragma unroll 8
        for (int k = 0; k < 64; k++) {
            float a0 = Qs[(r0 + 0) * PAD + k];
            float a1 = Qs[(r0 + 1) * PAD + k];
            float a2 = Qs[(r0 + 2) * PAD + k];
            float a3 = Qs[(r0 + 3) * PAD + k];
            float b0 = Ks[(c0 + 0) * PAD + k];
            float b1 = Ks[(c0 + 1) * PAD + k];
            float b2 = Ks[(c0 + 2) * PAD + k];
            float b3 = Ks[(c0 + 3) * PAD + k];
            s[0][0] = fmaf(a0, b0, s[0][0]); s[0][1] = fmaf(a0, b1, s[0][1]);
            s[0][2] = fmaf(a0, b2, s[0][2]); s[0][3] = fmaf(a0, b3, s[0][3]);
            s[1][0] = fmaf(a1, b0, s[1][0]); s[1][1] = fmaf(a1, b1, s[1][1]);
            s[1][2] = fmaf(a1, b2, s[1][2]); s[1][3] = fmaf(a1, b3, s[1][3]);
            s[2][0] = fmaf(a2, b0, s[2][0]); s[2][1] = fmaf(a2, b1, s[2][1]);
            s[2][2] = fmaf(a2, b2, s[2][2]); s[2][3] = fmaf(a2, b3, s[2][3]);
            s[3][0] = fmaf(a3, b0, s[3][0]); s[3][1] = fmaf(a3, b1, s[3][1]);
            s[3][2] = fmaf(a3, b2, s[3][2]); s[3][3] = fmaf(a3, b3, s[3][3]);
        }

        float mt[4];
#pragma unroll
        for (int i = 0; i < 4; i++) {
            int ig = qi0 + r0 + i;
            int4 mk = *(const int4*)(maskp + (size_t)ig * S_DIM + j0 + c0);
            int mm[4] = {mk.x, mk.y, mk.z, mk.w};
#pragma unroll
            for (int j = 0; j < 4; j++) {
                int jg = j0 + c0 + j;
                bool valid = (jg <= ig) && (mm[j] != 0);
                if (!valid) s[i][j] = -1e30f;
            }
            float4 sg;
            sg.x = 1.0f / (1.0f + __expf(-s[i][0]));
            sg.y = 1.0f / (1.0f + __expf(-s[i][1]));
            sg.z = 1.0f / (1.0f + __expf(-s[i][2]));
            sg.w = 1.0f / (1.0f + __expf(-s[i][3]));
            *(float4*)(arcb + (size_t)(r0 + i) * S_DIM + j0 + c0) = sg;
            mt[i] = fmaxf(fmaxf(s[i][0], s[i][1]), fmaxf(s[i][2], s[i][3]));
        }
#pragma unroll
        for (int off = 8; off >= 1; off >>= 1) {
#pragma unroll
            for (int i = 0; i < 4; i++)
                mt[i] = fmaxf(mt[i], __shfl_xor_sync(0xffffffffu, mt[i], off));
        }

#pragma unroll
        for (int i = 0; i < 4; i++) {
            float mn = fmaxf(m_[i], mt[i]);
            float sc = __expf(m_[i] - mn);
            float rs = 0.0f;
#pragma unroll
            for (int j = 0; j < 4; j++) {
                float p = __expf(s[i][j] - mn);
                Ps[(r0 + i) * PAD + c0 + j] = p;
                rs += p;
            }
#pragma unroll
            for (int off = 8; off >= 1; off >>= 1)
                rs += __shfl_xor_sync(0xffffffffu, rs, off);
            l_[i] = l_[i] * sc + rs;
            m_[i] = mn;
            acc[i][0] *= sc; acc[i][1] *= sc; acc[i][2] *= sc; acc[i][3] *= sc;
        }
        __syncthreads();

#pragma unroll 8
        for (int k = 0; k < 64; k++) {
            float p0 = Ps[(r0 + 0) * PAD + k];
            float p1 = Ps[(r0 + 1) * PAD + k];
            float p2 = Ps[(r0 + 2) * PAD + k];
            float p3 = Ps[(r0 + 3) * PAD + k];
            float v0 = Vs[k * PAD + c0 + 0];
            float v1 = Vs[k * PAD + c0 + 1];
            float v2 = Vs[k * PAD + c0 + 2];
            float v3 = Vs[k * PAD + c0 + 3];
            acc[0][0] = fmaf(p0, v0, acc[0][0]); acc[0][1] = fmaf(p0, v1, acc[0][1]);
            acc[0][2] = fmaf(p0, v2, acc[0][2]); acc[0][3] = fmaf(p0, v3, acc[0][3]);
            acc[1][0] = fmaf(p1, v0, acc[1][0]); acc[1][1] = fmaf(p1, v1, acc[1][1]);
            acc[1][2] = fmaf(p1, v2, acc[1][2]); acc[1][3] = fmaf(p1, v3, acc[1][3]);
            acc[2][0] = fmaf(p2, v0, acc[2][0]); acc[2][1] = fmaf(p2, v1, acc[2][1]);
            acc[2][2] = fmaf(p2, v2, acc[2][2]); acc[2][3] = fmaf(p2, v3, acc[2][3]);
            acc[3][0] = fmaf(p3, v0, acc[3][0]); acc[3][1] = fmaf(p3, v1, acc[3][1]);
            acc[3][2] = fmaf(p3, v2, acc[3][2]); acc[3][3] = fmaf(p3, v3, acc[3][3]);
        }
    }

#pragma unroll
    for (int i = 0; i < 4; i++) {
        float inv = (l_[i] > 0.0f) ? (1.0f / l_[i]) : 0.0f;
        float4 o = make_float4(acc[i][0] * inv, acc[i][1] * inv,
                               acc[i][2] * inv, acc[i][3] * inv);
        *(float4*)(headout + ((size_t)b * S_DIM + qi0 + r0 + i) * E_DIM + h * DH + c0) = o;
    }
}

// ---------------------------------------------------------------------------
extern "C" void kernel_launch(void* const* d_in, const int* in_sizes, int n_in,
                              void* d_out, int out_size)
{
    const float* x       = (const float*)d_in[0];
    const float* w_qkv   = (const float*)d_in[1];
    const float* w_proj  = (const float*)d_in[2];
    const int* mask_head  = (const int*)d_in[3];
    const int* mask_child = (const int*)d_in[4];

    float* out = (float*)d_out;
    float* arc = out + (size_t)B_DIM * S_DIM * E_DIM;

    float* qkvbuf = nullptr;
    float* hout   = nullptr;
    cudaGetSymbolAddress((void**)&qkvbuf, g_qkv);
    cudaGetSymbolAddress((void**)&hout, g_headout);

    const int gemm_smem = STAGE;   // 73728 -> 2 CTAs/SM
    cudaFuncSetAttribute(gemm_mma,
                         cudaFuncAttributeMaxDynamicSharedMemorySize, gemm_smem);
    cudaFuncSetAttribute(flash_kernel,
                         cudaFuncAttributeMaxDynamicSharedMemorySize,
                         (int)(4u * 64u * 65u * sizeof(float)));

    // 1) qkv = x @ w_qkv^T   [2048 x 3072 x 1024]
    {
        dim3 grid(E3 / 128, (B_DIM * S_DIM) / 128);
        gemm_mma<<<grid, 256, gemm_smem>>>(x, w_qkv, qkvbuf, E3, E_DIM);
    }

    // 2) fused attention + sigmoid side output
    {
        size_t smem = 4u * 64u * 65u * sizeof(float);
        dim3 grid(S_DIM / 64, B_DIM * MH);
        flash_kernel<<<grid, 256, smem>>>(qkvbuf, mask_head, mask_child, arc, hout);
    }

    // 3) out = headout @ w_proj^T   [2048 x 1024 x 1024]
    {
        dim3 grid(E_DIM / 128, (B_DIM * S_DIM) / 128);
        gemm_mma<<<grid, 256, gemm_smem>>>(hout, w_proj, out, E_DIM, E_DIM);
    }
}

// round 8
// speedup vs baseline: 1.6221x; 1.0280x over previous
#include <cuda_runtime.h>
#include <cuda_bf16.h>
#include <cstdint>

#define B_DIM 2
#define S_DIM 1024
#define E_DIM 1024
#define MH    16
#define DH    64
#define E3    3072

// Scratch (no cudaMalloc allowed)
__device__ float g_qkv[B_DIM * S_DIM * E3];        // [B*S, 3E]
__device__ float g_headout[B_DIM * S_DIM * E_DIM]; // [B*S, E]

__device__ __forceinline__ uint32_t smem_u32(const void* p) {
    uint32_t a;
    asm("{ .reg .u64 t; cvta.to.shared.u64 t, %1; cvt.u32.u64 %0, t; }"
        : "=r"(a) : "l"(p));
    return a;
}

__device__ __forceinline__ uint32_t pack_bf2(__nv_bfloat16 lo, __nv_bfloat16 hi) {
    return (uint32_t)__bfloat16_as_ushort(lo) | ((uint32_t)__bfloat16_as_ushort(hi) << 16);
}

__device__ __forceinline__ void mma16816(float* d, const uint32_t* a,
                                         uint32_t b0, uint32_t b1) {
    asm volatile(
        "mma.sync.aligned.m16n8k16.row.col.f32.bf16.bf16.f32 "
        "{%0,%1,%2,%3}, {%4,%5,%6,%7}, {%8,%9}, {%0,%1,%2,%3};"
        : "+f"(d[0]), "+f"(d[1]), "+f"(d[2]), "+f"(d[3])
        : "r"(a[0]), "r"(a[1]), "r"(a[2]), "r"(a[3]), "r"(b0), "r"(b1));
}

__device__ __forceinline__ void ldsm4(uint32_t* d, uint32_t addr) {
    asm volatile("ldmatrix.sync.aligned.m8n8.x4.shared.b16 {%0,%1,%2,%3}, [%4];"
        : "=r"(d[0]), "=r"(d[1]), "=r"(d[2]), "=r"(d[3]) : "r"(addr));
}

// Split one float4 into hi/lo bf16 pairs and store 8B each
__device__ __forceinline__ void split_store(float4 v, char* hi, char* lo) {
    __nv_bfloat16 h0 = __float2bfloat16(v.x);
    __nv_bfloat16 h1 = __float2bfloat16(v.y);
    __nv_bfloat16 h2 = __float2bfloat16(v.z);
    __nv_bfloat16 h3 = __float2bfloat16(v.w);
    __nv_bfloat16 l0 = __float2bfloat16(v.x - __bfloat162float(h0));
    __nv_bfloat16 l1 = __float2bfloat16(v.y - __bfloat162float(h1));
    __nv_bfloat16 l2 = __float2bfloat16(v.z - __bfloat162float(h2));
    __nv_bfloat16 l3 = __float2bfloat16(v.w - __bfloat162float(h3));
    *(uint2*)hi = make_uint2(pack_bf2(h0, h1), pack_bf2(h2, h3));
    *(uint2*)lo = make_uint2(pack_bf2(l0, l1), pack_bf2(l2, l3));
}

// ---------------------------------------------------------------------------
// HMMA GEMM: C[M,N] = A[M,K] @ W[N,K]^T  (fp32 via 2-term bf16 split)
// CTA 128x128, 8 warps (4x2), warp tile 32x64, K chunk 64.
// Single SMEM stage, 2 CTAs/SM for cross-CTA load/MMA overlap.
// ---------------------------------------------------------------------------
#define RSTR  144
#define TSZ   (128 * RSTR)
#define STAGE (4 * TSZ)     /* 73728 */

__global__ __launch_bounds__(256, 2) void gemm_mma(
    const float* __restrict__ A, const float* __restrict__ W,
    float* __restrict__ C, int Nn, int Kn)
{
    extern __shared__ char smem[];
    uint32_t sb = smem_u32(smem);

    int tid = threadIdx.x;
    int lane = tid & 31, wid = tid >> 5;
    int wm = wid >> 1, wn = wid & 1;          // warp grid 4x2
    int g = lane >> 2, t = lane & 3;
    int row0 = blockIdx.y * 128;
    int col0 = blockIdx.x * 128;

    // ldmatrix per-lane offsets
    int qm = lane >> 3, rm = lane & 7;
    uint32_t aOff = (uint32_t)(((qm & 1) * 8 + rm) * RSTR + (qm >> 1) * 16);
    uint32_t bOff = (uint32_t)(((qm >> 1) * 8 + rm) * RSTR + (qm & 1) * 16);

    float acc[2][8][4];
#pragma unroll
    for (int mt = 0; mt < 2; mt++)
#pragma unroll
        for (int j = 0; j < 8; j++)
#pragma unroll
            for (int q = 0; q < 4; q++) acc[mt][j][q] = 0.0f;

    int r  = tid >> 1;            // 0..127
    int ch = (tid & 1) * 32;      // 0 or 32
    const float* Ag = A + (size_t)(row0 + r) * Kn + ch;
    const float* Wg = W + (size_t)(col0 + r) * Kn + ch;
    int soff = r * RSTR + ch * 2;

    uint32_t aRow0 = (uint32_t)((wm * 32) * RSTR);
    uint32_t bRow0 = (uint32_t)((wn * 64) * RSTR);

    int nChunks = Kn >> 6;
    for (int c = 0; c < nChunks; c++) {
        // -------- fill SMEM (convert fp32 -> bf16 hi/lo) --------
#pragma unroll
        for (int i = 0; i < 8; i++) {
            int off = soff + i * 8;
            split_store(*(const float4*)(Ag + c * 64 + i * 4),
                        smem + off, smem + TSZ + off);
            split_store(*(const float4*)(Wg + c * 64 + i * 4),
                        smem + 2 * TSZ + off, smem + 3 * TSZ + off);
        }
        __syncthreads();

        // -------- compute: 4 k16 steps --------
#pragma unroll
        for (int ks = 0; ks < 4; ks++) {
            uint32_t kb0 = (uint32_t)(ks * 32);

            uint32_t ah[2][4], al[2][4];
            ldsm4(ah[0], sb + aRow0 + kb0 + aOff);
            ldsm4(ah[1], sb + aRow0 + 16 * RSTR + kb0 + aOff);
            ldsm4(al[0], sb + TSZ + aRow0 + kb0 + aOff);
            ldsm4(al[1], sb + TSZ + aRow0 + 16 * RSTR + kb0 + aOff);

            uint32_t bh[4][4], bl[4][4];
#pragma unroll
            for (int jj = 0; jj < 4; jj++) {
                uint32_t bbase = sb + bRow0 + (uint32_t)(jj * 16 * RSTR) + kb0 + bOff;
                ldsm4(bh[jj], bbase + 2 * TSZ);
                ldsm4(bl[jj], bbase + 3 * TSZ);
            }

            // product-major: hh x16, hl x16, lh x16 (same per-acc order as before)
#pragma unroll
            for (int jj = 0; jj < 4; jj++) {
                int j0 = jj * 2, j1 = jj * 2 + 1;
                mma16816(acc[0][j0], ah[0], bh[jj][0], bh[jj][1]);
                mma16816(acc[1][j0], ah[1], bh[jj][0], bh[jj][1]);
                mma16816(acc[0][j1], ah[0], bh[jj][2], bh[jj][3]);
                mma16816(acc[1][j1], ah[1], bh[jj][2], bh[jj][3]);
            }
#pragma unroll
            for (int jj = 0; jj < 4; jj++) {
                int j0 = jj * 2, j1 = jj * 2 + 1;
                mma16816(acc[0][j0], ah[0], bl[jj][0], bl[jj][1]);
                mma16816(acc[1][j0], ah[1], bl[jj][0], bl[jj][1]);
                mma16816(acc[0][j1], ah[0], bl[jj][2], bl[jj][3]);
                mma16816(acc[1][j1], ah[1], bl[jj][2], bl[jj][3]);
            }
#pragma unroll
            for (int jj = 0; jj < 4; jj++) {
                int j0 = jj * 2, j1 = jj * 2 + 1;
                mma16816(acc[0][j0], al[0], bh[jj][0], bh[jj][1]);
                mma16816(acc[1][j0], al[1], bh[jj][0], bh[jj][1]);
                mma16816(acc[0][j1], al[0], bh[jj][2], bh[jj][3]);
                mma16816(acc[1][j1], al[1], bh[jj][2], bh[jj][3]);
            }
        }
        __syncthreads();
    }

    // -------- epilogue --------
#pragma unroll
    for (int mt = 0; mt < 2; mt++) {
        int rr = row0 + wm * 32 + mt * 16 + g;
#pragma unroll
        for (int j = 0; j < 8; j++) {
            int cc = col0 + wn * 64 + j * 8 + t * 2;
            *(float2*)(C + (size_t)rr * Nn + cc) =
                make_float2(acc[mt][j][0], acc[mt][j][1]);
            *(float2*)(C + (size_t)(rr + 8) * Nn + cc) =
                make_float2(acc[mt][j][2], acc[mt][j][3]);
        }
    }
}

// ---------------------------------------------------------------------------
// Fused attention: MUFU-reduced variant.
//   u = expf(s) once per score; sigmoid = u/(1+u); softmax p = u * expf(-mn)
// ---------------------------------------------------------------------------
__global__ __launch_bounds__(256) void flash_kernel(
    const float* __restrict__ qkv,
    const int* __restrict__ mask_head,
    const int* __restrict__ mask_child,
    float* __restrict__ arc,
    float* __restrict__ headout)
{
    extern __shared__ float sm[];
    const int PAD = 65;
    float* Qs = sm;
    float* Ks = Qs + 64 * PAD;
    float* Vs = Ks + 64 * PAD;
    float* Ps = Vs + 64 * PAD;

    int tid = threadIdx.x;
    int tx = tid & 15, ty = tid >> 4;
    int bh = blockIdx.y;
    int b = bh >> 4, h = bh & 15;
    int qi0 = blockIdx.x * 64;

    const int* maskp =
        ((h < 8) ? mask_head : mask_child) + (size_t)b * S_DIM * S_DIM;
    const float* qb = qkv + (size_t)b * S_DIM * E3 + h * DH;
    const float* kb = qb + E_DIM;
    const float* vb = qb + 2 * E_DIM;
    float* arcb = arc + ((size_t)bh * S_DIM + qi0) * S_DIM;

    {
        int r = tid >> 4;
        int c = (tid & 15) << 2;
#pragma unroll
        for (int rr = 0; rr < 64; rr += 16) {
            float4 v = *(const float4*)(qb + (size_t)(qi0 + r + rr) * E3 + c);
            float* d = Qs + (r + rr) * PAD + c;
            const float sc = 1.0f / 64.0f;
            d[0] = v.x * sc; d[1] = v.y * sc; d[2] = v.z * sc; d[3] = v.w * sc;
        }
    }

    float m_[4], l_[4], acc[4][4];
#pragma unroll
    for (int i = 0; i < 4; i++) {
        m_[i] = -1e30f; l_[i] = 0.0f;
#pragma unroll
        for (int j = 0; j < 4; j++) acc[i][j] = 0.0f;
    }
    int r0 = ty * 4, c0 = tx * 4;
    int lastTile = qi0 >> 6;

    for (int kj = 0; kj < S_DIM / 64; kj++) {
        int j0 = kj * 64;
        if (kj > lastTile) {
            float4 z = make_float4(0.f, 0.f, 0.f, 0.f);
#pragma unroll
            for (int i = 0; i < 4; i++)
                *(float4*)(arcb + (size_t)(r0 + i) * S_DIM + j0 + c0) = z;
            continue;
        }

        __syncthreads();
        {
            int r = tid >> 4;
            int c = (tid & 15) << 2;
#pragma unroll
            for (int rr = 0; rr < 64; rr += 16) {
                float4 kv = *(const float4*)(kb + (size_t)(j0 + r + rr) * E3 + c);
                float4 vv = *(const float4*)(vb + (size_t)(j0 + r + rr) * E3 + c);
                float* kd = Ks + (r + rr) * PAD + c;
                kd[0] = kv.x; kd[1] = kv.y; kd[2] = kv.z; kd[3] = kv.w;
                float* vd = Vs + (r + rr) * PAD + c;
                vd[0] = vv.x; vd[1] = vv.y; vd[2] = vv.z; vd[3] = vv.w;
            }
        }
        __syncthreads();

        float s[4][4];
#pragma unroll
        for (int i = 0; i < 4; i++)
#pragma unroll
            for (int j = 0; j < 4; j++) s[i][j] = 0.0f;
#pragma unroll 8
        for (int k = 0; k < 64; k++) {
            float a0 = Qs[(r0 + 0) * PAD + k];
            float a1 = Qs[(r0 + 1) * PAD + k];
            float a2 = Qs[(r0 + 2) * PAD + k];
            float a3 = Qs[(r0 + 3) * PAD + k];
            float b0 = Ks[(c0 + 0) * PAD + k];
            float b1 = Ks[(c0 + 1) * PAD + k];
            float b2 = Ks[(c0 + 2) * PAD + k];
            float b3 = Ks[(c0 + 3) * PAD + k];
            s[0][0] = fmaf(a0, b0, s[0][0]); s[0][1] = fmaf(a0, b1, s[0][1]);
            s[0][2] = fmaf(a0, b2, s[0][2]); s[0][3] = fmaf(a0, b3, s[0][3]);
            s[1][0] = fmaf(a1, b0, s[1][0]); s[1][1] = fmaf(a1, b1, s[1][1]);
            s[1][2] = fmaf(a1, b2, s[1][2]); s[1][3] = fmaf(a1, b3, s[1][3]);
            s[2][0] = fmaf(a2, b0, s[2][0]); s[2][1] = fmaf(a2, b1, s[2][1]);
            s[2][2] = fmaf(a2, b2, s[2][2]); s[2][3] = fmaf(a2, b3, s[2][3]);
            s[3][0] = fmaf(a3, b0, s[3][0]); s[3][1] = fmaf(a3, b1, s[3][1]);
            s[3][2] = fmaf(a3, b2, s[3][2]); s[3][3] = fmaf(a3, b3, s[3][3]);
        }

        // mask + single-exp sigmoid + row max
        float mt[4];
        float u[4][4];
#pragma unroll
        for (int i = 0; i < 4; i++) {
            int ig = qi0 + r0 + i;
            int4 mk = *(const int4*)(maskp + (size_t)ig * S_DIM + j0 + c0);
            int mm[4] = {mk.x, mk.y, mk.z, mk.w};
#pragma unroll
            for (int j = 0; j < 4; j++) {
                int jg = j0 + c0 + j;
                bool valid = (jg <= ig) && (mm[j] != 0);
                if (!valid) s[i][j] = -1e30f;
                u[i][j] = __expf(s[i][j]);   // 0 for masked
            }
            float4 sg;
            sg.x = __fdividef(u[i][0], 1.0f + u[i][0]);
            sg.y = __fdividef(u[i][1], 1.0f + u[i][1]);
            sg.z = __fdividef(u[i][2], 1.0f + u[i][2]);
            sg.w = __fdividef(u[i][3], 1.0f + u[i][3]);
            *(float4*)(arcb + (size_t)(r0 + i) * S_DIM + j0 + c0) = sg;
            mt[i] = fmaxf(fmaxf(s[i][0], s[i][1]), fmaxf(s[i][2], s[i][3]));
        }
#pragma unroll
        for (int off = 8; off >= 1; off >>= 1) {
#pragma unroll
            for (int i = 0; i < 4; i++)
                mt[i] = fmaxf(mt[i], __shfl_xor_sync(0xffffffffu, mt[i], off));
        }

        // online softmax update: p = u * exp(-mn)
#pragma unroll
        for (int i = 0; i < 4; i++) {
            float mn = fmaxf(fmaxf(m_[i], mt[i]), -80.0f);
            float sc = __expf(m_[i] - mn);
            float cexp = __expf(-mn);
            float rs = 0.0f;
#pragma unroll
            for (int j = 0; j < 4; j++) {
                float p = u[i][j] * cexp;
                Ps[(r0 + i) * PAD + c0 + j] = p;
                rs += p;
            }
#pragma unroll
            for (int off = 8; off >= 1; off >>= 1)
                rs += __shfl_xor_sync(0xffffffffu, rs, off);
            l_[i] = l_[i] * sc + rs;
            m_[i] = mn;
            acc[i][0] *= sc; acc[i][1] *= sc; acc[i][2] *= sc; acc[i][3] *= sc;
        }
        __syncthreads();

#pragma unroll 8
        for (int k = 0; k < 64; k++) {
            float p0 = Ps[(r0 + 0) * PAD + k];
            float p1 = Ps[(r0 + 1) * PAD + k];
            float p2 = Ps[(r0 + 2) * PAD + k];
            float p3 = Ps[(r0 + 3) * PAD + k];
            float v0 = Vs[k * PAD + c0 + 0];
            float v1 = Vs[k * PAD + c0 + 1];
            float v2 = Vs[k * PAD + c0 + 2];
            float v3 = Vs[k * PAD + c0 + 3];
            acc[0][0] = fmaf(p0, v0, acc[0][0]); acc[0][1] = fmaf(p0, v1, acc[0][1]);
            acc[0][2] = fmaf(p0, v2, acc[0][2]); acc[0][3] = fmaf(p0, v3, acc[0][3]);
            acc[1][0] = fmaf(p1, v0, acc[1][0]); acc[1][1] = fmaf(p1, v1, acc[1][1]);
            acc[1][2] = fmaf(p1, v2, acc[1][2]); acc[1][3] = fmaf(p1, v3, acc[1][3]);
            acc[2][0] = fmaf(p2, v0, acc[2][0]); acc[2][1] = fmaf(p2, v1, acc[2][1]);
            acc[2][2] = fmaf(p2, v2, acc[2][2]); acc[2][3] = fmaf(p2, v3, acc[2][3]);
            acc[3][0] = fmaf(p3, v0, acc[3][0]); acc[3][1] = fmaf(p3, v1, acc[3][1]);
            acc[3][2] = fmaf(p3, v2, acc[3][2]); acc[3][3] = fmaf(p3, v3, acc[3][3]);
        }
    }

#pragma unroll
    for (int i = 0; i < 4; i++) {
        float inv = (l_[i] > 0.0f) ? (1.0f / l_[i]) : 0.0f;
        float4 o = make_float4(acc[i][0] * inv, acc[i][1] * inv,
                               acc[i][2] * inv, acc[i][3] * inv);
        *(float4*)(headout + ((size_t)b * S_DIM + qi0 + r0 + i) * E_DIM + h * DH + c0) = o;
    }
}

// ---------------------------------------------------------------------------
extern "C" void kernel_launch(void* const* d_in, const int* in_sizes, int n_in,
                              void* d_out, int out_size)
{
    const float* x       = (const float*)d_in[0];
    const float* w_qkv   = (const float*)d_in[1];
    const float* w_proj  = (const float*)d_in[2];
    const int* mask_head  = (const int*)d_in[3];
    const int* mask_child = (const int*)d_in[4];

    float* out = (float*)d_out;
    float* arc = out + (size_t)B_DIM * S_DIM * E_DIM;

    float* qkvbuf = nullptr;
    float* hout   = nullptr;
    cudaGetSymbolAddress((void**)&qkvbuf, g_qkv);
    cudaGetSymbolAddress((void**)&hout, g_headout);

    const int gemm_smem = STAGE;   // 73728 -> 2 CTAs/SM
    cudaFuncSetAttribute(gemm_mma,
                         cudaFuncAttributeMaxDynamicSharedMemorySize, gemm_smem);
    cudaFuncSetAttribute(flash_kernel,
                         cudaFuncAttributeMaxDynamicSharedMemorySize,
                         (int)(4u * 64u * 65u * sizeof(float)));

    // 1) qkv = x @ w_qkv^T   [2048 x 3072 x 1024]
    {
        dim3 grid(E3 / 128, (B_DIM * S_DIM) / 128);
        gemm_mma<<<grid, 256, gemm_smem>>>(x, w_qkv, qkvbuf, E3, E_DIM);
    }

    // 2) fused attention + sigmoid side output
    {
        size_t smem = 4u * 64u * 65u * sizeof(float);
        dim3 grid(S_DIM / 64, B_DIM * MH);
        flash_kernel<<<grid, 256, smem>>>(qkvbuf, mask_head, mask_child, arc, hout);
    }

    // 3) out = headout @ w_proj^T   [2048 x 1024 x 1024]
    {
        dim3 grid(E_DIM / 128, (B_DIM * S_DIM) / 128);
        gemm_mma<<<grid, 256, gemm_smem>>>(hout, w_proj, out, E_DIM, E_DIM);
    }
}

// round 9
// speedup vs baseline: 1.7757x; 1.0947x over previous
#include <cuda_runtime.h>
#include <cuda_bf16.h>
#include <cstdint>

#define B_DIM 2
#define S_DIM 1024
#define E_DIM 1024
#define MH    16
#define DH    64
#define E3    3072

// Scratch (no cudaMalloc allowed)
__device__ float g_qkv[B_DIM * S_DIM * E3];              // [B*S, 3E] fp32
__device__ __nv_bfloat16 g_xh[B_DIM * S_DIM * E_DIM];    // x hi/lo
__device__ __nv_bfloat16 g_xl[B_DIM * S_DIM * E_DIM];
__device__ __nv_bfloat16 g_wqh[E3 * E_DIM];              // w_qkv hi/lo
__device__ __nv_bfloat16 g_wql[E3 * E_DIM];
__device__ __nv_bfloat16 g_wph[E_DIM * E_DIM];           // w_proj hi/lo
__device__ __nv_bfloat16 g_wpl[E_DIM * E_DIM];
__device__ __nv_bfloat16 g_hoh[B_DIM * S_DIM * E_DIM];   // head-out hi/lo
__device__ __nv_bfloat16 g_hol[B_DIM * S_DIM * E_DIM];

__device__ __forceinline__ uint32_t smem_u32(const void* p) {
    uint32_t a;
    asm("{ .reg .u64 t; cvta.to.shared.u64 t, %1; cvt.u32.u64 %0, t; }"
        : "=r"(a) : "l"(p));
    return a;
}

__device__ __forceinline__ uint32_t pack_bf2(__nv_bfloat16 lo, __nv_bfloat16 hi) {
    return (uint32_t)__bfloat16_as_ushort(lo) | ((uint32_t)__bfloat16_as_ushort(hi) << 16);
}

__device__ __forceinline__ void mma16816(float* d, const uint32_t* a,
                                         uint32_t b0, uint32_t b1) {
    asm volatile(
        "mma.sync.aligned.m16n8k16.row.col.f32.bf16.bf16.f32 "
        "{%0,%1,%2,%3}, {%4,%5,%6,%7}, {%8,%9}, {%0,%1,%2,%3};"
        : "+f"(d[0]), "+f"(d[1]), "+f"(d[2]), "+f"(d[3])
        : "r"(a[0]), "r"(a[1]), "r"(a[2]), "r"(a[3]), "r"(b0), "r"(b1));
}

__device__ __forceinline__ void ldsm4(uint32_t* d, uint32_t addr) {
    asm volatile("ldmatrix.sync.aligned.m8n8.x4.shared.b16 {%0,%1,%2,%3}, [%4];"
        : "=r"(d[0]), "=r"(d[1]), "=r"(d[2]), "=r"(d[3]) : "r"(addr));
}

__device__ __forceinline__ void cpa16(uint32_t dst, const void* src) {
    asm volatile("cp.async.cg.shared.global [%0], [%1], 16;"
                 :: "r"(dst), "l"(src));
}

// ---------------------------------------------------------------------------
// Pre-pass: split fp32 -> bf16 hi/lo (vectorized, one-shot)
// ---------------------------------------------------------------------------
__global__ void split_kernel(const float* __restrict__ in,
                             __nv_bfloat16* __restrict__ hi,
                             __nv_bfloat16* __restrict__ lo, int n4)
{
    int i = blockIdx.x * blockDim.x + threadIdx.x;
    if (i >= n4) return;
    float4 v = *(const float4*)(in + i * 4);
    __nv_bfloat16 h0 = __float2bfloat16(v.x);
    __nv_bfloat16 h1 = __float2bfloat16(v.y);
    __nv_bfloat16 h2 = __float2bfloat16(v.z);
    __nv_bfloat16 h3 = __float2bfloat16(v.w);
    __nv_bfloat16 l0 = __float2bfloat16(v.x - __bfloat162float(h0));
    __nv_bfloat16 l1 = __float2bfloat16(v.y - __bfloat162float(h1));
    __nv_bfloat16 l2 = __float2bfloat16(v.z - __bfloat162float(h2));
    __nv_bfloat16 l3 = __float2bfloat16(v.w - __bfloat162float(h3));
    *(uint2*)(hi + i * 4) = make_uint2(pack_bf2(h0, h1), pack_bf2(h2, h3));
    *(uint2*)(lo + i * 4) = make_uint2(pack_bf2(l0, l1), pack_bf2(l2, l3));
}

// ---------------------------------------------------------------------------
// HMMA GEMM on pre-split bf16: C[M,N] = A@W^T (3-term hi/lo products)
// CTA 128x128, 8 warps (4x2), K chunk 64, cp.async fill, 2 CTAs/SM.
// ---------------------------------------------------------------------------
#define RSTR  144
#define TSZ   (128 * RSTR)
#define STAGE (4 * TSZ)     /* 73728 */

__global__ __launch_bounds__(256, 2) void gemm_bf(
    const __nv_bfloat16* __restrict__ Ah_, const __nv_bfloat16* __restrict__ Al_,
    const __nv_bfloat16* __restrict__ Wh_, const __nv_bfloat16* __restrict__ Wl_,
    float* __restrict__ C, int Nn, int Kn)
{
    extern __shared__ char smem[];
    uint32_t sb = smem_u32(smem);

    int tid = threadIdx.x;
    int lane = tid & 31, wid = tid >> 5;
    int wm = wid >> 1, wn = wid & 1;
    int g = lane >> 2, t = lane & 3;
    int row0 = blockIdx.y * 128;
    int col0 = blockIdx.x * 128;

    int qm = lane >> 3, rm = lane & 7;
    uint32_t aOff = (uint32_t)(((qm & 1) * 8 + rm) * RSTR + (qm >> 1) * 16);
    uint32_t bOff = (uint32_t)(((qm >> 1) * 8 + rm) * RSTR + (qm & 1) * 16);

    float acc[2][8][4];
#pragma unroll
    for (int mt = 0; mt < 2; mt++)
#pragma unroll
        for (int j = 0; j < 8; j++)
#pragma unroll
            for (int q = 0; q < 4; q++) acc[mt][j][q] = 0.0f;

    // fill mapping: 2 threads per row, 4x16B segments each
    int r = tid >> 1;
    int half = tid & 1;
    const char* srcAh = (const char*)(Ah_ + (size_t)(row0 + r) * Kn) + half * 64;
    const char* srcAl = (const char*)(Al_ + (size_t)(row0 + r) * Kn) + half * 64;
    const char* srcWh = (const char*)(Wh_ + (size_t)(col0 + r) * Kn) + half * 64;
    const char* srcWl = (const char*)(Wl_ + (size_t)(col0 + r) * Kn) + half * 64;
    uint32_t dstBase = sb + (uint32_t)(r * RSTR + half * 64);

    uint32_t aRow0 = (uint32_t)((wm * 32) * RSTR);
    uint32_t bRow0 = (uint32_t)((wn * 64) * RSTR);

    int nChunks = Kn >> 6;
    for (int c = 0; c < nChunks; c++) {
        // -------- fill SMEM via cp.async (16 x 16B per thread) --------
        int cb = c * 128;   // chunk byte offset within a row
#pragma unroll
        for (int i = 0; i < 4; i++) {
            cpa16(dstBase + i * 16,           srcAh + cb + i * 16);
            cpa16(dstBase + TSZ + i * 16,     srcAl + cb + i * 16);
            cpa16(dstBase + 2 * TSZ + i * 16, srcWh + cb + i * 16);
            cpa16(dstBase + 3 * TSZ + i * 16, srcWl + cb + i * 16);
        }
        asm volatile("cp.async.commit_group;");
        asm volatile("cp.async.wait_group 0;");
        __syncthreads();

        // -------- compute: 4 k16 steps --------
#pragma unroll
        for (int ks = 0; ks < 4; ks++) {
            uint32_t kb0 = (uint32_t)(ks * 32);

            uint32_t ah[2][4], al[2][4];
            ldsm4(ah[0], sb + aRow0 + kb0 + aOff);
            ldsm4(ah[1], sb + aRow0 + 16 * RSTR + kb0 + aOff);
            ldsm4(al[0], sb + TSZ + aRow0 + kb0 + aOff);
            ldsm4(al[1], sb + TSZ + aRow0 + 16 * RSTR + kb0 + aOff);

            uint32_t bh[4][4], bl[4][4];
#pragma unroll
            for (int jj = 0; jj < 4; jj++) {
                uint32_t bbase = sb + bRow0 + (uint32_t)(jj * 16 * RSTR) + kb0 + bOff;
                ldsm4(bh[jj], bbase + 2 * TSZ);
                ldsm4(bl[jj], bbase + 3 * TSZ);
            }

#pragma unroll
            for (int jj = 0; jj < 4; jj++) {
                int j0 = jj * 2, j1 = jj * 2 + 1;
                mma16816(acc[0][j0], ah[0], bh[jj][0], bh[jj][1]);
                mma16816(acc[1][j0], ah[1], bh[jj][0], bh[jj][1]);
                mma16816(acc[0][j1], ah[0], bh[jj][2], bh[jj][3]);
                mma16816(acc[1][j1], ah[1], bh[jj][2], bh[jj][3]);
            }
#pragma unroll
            for (int jj = 0; jj < 4; jj++) {
                int j0 = jj * 2, j1 = jj * 2 + 1;
                mma16816(acc[0][j0], ah[0], bl[jj][0], bl[jj][1]);
                mma16816(acc[1][j0], ah[1], bl[jj][0], bl[jj][1]);
                mma16816(acc[0][j1], ah[0], bl[jj][2], bl[jj][3]);
                mma16816(acc[1][j1], ah[1], bl[jj][2], bl[jj][3]);
            }
#pragma unroll
            for (int jj = 0; jj < 4; jj++) {
                int j0 = jj * 2, j1 = jj * 2 + 1;
                mma16816(acc[0][j0], al[0], bh[jj][0], bh[jj][1]);
                mma16816(acc[1][j0], al[1], bh[jj][0], bh[jj][1]);
                mma16816(acc[0][j1], al[0], bh[jj][2], bh[jj][3]);
                mma16816(acc[1][j1], al[1], bh[jj][2], bh[jj][3]);
            }
        }
        __syncthreads();
    }

    // -------- epilogue --------
#pragma unroll
    for (int mt = 0; mt < 2; mt++) {
        int rr = row0 + wm * 32 + mt * 16 + g;
#pragma unroll
        for (int j = 0; j < 8; j++) {
            int cc = col0 + wn * 64 + j * 8 + t * 2;
            *(float2*)(C + (size_t)rr * Nn + cc) =
                make_float2(acc[mt][j][0], acc[mt][j][1]);
            *(float2*)(C + (size_t)(rr + 8) * Nn + cc) =
                make_float2(acc[mt][j][2], acc[mt][j][3]);
        }
    }
}

// ---------------------------------------------------------------------------
// Fused attention (R8 version) + bf16 hi/lo head-out epilogue
// ---------------------------------------------------------------------------
__global__ __launch_bounds__(256) void flash_kernel(
    const float* __restrict__ qkv,
    const int* __restrict__ mask_head,
    const int* __restrict__ mask_child,
    float* __restrict__ arc,
    __nv_bfloat16* __restrict__ hoh,
    __nv_bfloat16* __restrict__ hol)
{
    extern __shared__ float sm[];
    const int PAD = 65;
    float* Qs = sm;
    float* Ks = Qs + 64 * PAD;
    float* Vs = Ks + 64 * PAD;
    float* Ps = Vs + 64 * PAD;

    int tid = threadIdx.x;
    int tx = tid & 15, ty = tid >> 4;
    int bh = blockIdx.y;
    int b = bh >> 4, h = bh & 15;
    int qi0 = blockIdx.x * 64;

    const int* maskp =
        ((h < 8) ? mask_head : mask_child) + (size_t)b * S_DIM * S_DIM;
    const float* qb = qkv + (size_t)b * S_DIM * E3 + h * DH;
    const float* kb = qb + E_DIM;
    const float* vb = qb + 2 * E_DIM;
    float* arcb = arc + ((size_t)bh * S_DIM + qi0) * S_DIM;

    {
        int r = tid >> 4;
        int c = (tid & 15) << 2;
#pragma unroll
        for (int rr = 0; rr < 64; rr += 16) {
            float4 v = *(const float4*)(qb + (size_t)(qi0 + r + rr) * E3 + c);
            float* d = Qs + (r + rr) * PAD + c;
            const float sc = 1.0f / 64.0f;
            d[0] = v.x * sc; d[1] = v.y * sc; d[2] = v.z * sc; d[3] = v.w * sc;
        }
    }

    float m_[4], l_[4], acc[4][4];
#pragma unroll
    for (int i = 0; i < 4; i++) {
        m_[i] = -1e30f; l_[i] = 0.0f;
#pragma unroll
        for (int j = 0; j < 4; j++) acc[i][j] = 0.0f;
    }
    int r0 = ty * 4, c0 = tx * 4;
    int lastTile = qi0 >> 6;

    for (int kj = 0; kj < S_DIM / 64; kj++) {
        int j0 = kj * 64;
        if (kj > lastTile) {
            float4 z = make_float4(0.f, 0.f, 0.f, 0.f);
#pragma unroll
            for (int i = 0; i < 4; i++)
                *(float4*)(arcb + (size_t)(r0 + i) * S_DIM + j0 + c0) = z;
            continue;
        }

        __syncthreads();
        {
            int r = tid >> 4;
            int c = (tid & 15) << 2;
#pragma unroll
            for (int rr = 0; rr < 64; rr += 16) {
                float4 kv = *(const float4*)(kb + (size_t)(j0 + r + rr) * E3 + c);
                float4 vv = *(const float4*)(vb + (size_t)(j0 + r + rr) * E3 + c);
                float* kd = Ks + (r + rr) * PAD + c;
                kd[0] = kv.x; kd[1] = kv.y; kd[2] = kv.z; kd[3] = kv.w;
                float* vd = Vs + (r + rr) * PAD + c;
                vd[0] = vv.x; vd[1] = vv.y; vd[2] = vv.z; vd[3] = vv.w;
            }
        }
        __syncthreads();

        float s[4][4];
#pragma unroll
        for (int i = 0; i < 4; i++)
#pragma unroll
            for (int j = 0; j < 4; j++) s[i][j] = 0.0f;
#pragma unroll 8
        for (int k = 0; k < 64; k++) {
            float a0 = Qs[(r0 + 0) * PAD + k];
            float a1 = Qs[(r0 + 1) * PAD + k];
            float a2 = Qs[(r0 + 2) * PAD + k];
            float a3 = Qs[(r0 + 3) * PAD + k];
            float b0 = Ks[(c0 + 0) * PAD + k];
            float b1 = Ks[(c0 + 1) * PAD + k];
            float b2 = Ks[(c0 + 2) * PAD + k];
            float b3 = Ks[(c0 + 3) * PAD + k];
            s[0][0] = fmaf(a0, b0, s[0][0]); s[0][1] = fmaf(a0, b1, s[0][1]);
            s[0][2] = fmaf(a0, b2, s[0][2]); s[0][3] = fmaf(a0, b3, s[0][3]);
            s[1][0] = fmaf(a1, b0, s[1][0]); s[1][1] = fmaf(a1, b1, s[1][1]);
            s[1][2] = fmaf(a1, b2, s[1][2]); s[1][3] = fmaf(a1, b3, s[1][3]);
            s[2][0] = fmaf(a2, b0, s[2][0]); s[2][1] = fmaf(a2, b1, s[2][1]);
            s[2][2] = fmaf(a2, b2, s[2][2]); s[2][3] = fmaf(a2, b3, s[2][3]);
            s[3][0] = fmaf(a3, b0, s[3][0]); s[3][1] = fmaf(a3, b1, s[3][1]);
            s[3][2] = fmaf(a3, b2, s[3][2]); s[3][3] = fmaf(a3, b3, s[3][3]);
        }

        float mt[4];
        float u[4][4];
#pragma unroll
        for (int i = 0; i < 4; i++) {
            int ig = qi0 + r0 + i;
            int4 mk = *(const int4*)(maskp + (size_t)ig * S_DIM + j0 + c0);
            int mm[4] = {mk.x, mk.y, mk.z, mk.w};
#pragma unroll
            for (int j = 0; j < 4; j++) {
                int jg = j0 + c0 + j;
                bool valid = (jg <= ig) && (mm[j] != 0);
                if (!valid) s[i][j] = -1e30f;
                u[i][j] = __expf(s[i][j]);
            }
            float4 sg;
            sg.x = __fdividef(u[i][0], 1.0f + u[i][0]);
            sg.y = __fdividef(u[i][1], 1.0f + u[i][1]);
            sg.z = __fdividef(u[i][2], 1.0f + u[i][2]);
            sg.w = __fdividef(u[i][3], 1.0f + u[i][3]);
            *(float4*)(arcb + (size_t)(r0 + i) * S_DIM + j0 + c0) = sg;
            mt[i] = fmaxf(fmaxf(s[i][0], s[i][1]), fmaxf(s[i][2], s[i][3]));
        }
#pragma unroll
        for (int off = 8; off >= 1; off >>= 1) {
#pragma unroll
            for (int i = 0; i < 4; i++)
                mt[i] = fmaxf(mt[i], __shfl_xor_sync(0xffffffffu, mt[i], off));
        }

#pragma unroll
        for (int i = 0; i < 4; i++) {
            float mn = fmaxf(fmaxf(m_[i], mt[i]), -80.0f);
            float sc = __expf(m_[i] - mn);
            float cexp = __expf(-mn);
            float rs = 0.0f;
#pragma unroll
            for (int j = 0; j < 4; j++) {
                float p = u[i][j] * cexp;
                Ps[(r0 + i) * PAD + c0 + j] = p;
                rs += p;
            }
#pragma unroll
            for (int off = 8; off >= 1; off >>= 1)
                rs += __shfl_xor_sync(0xffffffffu, rs, off);
            l_[i] = l_[i] * sc + rs;
            m_[i] = mn;
            acc[i][0] *= sc; acc[i][1] *= sc; acc[i][2] *= sc; acc[i][3] *= sc;
        }
        __syncthreads();

#pragma unroll 8
        for (int k = 0; k < 64; k++) {
            float p0 = Ps[(r0 + 0) * PAD + k];
            float p1 = Ps[(r0 + 1) * PAD + k];
            float p2 = Ps[(r0 + 2) * PAD + k];
            float p3 = Ps[(r0 + 3) * PAD + k];
            float v0 = Vs[k * PAD + c0 + 0];
            float v1 = Vs[k * PAD + c0 + 1];
            float v2 = Vs[k * PAD + c0 + 2];
            float v3 = Vs[k * PAD + c0 + 3];
            acc[0][0] = fmaf(p0, v0, acc[0][0]); acc[0][1] = fmaf(p0, v1, acc[0][1]);
            acc[0][2] = fmaf(p0, v2, acc[0][2]); acc[0][3] = fmaf(p0, v3, acc[0][3]);
            acc[1][0] = fmaf(p1, v0, acc[1][0]); acc[1][1] = fmaf(p1, v1, acc[1][1]);
            acc[1][2] = fmaf(p1, v2, acc[1][2]); acc[1][3] = fmaf(p1, v3, acc[1][3]);
            acc[2][0] = fmaf(p2, v0, acc[2][0]); acc[2][1] = fmaf(p2, v1, acc[2][1]);
            acc[2][2] = fmaf(p2, v2, acc[2][2]); acc[2][3] = fmaf(p2, v3, acc[2][3]);
            acc[3][0] = fmaf(p3, v0, acc[3][0]); acc[3][1] = fmaf(p3, v1, acc[3][1]);
            acc[3][2] = fmaf(p3, v2, acc[3][2]); acc[3][3] = fmaf(p3, v3, acc[3][3]);
        }
    }

    // epilogue: O = acc / l -> bf16 hi/lo head-major [B,S,E]
#pragma unroll
    for (int i = 0; i < 4; i++) {
        float inv = (l_[i] > 0.0f) ? (1.0f / l_[i]) : 0.0f;
        float o0 = acc[i][0] * inv, o1 = acc[i][1] * inv;
        float o2 = acc[i][2] * inv, o3 = acc[i][3] * inv;
        __nv_bfloat16 h0 = __float2bfloat16(o0);
        __nv_bfloat16 h1 = __float2bfloat16(o1);
        __nv_bfloat16 h2 = __float2bfloat16(o2);
        __nv_bfloat16 h3 = __float2bfloat16(o3);
        __nv_bfloat16 l0 = __float2bfloat16(o0 - __bfloat162float(h0));
        __nv_bfloat16 l1 = __float2bfloat16(o1 - __bfloat162float(h1));
        __nv_bfloat16 l2 = __float2bfloat16(o2 - __bfloat162float(h2));
        __nv_bfloat16 l3 = __float2bfloat16(o3 - __bfloat162float(h3));
        size_t idx = ((size_t)b * S_DIM + qi0 + r0 + i) * E_DIM + h * DH + c0;
        *(uint2*)(hoh + idx) = make_uint2(pack_bf2(h0, h1), pack_bf2(h2, h3));
        *(uint2*)(hol + idx) = make_uint2(pack_bf2(l0, l1), pack_bf2(l2, l3));
    }
}

// ---------------------------------------------------------------------------
extern "C" void kernel_launch(void* const* d_in, const int* in_sizes, int n_in,
                              void* d_out, int out_size)
{
    const float* x       = (const float*)d_in[0];
    const float* w_qkv   = (const float*)d_in[1];
    const float* w_proj  = (const float*)d_in[2];
    const int* mask_head  = (const int*)d_in[3];
    const int* mask_child = (const int*)d_in[4];

    float* out = (float*)d_out;
    float* arc = out + (size_t)B_DIM * S_DIM * E_DIM;

    float* qkvbuf = nullptr;
    __nv_bfloat16 *xh, *xl, *wqh, *wql, *wph, *wpl, *hoh, *hol;
    cudaGetSymbolAddress((void**)&qkvbuf, g_qkv);
    cudaGetSymbolAddress((void**)&xh, g_xh);
    cudaGetSymbolAddress((void**)&xl, g_xl);
    cudaGetSymbolAddress((void**)&wqh, g_wqh);
    cudaGetSymbolAddress((void**)&wql, g_wql);
    cudaGetSymbolAddress((void**)&wph, g_wph);
    cudaGetSymbolAddress((void**)&wpl, g_wpl);
    cudaGetSymbolAddress((void**)&hoh, g_hoh);
    cudaGetSymbolAddress((void**)&hol, g_hol);

    const int gemm_smem = STAGE;   // 73728 -> 2 CTAs/SM
    cudaFuncSetAttribute(gemm_bf,
                         cudaFuncAttributeMaxDynamicSharedMemorySize, gemm_smem);
    cudaFuncSetAttribute(flash_kernel,
                         cudaFuncAttributeMaxDynamicSharedMemorySize,
                         (int)(4u * 64u * 65u * sizeof(float)));

    // 0) pre-split inputs into bf16 hi/lo
    {
        int n4x = (B_DIM * S_DIM * E_DIM) / 4;
        split_kernel<<<(n4x + 255) / 256, 256>>>(x, xh, xl, n4x);
        int n4q = (E3 * E_DIM) / 4;
        split_kernel<<<(n4q + 255) / 256, 256>>>(w_qkv, wqh, wql, n4q);
        int n4p = (E_DIM * E_DIM) / 4;
        split_kernel<<<(n4p + 255) / 256, 256>>>(w_proj, wph, wpl, n4p);
    }

    // 1) qkv = x @ w_qkv^T   [2048 x 3072 x 1024]
    {
        dim3 grid(E3 / 128, (B_DIM * S_DIM) / 128);
        gemm_bf<<<grid, 256, gemm_smem>>>(xh, xl, wqh, wql, qkvbuf, E3, E_DIM);
    }

    // 2) fused attention + sigmoid side output + bf16 head-out
    {
        size_t smem = 4u * 64u * 65u * sizeof(float);
        dim3 grid(S_DIM / 64, B_DIM * MH);
        flash_kernel<<<grid, 256, smem>>>(qkvbuf, mask_head, mask_child,
                                          arc, hoh, hol);
    }

    // 3) out = headout @ w_proj^T   [2048 x 1024 x 1024]
    {
        dim3 grid(E_DIM / 128, (B_DIM * S_DIM) / 128);
        gemm_bf<<<grid, 256, gemm_smem>>>(hoh, hol, wph, wpl, out, E_DIM, E_DIM);
    }
}

// round 10
// speedup vs baseline: 1.8785x; 1.0579x over previous
#include <cuda_runtime.h>
#include <cuda_bf16.h>
#include <cstdint>

#define B_DIM 2
#define S_DIM 1024
#define E_DIM 1024
#define MH    16
#define DH    64
#define E3    3072

// Scratch (no cudaMalloc allowed)
__device__ float g_qkv[B_DIM * S_DIM * E3];              // [B*S, 3E] fp32
__device__ __nv_bfloat16 g_xh[B_DIM * S_DIM * E_DIM];    // x hi/lo
__device__ __nv_bfloat16 g_xl[B_DIM * S_DIM * E_DIM];
__device__ __nv_bfloat16 g_wqh[E3 * E_DIM];              // w_qkv hi/lo
__device__ __nv_bfloat16 g_wql[E3 * E_DIM];
__device__ __nv_bfloat16 g_wph[E_DIM * E_DIM];           // w_proj hi/lo
__device__ __nv_bfloat16 g_wpl[E_DIM * E_DIM];
__device__ __nv_bfloat16 g_hoh[B_DIM * S_DIM * E_DIM];   // head-out hi/lo
__device__ __nv_bfloat16 g_hol[B_DIM * S_DIM * E_DIM];

__device__ __forceinline__ uint32_t smem_u32(const void* p) {
    uint32_t a;
    asm("{ .reg .u64 t; cvta.to.shared.u64 t, %1; cvt.u32.u64 %0, t; }"
        : "=r"(a) : "l"(p));
    return a;
}

__device__ __forceinline__ uint32_t pack_bf2(__nv_bfloat16 lo, __nv_bfloat16 hi) {
    return (uint32_t)__bfloat16_as_ushort(lo) | ((uint32_t)__bfloat16_as_ushort(hi) << 16);
}

__device__ __forceinline__ void mma16816(float* d, const uint32_t* a,
                                         uint32_t b0, uint32_t b1) {
    asm volatile(
        "mma.sync.aligned.m16n8k16.row.col.f32.bf16.bf16.f32 "
        "{%0,%1,%2,%3}, {%4,%5,%6,%7}, {%8,%9}, {%0,%1,%2,%3};"
        : "+f"(d[0]), "+f"(d[1]), "+f"(d[2]), "+f"(d[3])
        : "r"(a[0]), "r"(a[1]), "r"(a[2]), "r"(a[3]), "r"(b0), "r"(b1));
}

__device__ __forceinline__ void ldsm4(uint32_t* d, uint32_t addr) {
    asm volatile("ldmatrix.sync.aligned.m8n8.x4.shared.b16 {%0,%1,%2,%3}, [%4];"
        : "=r"(d[0]), "=r"(d[1]), "=r"(d[2]), "=r"(d[3]) : "r"(addr));
}

__device__ __forceinline__ void cpa16(uint32_t dst, const void* src) {
    asm volatile("cp.async.cg.shared.global [%0], [%1], 16;"
                 :: "r"(dst), "l"(src));
}

// ---------------------------------------------------------------------------
// Pre-pass: split fp32 -> bf16 hi/lo (vectorized, one-shot)
// ---------------------------------------------------------------------------
__global__ void split_kernel(const float* __restrict__ in,
                             __nv_bfloat16* __restrict__ hi,
                             __nv_bfloat16* __restrict__ lo, int n4)
{
    int i = blockIdx.x * blockDim.x + threadIdx.x;
    if (i >= n4) return;
    float4 v = *(const float4*)(in + i * 4);
    __nv_bfloat16 h0 = __float2bfloat16(v.x);
    __nv_bfloat16 h1 = __float2bfloat16(v.y);
    __nv_bfloat16 h2 = __float2bfloat16(v.z);
    __nv_bfloat16 h3 = __float2bfloat16(v.w);
    __nv_bfloat16 l0 = __float2bfloat16(v.x - __bfloat162float(h0));
    __nv_bfloat16 l1 = __float2bfloat16(v.y - __bfloat162float(h1));
    __nv_bfloat16 l2 = __float2bfloat16(v.z - __bfloat162float(h2));
    __nv_bfloat16 l3 = __float2bfloat16(v.w - __bfloat162float(h3));
    *(uint2*)(hi + i * 4) = make_uint2(pack_bf2(h0, h1), pack_bf2(h2, h3));
    *(uint2*)(lo + i * 4) = make_uint2(pack_bf2(l0, l1), pack_bf2(l2, l3));
}

// ---------------------------------------------------------------------------
// HMMA GEMM on pre-split bf16: C[M,N] = A@W^T (3-term hi/lo products)
// CTA 128x128, 8 warps (4x2), K chunk 32, 2-stage cp.async pipeline,
// 2 CTAs/SM.
// ---------------------------------------------------------------------------
#define RSTR  80
#define TSZb  (128 * RSTR)    /* 10240 */
#define SSTG  (4 * TSZb)      /* 40960 per stage */

__global__ __launch_bounds__(256, 2) void gemm_bf(
    const __nv_bfloat16* __restrict__ Ah_, const __nv_bfloat16* __restrict__ Al_,
    const __nv_bfloat16* __restrict__ Wh_, const __nv_bfloat16* __restrict__ Wl_,
    float* __restrict__ C, int Nn, int Kn)
{
    extern __shared__ char smem[];
    uint32_t sb = smem_u32(smem);

    int tid = threadIdx.x;
    int lane = tid & 31, wid = tid >> 5;
    int wm = wid >> 1, wn = wid & 1;
    int g = lane >> 2, t = lane & 3;
    int row0 = blockIdx.y * 128;
    int col0 = blockIdx.x * 128;

    int qm = lane >> 3, rm = lane & 7;
    uint32_t aOff = (uint32_t)(((qm & 1) * 8 + rm) * RSTR + (qm >> 1) * 16);
    uint32_t bOff = (uint32_t)(((qm >> 1) * 8 + rm) * RSTR + (qm & 1) * 16);

    float acc[2][8][4];
#pragma unroll
    for (int mt = 0; mt < 2; mt++)
#pragma unroll
        for (int j = 0; j < 8; j++)
#pragma unroll
            for (int q = 0; q < 4; q++) acc[mt][j][q] = 0.0f;

    // fill mapping: 2 threads per row, each 32B (2x16B) per array
    int r = tid >> 1;
    int half = tid & 1;
    const char* srcAh = (const char*)(Ah_ + (size_t)(row0 + r) * Kn) + half * 32;
    const char* srcAl = (const char*)(Al_ + (size_t)(row0 + r) * Kn) + half * 32;
    const char* srcWh = (const char*)(Wh_ + (size_t)(col0 + r) * Kn) + half * 32;
    const char* srcWl = (const char*)(Wl_ + (size_t)(col0 + r) * Kn) + half * 32;
    uint32_t dstOff = (uint32_t)(r * RSTR + half * 32);

    uint32_t aRow0 = (uint32_t)((wm * 32) * RSTR);
    uint32_t bRow0 = (uint32_t)((wn * 64) * RSTR);

    int nChunks = Kn >> 5;   // K chunk 32

    // prologue: prefetch chunk 0 into stage 0
    {
        uint32_t base = sb + dstOff;
        cpa16(base, srcAh);               cpa16(base + 16, srcAh + 16);
        cpa16(base + TSZb, srcAl);        cpa16(base + TSZb + 16, srcAl + 16);
        cpa16(base + 2 * TSZb, srcWh);    cpa16(base + 2 * TSZb + 16, srcWh + 16);
        cpa16(base + 3 * TSZb, srcWl);    cpa16(base + 3 * TSZb + 16, srcWl + 16);
        asm volatile("cp.async.commit_group;");
    }

    for (int c = 0; c < nChunks; c++) {
        int s = c & 1;

        if (c + 1 < nChunks) {
            // prefetch chunk c+1 into the other stage
            uint32_t base = sb + (uint32_t)((s ^ 1) * SSTG) + dstOff;
            int cb = (c + 1) * 64;
            cpa16(base, srcAh + cb);              cpa16(base + 16, srcAh + cb + 16);
            cpa16(base + TSZb, srcAl + cb);       cpa16(base + TSZb + 16, srcAl + cb + 16);
            cpa16(base + 2 * TSZb, srcWh + cb);   cpa16(base + 2 * TSZb + 16, srcWh + cb + 16);
            cpa16(base + 3 * TSZb, srcWl + cb);   cpa16(base + 3 * TSZb + 16, srcWl + cb + 16);
            asm volatile("cp.async.commit_group;");
            asm volatile("cp.async.wait_group 1;");
        } else {
            asm volatile("cp.async.wait_group 0;");
        }
        __syncthreads();

        uint32_t stg = sb + (uint32_t)(s * SSTG);

        // -------- compute: 2 k16 steps --------
#pragma unroll
        for (int ks = 0; ks < 2; ks++) {
            uint32_t kb0 = (uint32_t)(ks * 32);

            uint32_t ah[2][4], al[2][4];
            ldsm4(ah[0], stg + aRow0 + kb0 + aOff);
            ldsm4(ah[1], stg + aRow0 + 16 * RSTR + kb0 + aOff);
            ldsm4(al[0], stg + TSZb + aRow0 + kb0 + aOff);
            ldsm4(al[1], stg + TSZb + aRow0 + 16 * RSTR + kb0 + aOff);

            uint32_t bh[4][4], bl[4][4];
#pragma unroll
            for (int jj = 0; jj < 4; jj++) {
                uint32_t bbase = stg + bRow0 + (uint32_t)(jj * 16 * RSTR) + kb0 + bOff;
                ldsm4(bh[jj], bbase + 2 * TSZb);
                ldsm4(bl[jj], bbase + 3 * TSZb);
            }

#pragma unroll
            for (int jj = 0; jj < 4; jj++) {
                int j0 = jj * 2, j1 = jj * 2 + 1;
                mma16816(acc[0][j0], ah[0], bh[jj][0], bh[jj][1]);
                mma16816(acc[1][j0], ah[1], bh[jj][0], bh[jj][1]);
                mma16816(acc[0][j1], ah[0], bh[jj][2], bh[jj][3]);
                mma16816(acc[1][j1], ah[1], bh[jj][2], bh[jj][3]);
            }
#pragma unroll
            for (int jj = 0; jj < 4; jj++) {
                int j0 = jj * 2, j1 = jj * 2 + 1;
                mma16816(acc[0][j0], ah[0], bl[jj][0], bl[jj][1]);
                mma16816(acc[1][j0], ah[1], bl[jj][0], bl[jj][1]);
                mma16816(acc[0][j1], ah[0], bl[jj][2], bl[jj][3]);
                mma16816(acc[1][j1], ah[1], bl[jj][2], bl[jj][3]);
            }
#pragma unroll
            for (int jj = 0; jj < 4; jj++) {
                int j0 = jj * 2, j1 = jj * 2 + 1;
                mma16816(acc[0][j0], al[0], bh[jj][0], bh[jj][1]);
                mma16816(acc[1][j0], al[1], bh[jj][0], bh[jj][1]);
                mma16816(acc[0][j1], al[0], bh[jj][2], bh[jj][3]);
                mma16816(acc[1][j1], al[1], bh[jj][2], bh[jj][3]);
            }
        }
        __syncthreads();
    }

    // -------- epilogue --------
#pragma unroll
    for (int mt = 0; mt < 2; mt++) {
        int rr = row0 + wm * 32 + mt * 16 + g;
#pragma unroll
        for (int j = 0; j < 8; j++) {
            int cc = col0 + wn * 64 + j * 8 + t * 2;
            *(float2*)(C + (size_t)rr * Nn + cc) =
                make_float2(acc[mt][j][0], acc[mt][j][1]);
            *(float2*)(C + (size_t)(rr + 8) * Nn + cc) =
                make_float2(acc[mt][j][2], acc[mt][j][3]);
        }
    }
}

// ---------------------------------------------------------------------------
// Fused attention (R8/R9 version) + bf16 hi/lo head-out epilogue
// ---------------------------------------------------------------------------
__global__ __launch_bounds__(256) void flash_kernel(
    const float* __restrict__ qkv,
    const int* __restrict__ mask_head,
    const int* __restrict__ mask_child,
    float* __restrict__ arc,
    __nv_bfloat16* __restrict__ hoh,
    __nv_bfloat16* __restrict__ hol)
{
    extern __shared__ float sm[];
    const int PAD = 65;
    float* Qs = sm;
    float* Ks = Qs + 64 * PAD;
    float* Vs = Ks + 64 * PAD;
    float* Ps = Vs + 64 * PAD;

    int tid = threadIdx.x;
    int tx = tid & 15, ty = tid >> 4;
    int bh = blockIdx.y;
    int b = bh >> 4, h = bh & 15;
    int qi0 = blockIdx.x * 64;

    const int* maskp =
        ((h < 8) ? mask_head : mask_child) + (size_t)b * S_DIM * S_DIM;
    const float* qb = qkv + (size_t)b * S_DIM * E3 + h * DH;
    const float* kb = qb + E_DIM;
    const float* vb = qb + 2 * E_DIM;
    float* arcb = arc + ((size_t)bh * S_DIM + qi0) * S_DIM;

    {
        int r = tid >> 4;
        int c = (tid & 15) << 2;
#pragma unroll
        for (int rr = 0; rr < 64; rr += 16) {
            float4 v = *(const float4*)(qb + (size_t)(qi0 + r + rr) * E3 + c);
            float* d = Qs + (r + rr) * PAD + c;
            const float sc = 1.0f / 64.0f;
            d[0] = v.x * sc; d[1] = v.y * sc; d[2] = v.z * sc; d[3] = v.w * sc;
        }
    }

    float m_[4], l_[4], acc[4][4];
#pragma unroll
    for (int i = 0; i < 4; i++) {
        m_[i] = -1e30f; l_[i] = 0.0f;
#pragma unroll
        for (int j = 0; j < 4; j++) acc[i][j] = 0.0f;
    }
    int r0 = ty * 4, c0 = tx * 4;
    int lastTile = qi0 >> 6;

    for (int kj = 0; kj < S_DIM / 64; kj++) {
        int j0 = kj * 64;
        if (kj > lastTile) {
            float4 z = make_float4(0.f, 0.f, 0.f, 0.f);
#pragma unroll
            for (int i = 0; i < 4; i++)
                *(float4*)(arcb + (size_t)(r0 + i) * S_DIM + j0 + c0) = z;
            continue;
        }

        __syncthreads();
        {
            int r = tid >> 4;
            int c = (tid & 15) << 2;
#pragma unroll
            for (int rr = 0; rr < 64; rr += 16) {
                float4 kv = *(const float4*)(kb + (size_t)(j0 + r + rr) * E3 + c);
                float4 vv = *(const float4*)(vb + (size_t)(j0 + r + rr) * E3 + c);
                float* kd = Ks + (r + rr) * PAD + c;
                kd[0] = kv.x; kd[1] = kv.y; kd[2] = kv.z; kd[3] = kv.w;
                float* vd = Vs + (r + rr) * PAD + c;
                vd[0] = vv.x; vd[1] = vv.y; vd[2] = vv.z; vd[3] = vv.w;
            }
        }
        __syncthreads();

        float s[4][4];
#pragma unroll
        for (int i = 0; i < 4; i++)
#pragma unroll
            for (int j = 0; j < 4; j++) s[i][j] = 0.0f;
#pragma unroll 8
        for (int k = 0; k < 64; k++) {
            float a0 = Qs[(r0 + 0) * PAD + k];
            float a1 = Qs[(r0 + 1) * PAD + k];
            float a2 = Qs[(r0 + 2) * PAD + k];
            float a3 = Qs[(r0 + 3) * PAD + k];
            float b0 = Ks[(c0 + 0) * PAD + k];
            float b1 = Ks[(c0 + 1) * PAD + k];
            float b2 = Ks[(c0 + 2) * PAD + k];
            float b3 = Ks[(c0 + 3) * PAD + k];
            s[0][0] = fmaf(a0, b0, s[0][0]); s[0][1] = fmaf(a0, b1, s[0][1]);
            s[0][2] = fmaf(a0, b2, s[0][2]); s[0][3] = fmaf(a0, b3, s[0][3]);
            s[1][0] = fmaf(a1, b0, s[1][0]); s[1][1] = fmaf(a1, b1, s[1][1]);
            s[1][2] = fmaf(a1, b2, s[1][2]); s[1][3] = fmaf(a1, b3, s[1][3]);
            s[2][0] = fmaf(a2, b0, s[2][0]); s[2][1] = fmaf(a2, b1, s[2][1]);
            s[2][2] = fmaf(a2, b2, s[2][2]); s[2][3] = fmaf(a2, b3, s[2][3]);
            s[3][0] = fmaf(a3, b0, s[3][0]); s[3][1] = fmaf(a3, b1, s[3][1]);
            s[3][2] = fmaf(a3, b2, s[3][2]); s[3][3] = fmaf(a3, b3, s[3][3]);
        }

        float mt[4];
        float u[4][4];
#pragma unroll
        for (int i = 0; i < 4; i++) {
            int ig = qi0 + r0 + i;
            int4 mk = *(const int4*)(maskp + (size_t)ig * S_DIM + j0 + c0);
            int mm[4] = {mk.x, mk.y, mk.z, mk.w};
#pragma unroll
            for (int j = 0; j < 4; j++) {
                int jg = j0 + c0 + j;
                bool valid = (jg <= ig) && (mm[j] != 0);
                if (!valid) s[i][j] = -1e30f;
                u[i][j] = __expf(s[i][j]);
            }
            float4 sg;
            sg.x = __fdividef(u[i][0], 1.0f + u[i][0]);
            sg.y = __fdividef(u[i][1], 1.0f + u[i][1]);
            sg.z = __fdividef(u[i][2], 1.0f + u[i][2]);
            sg.w = __fdividef(u[i][3], 1.0f + u[i][3]);
            *(float4*)(arcb + (size_t)(r0 + i) * S_DIM + j0 + c0) = sg;
            mt[i] = fmaxf(fmaxf(s[i][0], s[i][1]), fmaxf(s[i][2], s[i][3]));
        }
#pragma unroll
        for (int off = 8; off >= 1; off >>= 1) {
#pragma unroll
            for (int i = 0; i < 4; i++)
                mt[i] = fmaxf(mt[i], __shfl_xor_sync(0xffffffffu, mt[i], off));
        }

#pragma unroll
        for (int i = 0; i < 4; i++) {
            float mn = fmaxf(fmaxf(m_[i], mt[i]), -80.0f);
            float sc = __expf(m_[i] - mn);
            float cexp = __expf(-mn);
            float rs = 0.0f;
#pragma unroll
            for (int j = 0; j < 4; j++) {
                float p = u[i][j] * cexp;
                Ps[(r0 + i) * PAD + c0 + j] = p;
                rs += p;
            }
#pragma unroll
            for (int off = 8; off >= 1; off >>= 1)
                rs += __shfl_xor_sync(0xffffffffu, rs, off);
            l_[i] = l_[i] * sc + rs;
            m_[i] = mn;
            acc[i][0] *= sc; acc[i][1] *= sc; acc[i][2] *= sc; acc[i][3] *= sc;
        }
        __syncthreads();

#pragma unroll 8
        for (int k = 0; k < 64; k++) {
            float p0 = Ps[(r0 + 0) * PAD + k];
            float p1 = Ps[(r0 + 1) * PAD + k];
            float p2 = Ps[(r0 + 2) * PAD + k];
            float p3 = Ps[(r0 + 3) * PAD + k];
            float v0 = Vs[k * PAD + c0 + 0];
            float v1 = Vs[k * PAD + c0 + 1];
            float v2 = Vs[k * PAD + c0 + 2];
            float v3 = Vs[k * PAD + c0 + 3];
            acc[0][0] = fmaf(p0, v0, acc[0][0]); acc[0][1] = fmaf(p0, v1, acc[0][1]);
            acc[0][2] = fmaf(p0, v2, acc[0][2]); acc[0][3] = fmaf(p0, v3, acc[0][3]);
            acc[1][0] = fmaf(p1, v0, acc[1][0]); acc[1][1] = fmaf(p1, v1, acc[1][1]);
            acc[1][2] = fmaf(p1, v2, acc[1][2]); acc[1][3] = fmaf(p1, v3, acc[1][3]);
            acc[2][0] = fmaf(p2, v0, acc[2][0]); acc[2][1] = fmaf(p2, v1, acc[2][1]);
            acc[2][2] = fmaf(p2, v2, acc[2][2]); acc[2][3] = fmaf(p2, v3, acc[2][3]);
            acc[3][0] = fmaf(p3, v0, acc[3][0]); acc[3][1] = fmaf(p3, v1, acc[3][1]);
            acc[3][2] = fmaf(p3, v2, acc[3][2]); acc[3][3] = fmaf(p3, v3, acc[3][3]);
        }
    }

    // epilogue: O = acc / l -> bf16 hi/lo head-major [B,S,E]
#pragma unroll
    for (int i = 0; i < 4; i++) {
        float inv = (l_[i] > 0.0f) ? (1.0f / l_[i]) : 0.0f;
        float o0 = acc[i][0] * inv, o1 = acc[i][1] * inv;
        float o2 = acc[i][2] * inv, o3 = acc[i][3] * inv;
        __nv_bfloat16 h0 = __float2bfloat16(o0);
        __nv_bfloat16 h1 = __float2bfloat16(o1);
        __nv_bfloat16 h2 = __float2bfloat16(o2);
        __nv_bfloat16 h3 = __float2bfloat16(o3);
        __nv_bfloat16 l0 = __float2bfloat16(o0 - __bfloat162float(h0));
        __nv_bfloat16 l1 = __float2bfloat16(o1 - __bfloat162float(h1));
        __nv_bfloat16 l2 = __float2bfloat16(o2 - __bfloat162float(h2));
        __nv_bfloat16 l3 = __float2bfloat16(o3 - __bfloat162float(h3));
        size_t idx = ((size_t)b * S_DIM + qi0 + r0 + i) * E_DIM + h * DH + c0;
        *(uint2*)(hoh + idx) = make_uint2(pack_bf2(h0, h1), pack_bf2(h2, h3));
        *(uint2*)(hol + idx) = make_uint2(pack_bf2(l0, l1), pack_bf2(l2, l3));
    }
}

// ---------------------------------------------------------------------------
extern "C" void kernel_launch(void* const* d_in, const int* in_sizes, int n_in,
                              void* d_out, int out_size)
{
    const float* x       = (const float*)d_in[0];
    const float* w_qkv   = (const float*)d_in[1];
    const float* w_proj  = (const float*)d_in[2];
    const int* mask_head  = (const int*)d_in[3];
    const int* mask_child = (const int*)d_in[4];

    float* out = (float*)d_out;
    float* arc = out + (size_t)B_DIM * S_DIM * E_DIM;

    float* qkvbuf = nullptr;
    __nv_bfloat16 *xh, *xl, *wqh, *wql, *wph, *wpl, *hoh, *hol;
    cudaGetSymbolAddress((void**)&qkvbuf, g_qkv);
    cudaGetSymbolAddress((void**)&xh, g_xh);
    cudaGetSymbolAddress((void**)&xl, g_xl);
    cudaGetSymbolAddress((void**)&wqh, g_wqh);
    cudaGetSymbolAddress((void**)&wql, g_wql);
    cudaGetSymbolAddress((void**)&wph, g_wph);
    cudaGetSymbolAddress((void**)&wpl, g_wpl);
    cudaGetSymbolAddress((void**)&hoh, g_hoh);
    cudaGetSymbolAddress((void**)&hol, g_hol);

    const int gemm_smem = 2 * SSTG;   // 81920 -> 2 CTAs/SM
    cudaFuncSetAttribute(gemm_bf,
                         cudaFuncAttributeMaxDynamicSharedMemorySize, gemm_smem);
    cudaFuncSetAttribute(flash_kernel,
                         cudaFuncAttributeMaxDynamicSharedMemorySize,
                         (int)(4u * 64u * 65u * sizeof(float)));

    // 0) pre-split inputs into bf16 hi/lo
    {
        int n4x = (B_DIM * S_DIM * E_DIM) / 4;
        split_kernel<<<(n4x + 255) / 256, 256>>>(x, xh, xl, n4x);
        int n4q = (E3 * E_DIM) / 4;
        split_kernel<<<(n4q + 255) / 256, 256>>>(w_qkv, wqh, wql, n4q);
        int n4p = (E_DIM * E_DIM) / 4;
        split_kernel<<<(n4p + 255) / 256, 256>>>(w_proj, wph, wpl, n4p);
    }

    // 1) qkv = x @ w_qkv^T   [2048 x 3072 x 1024]
    {
        dim3 grid(E3 / 128, (B_DIM * S_DIM) / 128);
        gemm_bf<<<grid, 256, gemm_smem>>>(xh, xl, wqh, wql, qkvbuf, E3, E_DIM);
    }

    // 2) fused attention + sigmoid side output + bf16 head-out
    {
        size_t smem = 4u * 64u * 65u * sizeof(float);
        dim3 grid(S_DIM / 64, B_DIM * MH);
        flash_kernel<<<grid, 256, smem>>>(qkvbuf, mask_head, mask_child,
                                          arc, hoh, hol);
    }

    // 3) out = headout @ w_proj^T   [2048 x 1024 x 1024]
    {
        dim3 grid(E_DIM / 128, (B_DIM * S_DIM) / 128);
        gemm_bf<<<grid, 256, gemm_smem>>>(hoh, hol, wph, wpl, out, E_DIM, E_DIM);
    }
}

// round 11
// speedup vs baseline: 2.4835x; 1.3221x over previous
#include <cuda_runtime.h>
#include <cuda_bf16.h>
#include <cstdint>

#define B_DIM 2
#define S_DIM 1024
#define E_DIM 1024
#define MH    16
#define DH    64
#define E3    3072

// Scratch (no cudaMalloc allowed)
__device__ float g_qkv[B_DIM * S_DIM * E3];              // [B*S, 3E] fp32
__device__ __nv_bfloat16 g_qkvh[B_DIM * S_DIM * E3];     // qkv hi/lo
__device__ __nv_bfloat16 g_qkvl[B_DIM * S_DIM * E3];
__device__ __nv_bfloat16 g_xh[B_DIM * S_DIM * E_DIM];    // x hi/lo
__device__ __nv_bfloat16 g_xl[B_DIM * S_DIM * E_DIM];
__device__ __nv_bfloat16 g_wqh[E3 * E_DIM];              // w_qkv hi/lo
__device__ __nv_bfloat16 g_wql[E3 * E_DIM];
__device__ __nv_bfloat16 g_wph[E_DIM * E_DIM];           // w_proj hi/lo
__device__ __nv_bfloat16 g_wpl[E_DIM * E_DIM];
__device__ __nv_bfloat16 g_hoh[B_DIM * S_DIM * E_DIM];   // head-out hi/lo
__device__ __nv_bfloat16 g_hol[B_DIM * S_DIM * E_DIM];

__device__ __forceinline__ uint32_t smem_u32(const void* p) {
    uint32_t a;
    asm("{ .reg .u64 t; cvta.to.shared.u64 t, %1; cvt.u32.u64 %0, t; }"
        : "=r"(a) : "l"(p));
    return a;
}

__device__ __forceinline__ uint32_t pack_bf2(__nv_bfloat16 lo, __nv_bfloat16 hi) {
    return (uint32_t)__bfloat16_as_ushort(lo) | ((uint32_t)__bfloat16_as_ushort(hi) << 16);
}

__device__ __forceinline__ void mma16816(float* d, const uint32_t* a,
                                         uint32_t b0, uint32_t b1) {
    asm volatile(
        "mma.sync.aligned.m16n8k16.row.col.f32.bf16.bf16.f32 "
        "{%0,%1,%2,%3}, {%4,%5,%6,%7}, {%8,%9}, {%0,%1,%2,%3};"
        : "+f"(d[0]), "+f"(d[1]), "+f"(d[2]), "+f"(d[3])
        : "r"(a[0]), "r"(a[1]), "r"(a[2]), "r"(a[3]), "r"(b0), "r"(b1));
}

__device__ __forceinline__ void ldsm4(uint32_t* d, uint32_t addr) {
    asm volatile("ldmatrix.sync.aligned.m8n8.x4.shared.b16 {%0,%1,%2,%3}, [%4];"
        : "=r"(d[0]), "=r"(d[1]), "=r"(d[2]), "=r"(d[3]) : "r"(addr));
}

__device__ __forceinline__ void ldsm4t(uint32_t* d, uint32_t addr) {
    asm volatile("ldmatrix.sync.aligned.m8n8.x4.trans.shared.b16 {%0,%1,%2,%3}, [%4];"
        : "=r"(d[0]), "=r"(d[1]), "=r"(d[2]), "=r"(d[3]) : "r"(addr));
}

__device__ __forceinline__ void cpa16(uint32_t dst, const void* src) {
    asm volatile("cp.async.cg.shared.global [%0], [%1], 16;"
                 :: "r"(dst), "l"(src));
}

// ---------------------------------------------------------------------------
// Pre-pass: split fp32 -> bf16 hi/lo (vectorized, one-shot)
// ---------------------------------------------------------------------------
__global__ void split_kernel(const float* __restrict__ in,
                             __nv_bfloat16* __restrict__ hi,
                             __nv_bfloat16* __restrict__ lo, int n4)
{
    int i = blockIdx.x * blockDim.x + threadIdx.x;
    if (i >= n4) return;
    float4 v = *(const float4*)(in + i * 4);
    __nv_bfloat16 h0 = __float2bfloat16(v.x);
    __nv_bfloat16 h1 = __float2bfloat16(v.y);
    __nv_bfloat16 h2 = __float2bfloat16(v.z);
    __nv_bfloat16 h3 = __float2bfloat16(v.w);
    __nv_bfloat16 l0 = __float2bfloat16(v.x - __bfloat162float(h0));
    __nv_bfloat16 l1 = __float2bfloat16(v.y - __bfloat162float(h1));
    __nv_bfloat16 l2 = __float2bfloat16(v.z - __bfloat162float(h2));
    __nv_bfloat16 l3 = __float2bfloat16(v.w - __bfloat162float(h3));
    *(uint2*)(hi + i * 4) = make_uint2(pack_bf2(h0, h1), pack_bf2(h2, h3));
    *(uint2*)(lo + i * 4) = make_uint2(pack_bf2(l0, l1), pack_bf2(l2, l3));
}

// ---------------------------------------------------------------------------
// HMMA GEMM on pre-split bf16 (unchanged from R10)
// ---------------------------------------------------------------------------
#define RSTR  80
#define TSZb  (128 * RSTR)
#define SSTG  (4 * TSZb)

__global__ __launch_bounds__(256, 2) void gemm_bf(
    const __nv_bfloat16* __restrict__ Ah_, const __nv_bfloat16* __restrict__ Al_,
    const __nv_bfloat16* __restrict__ Wh_, const __nv_bfloat16* __restrict__ Wl_,
    float* __restrict__ C, int Nn, int Kn)
{
    extern __shared__ char smem[];
    uint32_t sb = smem_u32(smem);

    int tid = threadIdx.x;
    int lane = tid & 31, wid = tid >> 5;
    int wm = wid >> 1, wn = wid & 1;
    int g = lane >> 2, t = lane & 3;
    int row0 = blockIdx.y * 128;
    int col0 = blockIdx.x * 128;

    int qm = lane >> 3, rm = lane & 7;
    uint32_t aOff = (uint32_t)(((qm & 1) * 8 + rm) * RSTR + (qm >> 1) * 16);
    uint32_t bOff = (uint32_t)(((qm >> 1) * 8 + rm) * RSTR + (qm & 1) * 16);

    float acc[2][8][4];
#pragma unroll
    for (int mt = 0; mt < 2; mt++)
#pragma unroll
        for (int j = 0; j < 8; j++)
#pragma unroll
            for (int q = 0; q < 4; q++) acc[mt][j][q] = 0.0f;

    int r = tid >> 1;
    int half = tid & 1;
    const char* srcAh = (const char*)(Ah_ + (size_t)(row0 + r) * Kn) + half * 32;
    const char* srcAl = (const char*)(Al_ + (size_t)(row0 + r) * Kn) + half * 32;
    const char* srcWh = (const char*)(Wh_ + (size_t)(col0 + r) * Kn) + half * 32;
    const char* srcWl = (const char*)(Wl_ + (size_t)(col0 + r) * Kn) + half * 32;
    uint32_t dstOff = (uint32_t)(r * RSTR + half * 32);

    uint32_t aRow0 = (uint32_t)((wm * 32) * RSTR);
    uint32_t bRow0 = (uint32_t)((wn * 64) * RSTR);

    int nChunks = Kn >> 5;

    {
        uint32_t base = sb + dstOff;
        cpa16(base, srcAh);               cpa16(base + 16, srcAh + 16);
        cpa16(base + TSZb, srcAl);        cpa16(base + TSZb + 16, srcAl + 16);
        cpa16(base + 2 * TSZb, srcWh);    cpa16(base + 2 * TSZb + 16, srcWh + 16);
        cpa16(base + 3 * TSZb, srcWl);    cpa16(base + 3 * TSZb + 16, srcWl + 16);
        asm volatile("cp.async.commit_group;");
    }

    for (int c = 0; c < nChunks; c++) {
        int s = c & 1;

        if (c + 1 < nChunks) {
            uint32_t base = sb + (uint32_t)((s ^ 1) * SSTG) + dstOff;
            int cb = (c + 1) * 64;
            cpa16(base, srcAh + cb);              cpa16(base + 16, srcAh + cb + 16);
            cpa16(base + TSZb, srcAl + cb);       cpa16(base + TSZb + 16, srcAl + cb + 16);
            cpa16(base + 2 * TSZb, srcWh + cb);   cpa16(base + 2 * TSZb + 16, srcWh + cb + 16);
            cpa16(base + 3 * TSZb, srcWl + cb);   cpa16(base + 3 * TSZb + 16, srcWl + cb + 16);
            asm volatile("cp.async.commit_group;");
            asm volatile("cp.async.wait_group 1;");
        } else {
            asm volatile("cp.async.wait_group 0;");
        }
        __syncthreads();

        uint32_t stg = sb + (uint32_t)(s * SSTG);

#pragma unroll
        for (int ks = 0; ks < 2; ks++) {
            uint32_t kb0 = (uint32_t)(ks * 32);

            uint32_t ah[2][4], al[2][4];
            ldsm4(ah[0], stg + aRow0 + kb0 + aOff);
            ldsm4(ah[1], stg + aRow0 + 16 * RSTR + kb0 + aOff);
            ldsm4(al[0], stg + TSZb + aRow0 + kb0 + aOff);
            ldsm4(al[1], stg + TSZb + aRow0 + 16 * RSTR + kb0 + aOff);

            uint32_t bh[4][4], bl[4][4];
#pragma unroll
            for (int jj = 0; jj < 4; jj++) {
                uint32_t bbase = stg + bRow0 + (uint32_t)(jj * 16 * RSTR) + kb0 + bOff;
                ldsm4(bh[jj], bbase + 2 * TSZb);
                ldsm4(bl[jj], bbase + 3 * TSZb);
            }

#pragma unroll
            for (int jj = 0; jj < 4; jj++) {
                int j0 = jj * 2, j1 = jj * 2 + 1;
                mma16816(acc[0][j0], ah[0], bh[jj][0], bh[jj][1]);
                mma16816(acc[1][j0], ah[1], bh[jj][0], bh[jj][1]);
                mma16816(acc[0][j1], ah[0], bh[jj][2], bh[jj][3]);
                mma16816(acc[1][j1], ah[1], bh[jj][2], bh[jj][3]);
            }
#pragma unroll
            for (int jj = 0; jj < 4; jj++) {
                int j0 = jj * 2, j1 = jj * 2 + 1;
                mma16816(acc[0][j0], ah[0], bl[jj][0], bl[jj][1]);
                mma16816(acc[1][j0], ah[1], bl[jj][0], bl[jj][1]);
                mma16816(acc[0][j1], ah[0], bl[jj][2], bl[jj][3]);
                mma16816(acc[1][j1], ah[1], bl[jj][2], bl[jj][3]);
            }
#pragma unroll
            for (int jj = 0; jj < 4; jj++) {
                int j0 = jj * 2, j1 = jj * 2 + 1;
                mma16816(acc[0][j0], al[0], bh[jj][0], bh[jj][1]);
                mma16816(acc[1][j0], al[1], bh[jj][0], bh[jj][1]);
                mma16816(acc[0][j1], al[0], bh[jj][2], bh[jj][3]);
                mma16816(acc[1][j1], al[1], bh[jj][2], bh[jj][3]);
            }
        }
        __syncthreads();
    }

#pragma unroll
    for (int mt = 0; mt < 2; mt++) {
        int rr = row0 + wm * 32 + mt * 16 + g;
#pragma unroll
        for (int j = 0; j < 8; j++) {
            int cc = col0 + wn * 64 + j * 8 + t * 2;
            *(float2*)(C + (size_t)rr * Nn + cc) =
                make_float2(acc[mt][j][0], acc[mt][j][1]);
            *(float2*)(C + (size_t)(rr + 8) * Nn + cc) =
                make_float2(acc[mt][j][2], acc[mt][j][3]);
        }
    }
}

// ---------------------------------------------------------------------------
// HMMA flash attention: q-block 128, 8 warps x m16, key tiles 64.
// hi/lo bf16 split on Q,K,P,V (3-product). P stays in registers.
// ---------------------------------------------------------------------------
#define FSTR   144
#define FQH    0
#define FQL    18432        /* 128*144 */
#define FKV    36864
#define FKVSTG 36864        /* 4 * 64*144 */
#define FKH    0
#define FKL    9216
#define FVH    18432
#define FVL    27648
#define FSMEM  110592

__global__ __launch_bounds__(256, 2) void flash_mma(
    const __nv_bfloat16* __restrict__ qkvh,
    const __nv_bfloat16* __restrict__ qkvl,
    const int* __restrict__ mask_head,
    const int* __restrict__ mask_child,
    float* __restrict__ arc,
    __nv_bfloat16* __restrict__ hoh,
    __nv_bfloat16* __restrict__ hol)
{
    extern __shared__ char fsm[];
    uint32_t sb = smem_u32(fsm);

    int tid = threadIdx.x;
    int lane = tid & 31, w = tid >> 5;
    int g = lane >> 2, t = lane & 3;
    int qm = lane >> 3, rm = lane & 7;

    // pair heavy/light q-blocks across SM-sharing bids
    const int perm[8] = {0, 1, 2, 3, 7, 6, 5, 4};
    int qbx = perm[blockIdx.x];
    int qi0 = qbx * 128;
    int bhx = blockIdx.y;
    int b = bhx >> 4, h = bhx & 15;

    const int* maskp = ((h < 8) ? mask_head : mask_child) + (size_t)b * S_DIM * S_DIM;
    const __nv_bfloat16* qh_g = qkvh + (size_t)b * S_DIM * E3 + h * DH;
    const __nv_bfloat16* ql_g = qkvl + (size_t)b * S_DIM * E3 + h * DH;
    const char* kh_g = (const char*)(qh_g + E_DIM);
    const char* kl_g = (const char*)(ql_g + E_DIM);
    const char* vh_g = (const char*)(qh_g + 2 * E_DIM);
    const char* vl_g = (const char*)(ql_g + 2 * E_DIM);
    const size_t rowB = (size_t)E3 * 2;   // bytes per token row

    // ---- Q load (cp.async group 0): 128 rows x 128B, hi+lo ----
    {
        int r = tid >> 1, hf = tid & 1;
        const char* sh = (const char*)(qh_g + (size_t)(qi0 + r) * E3) + hf * 64;
        const char* sl = (const char*)(ql_g + (size_t)(qi0 + r) * E3) + hf * 64;
        uint32_t d = sb + (uint32_t)(r * FSTR + hf * 64);
#pragma unroll
        for (int i = 0; i < 4; i++) {
            cpa16(d + i * 16, sh + i * 16);
            cpa16(d + FQL + i * 16, sl + i * 16);
        }
        asm volatile("cp.async.commit_group;");
    }

    int nT = 2 * qbx + 2;    // processed key tiles (causal)
    int r2 = tid >> 2, q4 = tid & 3;

    // ---- KV tile 0 prefetch (group 1) ----
    {
        size_t so = (size_t)r2 * rowB + q4 * 32;
        uint32_t d = sb + FKV + (uint32_t)(r2 * FSTR + q4 * 32);
        cpa16(d + FKH, kh_g + so);        cpa16(d + FKH + 16, kh_g + so + 16);
        cpa16(d + FKL, kl_g + so);        cpa16(d + FKL + 16, kl_g + so + 16);
        cpa16(d + FVH, vh_g + so);        cpa16(d + FVH + 16, vh_g + so + 16);
        cpa16(d + FVL, vl_g + so);        cpa16(d + FVL + 16, vl_g + so + 16);
        asm volatile("cp.async.commit_group;");
    }

    // ---- zero-fill arc for tiles above the causal diagonal ----
    float* arcw = arc + (size_t)bhx * S_DIM * S_DIM;
    {
        int zr = qi0 + (tid >> 1);
        int zc = (tid & 1) * 32;
        float4 z = make_float4(0.f, 0.f, 0.f, 0.f);
        for (int kj = nT; kj < S_DIM / 64; kj++) {
            float* p = arcw + (size_t)zr * S_DIM + kj * 64 + zc;
#pragma unroll
            for (int i = 0; i < 8; i++) *(float4*)(p + i * 4) = z;
        }
    }

    uint32_t aOff = (uint32_t)(((qm & 1) * 8 + rm) * FSTR + (qm >> 1) * 16);
    uint32_t bOff = (uint32_t)(((qm >> 1) * 8 + rm) * FSTR + (qm & 1) * 16);
    uint32_t qBase = sb + (uint32_t)(w * 16 * FSTR);

    float m0 = -1e30f, m1 = -1e30f, l0s = 0.f, l1s = 0.f;
    float oacc[8][4];
#pragma unroll
    for (int i = 0; i < 8; i++)
#pragma unroll
        for (int q = 0; q < 4; q++) oacc[i][q] = 0.f;

    int ig0 = qi0 + w * 16 + g;
    int ig1 = ig0 + 8;
    const int* mr0 = maskp + (size_t)ig0 * S_DIM;
    const int* mr1 = maskp + (size_t)ig1 * S_DIM;
    float* ar0 = arcw + (size_t)ig0 * S_DIM;
    float* ar1 = arcw + (size_t)ig1 * S_DIM;
    const float INV64 = 1.0f / 64.0f;

    for (int kj = 0; kj < nT; kj++) {
        int s = kj & 1;
        uint32_t kvb = sb + FKV + (uint32_t)(s * FKVSTG);

        if (kj + 1 < nT) {
            size_t so = (size_t)((kj + 1) * 64 + r2) * rowB + q4 * 32;
            uint32_t d = sb + FKV + (uint32_t)((s ^ 1) * FKVSTG)
                       + (uint32_t)(r2 * FSTR + q4 * 32);
            cpa16(d + FKH, kh_g + so);        cpa16(d + FKH + 16, kh_g + so + 16);
            cpa16(d + FKL, kl_g + so);        cpa16(d + FKL + 16, kl_g + so + 16);
            cpa16(d + FVH, vh_g + so);        cpa16(d + FVH + 16, vh_g + so + 16);
            cpa16(d + FVL, vl_g + so);        cpa16(d + FVL + 16, vl_g + so + 16);
            asm volatile("cp.async.commit_group;");
            asm volatile("cp.async.wait_group 1;");
        } else {
            asm volatile("cp.async.wait_group 0;");
        }
        __syncthreads();

        // ---- QK^T: sacc[8 n8-tiles][4] ----
        float sc_[8][4];
#pragma unroll
        for (int i = 0; i < 8; i++)
#pragma unroll
            for (int q = 0; q < 4; q++) sc_[i][q] = 0.f;

#pragma unroll
        for (int ks = 0; ks < 4; ks++) {
            uint32_t qa = qBase + (uint32_t)(ks * 32) + aOff;
            uint32_t qh_f[4], ql_f[4];
            ldsm4(qh_f, qa);
            ldsm4(ql_f, qa + FQL);
#pragma unroll
            for (int jj = 0; jj < 4; jj++) {
                uint32_t ka = kvb + (uint32_t)(jj * 16 * FSTR + ks * 32) + bOff;
                uint32_t kh_f[4], kl_f[4];
                ldsm4(kh_f, ka + FKH);
                ldsm4(kl_f, ka + FKL);
                int j0 = jj * 2, j1 = jj * 2 + 1;
                mma16816(sc_[j0], qh_f, kh_f[0], kh_f[1]);
                mma16816(sc_[j1], qh_f, kh_f[2], kh_f[3]);
                mma16816(sc_[j0], qh_f, kl_f[0], kl_f[1]);
                mma16816(sc_[j1], qh_f, kl_f[2], kl_f[3]);
                mma16816(sc_[j0], ql_f, kh_f[0], kh_f[1]);
                mma16816(sc_[j1], ql_f, kh_f[2], kh_f[3]);
            }
        }

        // ---- mask + sigmoid side-output + u = exp(s) ----
        int j0b = kj * 64;
        float u[8][4];
        float mt0 = -1e30f, mt1 = -1e30f;
#pragma unroll
        for (int tl = 0; tl < 8; tl++) {
            int jg = j0b + tl * 8 + t * 2;
            int2 mk0 = *(const int2*)(mr0 + jg);
            int2 mk1 = *(const int2*)(mr1 + jg);
            float s00 = sc_[tl][0] * INV64;
            float s01 = sc_[tl][1] * INV64;
            float s10 = sc_[tl][2] * INV64;
            float s11 = sc_[tl][3] * INV64;
            if (!((jg     <= ig0) && mk0.x)) s00 = -1e30f;
            if (!((jg + 1 <= ig0) && mk0.y)) s01 = -1e30f;
            if (!((jg     <= ig1) && mk1.x)) s10 = -1e30f;
            if (!((jg + 1 <= ig1) && mk1.y)) s11 = -1e30f;
            float u00 = __expf(s00), u01 = __expf(s01);
            float u10 = __expf(s10), u11 = __expf(s11);
            u[tl][0] = u00; u[tl][1] = u01; u[tl][2] = u10; u[tl][3] = u11;
            *(float2*)(ar0 + jg) = make_float2(__fdividef(u00, 1.f + u00),
                                               __fdividef(u01, 1.f + u01));
            *(float2*)(ar1 + jg) = make_float2(__fdividef(u10, 1.f + u10),
                                               __fdividef(u11, 1.f + u11));
            mt0 = fmaxf(mt0, fmaxf(s00, s01));
            mt1 = fmaxf(mt1, fmaxf(s10, s11));
        }
        mt0 = fmaxf(mt0, __shfl_xor_sync(0xffffffffu, mt0, 1));
        mt0 = fmaxf(mt0, __shfl_xor_sync(0xffffffffu, mt0, 2));
        mt1 = fmaxf(mt1, __shfl_xor_sync(0xffffffffu, mt1, 1));
        mt1 = fmaxf(mt1, __shfl_xor_sync(0xffffffffu, mt1, 2));

        float mn0 = fmaxf(fmaxf(m0, mt0), -80.f);
        float mn1 = fmaxf(fmaxf(m1, mt1), -80.f);
        float rc0 = __expf(m0 - mn0), rc1 = __expf(m1 - mn1);
        float ce0 = __expf(-mn0), ce1 = __expf(-mn1);

        float su0 = 0.f, su1 = 0.f;
#pragma unroll
        for (int tl = 0; tl < 8; tl++) {
            su0 += u[tl][0] + u[tl][1];
            su1 += u[tl][2] + u[tl][3];
        }
        su0 += __shfl_xor_sync(0xffffffffu, su0, 1);
        su0 += __shfl_xor_sync(0xffffffffu, su0, 2);
        su1 += __shfl_xor_sync(0xffffffffu, su1, 1);
        su1 += __shfl_xor_sync(0xffffffffu, su1, 2);

        l0s = l0s * rc0 + su0 * ce0;
        l1s = l1s * rc1 + su1 * ce1;
        m0 = mn0; m1 = mn1;
#pragma unroll
        for (int nt = 0; nt < 8; nt++) {
            oacc[nt][0] *= rc0; oacc[nt][1] *= rc0;
            oacc[nt][2] *= rc1; oacc[nt][3] *= rc1;
        }

        // ---- PV: P built from registers (C-frag == A-frag layout) ----
#pragma unroll
        for (int kk = 0; kk < 4; kk++) {
            int ta = 2 * kk, tb = 2 * kk + 1;
            float pa0 = u[ta][0] * ce0, pa1 = u[ta][1] * ce0;
            float pa2 = u[ta][2] * ce1, pa3 = u[ta][3] * ce1;
            float pb0 = u[tb][0] * ce0, pb1 = u[tb][1] * ce0;
            float pb2 = u[tb][2] * ce1, pb3 = u[tb][3] * ce1;

            __nv_bfloat16 ha0 = __float2bfloat16(pa0), ha1 = __float2bfloat16(pa1);
            __nv_bfloat16 ha2 = __float2bfloat16(pa2), ha3 = __float2bfloat16(pa3);
            __nv_bfloat16 hb0 = __float2bfloat16(pb0), hb1 = __float2bfloat16(pb1);
            __nv_bfloat16 hb2 = __float2bfloat16(pb2), hb3 = __float2bfloat16(pb3);

            uint32_t aPh[4], aPl[4];
            aPh[0] = pack_bf2(ha0, ha1);
            aPh[1] = pack_bf2(ha2, ha3);
            aPh[2] = pack_bf2(hb0, hb1);
            aPh[3] = pack_bf2(hb2, hb3);
            aPl[0] = pack_bf2(__float2bfloat16(pa0 - __bfloat162float(ha0)),
                              __float2bfloat16(pa1 - __bfloat162float(ha1)));
            aPl[1] = pack_bf2(__float2bfloat16(pa2 - __bfloat162float(ha2)),
                              __float2bfloat16(pa3 - __bfloat162float(ha3)));
            aPl[2] = pack_bf2(__float2bfloat16(pb0 - __bfloat162float(hb0)),
                              __float2bfloat16(pb1 - __bfloat162float(hb1)));
            aPl[3] = pack_bf2(__float2bfloat16(pb2 - __bfloat162float(hb2)),
                              __float2bfloat16(pb3 - __bfloat162float(hb3)));

#pragma unroll
            for (int np = 0; np < 4; np++) {
                uint32_t va = kvb + (uint32_t)(kk * 16 * FSTR + np * 32) + aOff;
                uint32_t vh_f[4], vl_f[4];
                ldsm4t(vh_f, va + FVH);
                ldsm4t(vl_f, va + FVL);
                int n0 = np * 2, n1 = np * 2 + 1;
                mma16816(oacc[n0], aPh, vh_f[0], vh_f[1]);
                mma16816(oacc[n1], aPh, vh_f[2], vh_f[3]);
                mma16816(oacc[n0], aPh, vl_f[0], vl_f[1]);
                mma16816(oacc[n1], aPh, vl_f[2], vl_f[3]);
                mma16816(oacc[n0], aPl, vh_f[0], vh_f[1]);
                mma16816(oacc[n1], aPl, vh_f[2], vh_f[3]);
            }
        }
        __syncthreads();
    }

    // ---- epilogue: O/l -> bf16 hi/lo, head-major [B,S,E] ----
    float i0 = (l0s > 0.f) ? (1.0f / l0s) : 0.f;
    float i1 = (l1s > 0.f) ? (1.0f / l1s) : 0.f;
#pragma unroll
    for (int nt = 0; nt < 8; nt++) {
        int col = h * DH + nt * 8 + t * 2;
        float o00 = oacc[nt][0] * i0, o01 = oacc[nt][1] * i0;
        float o10 = oacc[nt][2] * i1, o11 = oacc[nt][3] * i1;
        __nv_bfloat16 h00 = __float2bfloat16(o00), h01 = __float2bfloat16(o01);
        __nv_bfloat16 h10 = __float2bfloat16(o10), h11 = __float2bfloat16(o11);
        size_t idx0 = ((size_t)b * S_DIM + ig0) * E_DIM + col;
        size_t idx1 = ((size_t)b * S_DIM + ig1) * E_DIM + col;
        *(uint32_t*)(hoh + idx0) = pack_bf2(h00, h01);
        *(uint32_t*)(hoh + idx1) = pack_bf2(h10, h11);
        *(uint32_t*)(hol + idx0) =
            pack_bf2(__float2bfloat16(o00 - __bfloat162float(h00)),
                     __float2bfloat16(o01 - __bfloat162float(h01)));
        *(uint32_t*)(hol + idx1) =
            pack_bf2(__float2bfloat16(o10 - __bfloat162float(h10)),
                     __float2bfloat16(o11 - __bfloat162float(h11)));
    }
}

// ---------------------------------------------------------------------------
extern "C" void kernel_launch(void* const* d_in, const int* in_sizes, int n_in,
                              void* d_out, int out_size)
{
    const float* x       = (const float*)d_in[0];
    const float* w_qkv   = (const float*)d_in[1];
    const float* w_proj  = (const float*)d_in[2];
    const int* mask_head  = (const int*)d_in[3];
    const int* mask_child = (const int*)d_in[4];

    float* out = (float*)d_out;
    float* arc = out + (size_t)B_DIM * S_DIM * E_DIM;

    float* qkvbuf = nullptr;
    __nv_bfloat16 *qkvh, *qkvl, *xh, *xl, *wqh, *wql, *wph, *wpl, *hoh, *hol;
    cudaGetSymbolAddress((void**)&qkvbuf, g_qkv);
    cudaGetSymbolAddress((void**)&qkvh, g_qkvh);
    cudaGetSymbolAddress((void**)&qkvl, g_qkvl);
    cudaGetSymbolAddress((void**)&xh, g_xh);
    cudaGetSymbolAddress((void**)&xl, g_xl);
    cudaGetSymbolAddress((void**)&wqh, g_wqh);
    cudaGetSymbolAddress((void**)&wql, g_wql);
    cudaGetSymbolAddress((void**)&wph, g_wph);
    cudaGetSymbolAddress((void**)&wpl, g_wpl);
    cudaGetSymbolAddress((void**)&hoh, g_hoh);
    cudaGetSymbolAddress((void**)&hol, g_hol);

    const int gemm_smem = 2 * SSTG;
    cudaFuncSetAttribute(gemm_bf,
                         cudaFuncAttributeMaxDynamicSharedMemorySize, gemm_smem);
    cudaFuncSetAttribute(flash_mma,
                         cudaFuncAttributeMaxDynamicSharedMemorySize, FSMEM);

    // 0) pre-split inputs into bf16 hi/lo
    {
        int n4x = (B_DIM * S_DIM * E_DIM) / 4;
        split_kernel<<<(n4x + 255) / 256, 256>>>(x, xh, xl, n4x);
        int n4q = (E3 * E_DIM) / 4;
        split_kernel<<<(n4q + 255) / 256, 256>>>(w_qkv, wqh, wql, n4q);
        int n4p = (E_DIM * E_DIM) / 4;
        split_kernel<<<(n4p + 255) / 256, 256>>>(w_proj, wph, wpl, n4p);
    }

    // 1) qkv = x @ w_qkv^T   [2048 x 3072 x 1024]
    {
        dim3 grid(E3 / 128, (B_DIM * S_DIM) / 128);
        gemm_bf<<<grid, 256, gemm_smem>>>(xh, xl, wqh, wql, qkvbuf, E3, E_DIM);
    }

    // 1b) split qkv into bf16 hi/lo for the attention kernel
    {
        int n4 = (B_DIM * S_DIM * E3) / 4;
        split_kernel<<<(n4 + 255) / 256, 256>>>(qkvbuf, qkvh, qkvl, n4);
    }

    // 2) HMMA flash attention + sigmoid side output + bf16 head-out
    {
        dim3 grid(S_DIM / 128, B_DIM * MH);
        flash_mma<<<grid, 256, FSMEM>>>(qkvh, qkvl, mask_head, mask_child,
                                        arc, hoh, hol);
    }

    // 3) out = headout @ w_proj^T   [2048 x 1024 x 1024]
    {
        dim3 grid(E_DIM / 128, (B_DIM * S_DIM) / 128);
        gemm_bf<<<grid, 256, gemm_smem>>>(hoh, hol, wph, wpl, out, E_DIM, E_DIM);
    }
}

// round 12
// speedup vs baseline: 2.5571x; 1.0296x over previous
#include <cuda_runtime.h>
#include <cuda_bf16.h>
#include <cstdint>

#define B_DIM 2
#define S_DIM 1024
#define E_DIM 1024
#define MH    16
#define DH    64
#define E3    3072

// Scratch (no cudaMalloc allowed)
__device__ __nv_bfloat16 g_qkvh[B_DIM * S_DIM * E3];     // qkv hi/lo
__device__ __nv_bfloat16 g_qkvl[B_DIM * S_DIM * E3];
__device__ __nv_bfloat16 g_xh[B_DIM * S_DIM * E_DIM];    // x hi/lo
__device__ __nv_bfloat16 g_xl[B_DIM * S_DIM * E_DIM];
__device__ __nv_bfloat16 g_wqh[E3 * E_DIM];              // w_qkv hi/lo
__device__ __nv_bfloat16 g_wql[E3 * E_DIM];
__device__ __nv_bfloat16 g_wph[E_DIM * E_DIM];           // w_proj hi/lo
__device__ __nv_bfloat16 g_wpl[E_DIM * E_DIM];
__device__ __nv_bfloat16 g_hoh[B_DIM * S_DIM * E_DIM];   // head-out hi/lo
__device__ __nv_bfloat16 g_hol[B_DIM * S_DIM * E_DIM];

__device__ __forceinline__ uint32_t smem_u32(const void* p) {
    uint32_t a;
    asm("{ .reg .u64 t; cvta.to.shared.u64 t, %1; cvt.u32.u64 %0, t; }"
        : "=r"(a) : "l"(p));
    return a;
}

__device__ __forceinline__ uint32_t pack_bf2(__nv_bfloat16 lo, __nv_bfloat16 hi) {
    return (uint32_t)__bfloat16_as_ushort(lo) | ((uint32_t)__bfloat16_as_ushort(hi) << 16);
}

__device__ __forceinline__ void mma16816(float* d, const uint32_t* a,
                                         uint32_t b0, uint32_t b1) {
    asm volatile(
        "mma.sync.aligned.m16n8k16.row.col.f32.bf16.bf16.f32 "
        "{%0,%1,%2,%3}, {%4,%5,%6,%7}, {%8,%9}, {%0,%1,%2,%3};"
        : "+f"(d[0]), "+f"(d[1]), "+f"(d[2]), "+f"(d[3])
        : "r"(a[0]), "r"(a[1]), "r"(a[2]), "r"(a[3]), "r"(b0), "r"(b1));
}

__device__ __forceinline__ void ldsm4(uint32_t* d, uint32_t addr) {
    asm volatile("ldmatrix.sync.aligned.m8n8.x4.shared.b16 {%0,%1,%2,%3}, [%4];"
        : "=r"(d[0]), "=r"(d[1]), "=r"(d[2]), "=r"(d[3]) : "r"(addr));
}

__device__ __forceinline__ void ldsm4t(uint32_t* d, uint32_t addr) {
    asm volatile("ldmatrix.sync.aligned.m8n8.x4.trans.shared.b16 {%0,%1,%2,%3}, [%4];"
        : "=r"(d[0]), "=r"(d[1]), "=r"(d[2]), "=r"(d[3]) : "r"(addr));
}

__device__ __forceinline__ void cpa16(uint32_t dst, const void* src) {
    asm volatile("cp.async.cg.shared.global [%0], [%1], 16;"
                 :: "r"(dst), "l"(src));
}

// ---------------------------------------------------------------------------
// Pre-pass: split fp32 -> bf16 hi/lo (vectorized, one-shot)
// ---------------------------------------------------------------------------
__global__ void split_kernel(const float* __restrict__ in,
                             __nv_bfloat16* __restrict__ hi,
                             __nv_bfloat16* __restrict__ lo, int n4)
{
    int i = blockIdx.x * blockDim.x + threadIdx.x;
    if (i >= n4) return;
    float4 v = *(const float4*)(in + i * 4);
    __nv_bfloat16 h0 = __float2bfloat16(v.x);
    __nv_bfloat16 h1 = __float2bfloat16(v.y);
    __nv_bfloat16 h2 = __float2bfloat16(v.z);
    __nv_bfloat16 h3 = __float2bfloat16(v.w);
    __nv_bfloat16 l0 = __float2bfloat16(v.x - __bfloat162float(h0));
    __nv_bfloat16 l1 = __float2bfloat16(v.y - __bfloat162float(h1));
    __nv_bfloat16 l2 = __float2bfloat16(v.z - __bfloat162float(h2));
    __nv_bfloat16 l3 = __float2bfloat16(v.w - __bfloat162float(h3));
    *(uint2*)(hi + i * 4) = make_uint2(pack_bf2(h0, h1), pack_bf2(h2, h3));
    *(uint2*)(lo + i * 4) = make_uint2(pack_bf2(l0, l1), pack_bf2(l2, l3));
}

// ---------------------------------------------------------------------------
// HMMA GEMM on pre-split bf16. Single-sync 2-stage pipeline.
// If Ch != nullptr, writes bf16 hi/lo output; else fp32 to C.
// ---------------------------------------------------------------------------
#define RSTR  80
#define TSZb  (128 * RSTR)
#define SSTG  (4 * TSZb)

__global__ __launch_bounds__(256, 2) void gemm_bf(
    const __nv_bfloat16* __restrict__ Ah_, const __nv_bfloat16* __restrict__ Al_,
    const __nv_bfloat16* __restrict__ Wh_, const __nv_bfloat16* __restrict__ Wl_,
    float* __restrict__ C,
    __nv_bfloat16* __restrict__ Ch, __nv_bfloat16* __restrict__ Cl,
    int Nn, int Kn)
{
    extern __shared__ char smem[];
    uint32_t sb = smem_u32(smem);

    int tid = threadIdx.x;
    int lane = tid & 31, wid = tid >> 5;
    int wm = wid >> 1, wn = wid & 1;
    int g = lane >> 2, t = lane & 3;
    int row0 = blockIdx.y * 128;
    int col0 = blockIdx.x * 128;

    int qm = lane >> 3, rm = lane & 7;
    uint32_t aOff = (uint32_t)(((qm & 1) * 8 + rm) * RSTR + (qm >> 1) * 16);
    uint32_t bOff = (uint32_t)(((qm >> 1) * 8 + rm) * RSTR + (qm & 1) * 16);

    float acc[2][8][4];
#pragma unroll
    for (int mt = 0; mt < 2; mt++)
#pragma unroll
        for (int j = 0; j < 8; j++)
#pragma unroll
            for (int q = 0; q < 4; q++) acc[mt][j][q] = 0.0f;

    int r = tid >> 1;
    int half = tid & 1;
    const char* srcAh = (const char*)(Ah_ + (size_t)(row0 + r) * Kn) + half * 32;
    const char* srcAl = (const char*)(Al_ + (size_t)(row0 + r) * Kn) + half * 32;
    const char* srcWh = (const char*)(Wh_ + (size_t)(col0 + r) * Kn) + half * 32;
    const char* srcWl = (const char*)(Wl_ + (size_t)(col0 + r) * Kn) + half * 32;
    uint32_t dstOff = (uint32_t)(r * RSTR + half * 32);

    uint32_t aRow0 = (uint32_t)((wm * 32) * RSTR);
    uint32_t bRow0 = (uint32_t)((wn * 64) * RSTR);

    int nChunks = Kn >> 5;

    // prologue: prefetch chunk 0 into stage 0
    {
        uint32_t base = sb + dstOff;
        cpa16(base, srcAh);               cpa16(base + 16, srcAh + 16);
        cpa16(base + TSZb, srcAl);        cpa16(base + TSZb + 16, srcAl + 16);
        cpa16(base + 2 * TSZb, srcWh);    cpa16(base + 2 * TSZb + 16, srcWh + 16);
        cpa16(base + 3 * TSZb, srcWl);    cpa16(base + 3 * TSZb + 16, srcWl + 16);
        asm volatile("cp.async.commit_group;");
    }

    for (int c = 0; c < nChunks; c++) {
        int s = c & 1;

        asm volatile("cp.async.wait_group 0;");
        __syncthreads();     // everyone done with stage s^1 compute (iter c-1)

        if (c + 1 < nChunks) {
            uint32_t base = sb + (uint32_t)((s ^ 1) * SSTG) + dstOff;
            int cb = (c + 1) * 64;
            cpa16(base, srcAh + cb);              cpa16(base + 16, srcAh + cb + 16);
            cpa16(base + TSZb, srcAl + cb);       cpa16(base + TSZb + 16, srcAl + cb + 16);
            cpa16(base + 2 * TSZb, srcWh + cb);   cpa16(base + 2 * TSZb + 16, srcWh + cb + 16);
            cpa16(base + 3 * TSZb, srcWl + cb);   cpa16(base + 3 * TSZb + 16, srcWl + cb + 16);
            asm volatile("cp.async.commit_group;");
        }

        uint32_t stg = sb + (uint32_t)(s * SSTG);

#pragma unroll
        for (int ks = 0; ks < 2; ks++) {
            uint32_t kb0 = (uint32_t)(ks * 32);

            uint32_t ah[2][4], al[2][4];
            ldsm4(ah[0], stg + aRow0 + kb0 + aOff);
            ldsm4(ah[1], stg + aRow0 + 16 * RSTR + kb0 + aOff);
            ldsm4(al[0], stg + TSZb + aRow0 + kb0 + aOff);
            ldsm4(al[1], stg + TSZb + aRow0 + 16 * RSTR + kb0 + aOff);

            uint32_t bh[4][4], bl[4][4];
#pragma unroll
            for (int jj = 0; jj < 4; jj++) {
                uint32_t bbase = stg + bRow0 + (uint32_t)(jj * 16 * RSTR) + kb0 + bOff;
                ldsm4(bh[jj], bbase + 2 * TSZb);
                ldsm4(bl[jj], bbase + 3 * TSZb);
            }

#pragma unroll
            for (int jj = 0; jj < 4; jj++) {
                int j0 = jj * 2, j1 = jj * 2 + 1;
                mma16816(acc[0][j0], ah[0], bh[jj][0], bh[jj][1]);
                mma16816(acc[1][j0], ah[1], bh[jj][0], bh[jj][1]);
                mma16816(acc[0][j1], ah[0], bh[jj][2], bh[jj][3]);
                mma16816(acc[1][j1], ah[1], bh[jj][2], bh[jj][3]);
            }
#pragma unroll
            for (int jj = 0; jj < 4; jj++) {
                int j0 = jj * 2, j1 = jj * 2 + 1;
                mma16816(acc[0][j0], ah[0], bl[jj][0], bl[jj][1]);
                mma16816(acc[1][j0], ah[1], bl[jj][0], bl[jj][1]);
                mma16816(acc[0][j1], ah[0], bl[jj][2], bl[jj][3]);
                mma16816(acc[1][j1], ah[1], bl[jj][2], bl[jj][3]);
            }
#pragma unroll
            for (int jj = 0; jj < 4; jj++) {
                int j0 = jj * 2, j1 = jj * 2 + 1;
                mma16816(acc[0][j0], al[0], bh[jj][0], bh[jj][1]);
                mma16816(acc[1][j0], al[1], bh[jj][0], bh[jj][1]);
                mma16816(acc[0][j1], al[0], bh[jj][2], bh[jj][3]);
                mma16816(acc[1][j1], al[1], bh[jj][2], bh[jj][3]);
            }
        }
    }

    // -------- epilogue --------
    if (Ch) {
#pragma unroll
        for (int mt = 0; mt < 2; mt++) {
            int rr = row0 + wm * 32 + mt * 16 + g;
#pragma unroll
            for (int j = 0; j < 8; j++) {
                int cc = col0 + wn * 64 + j * 8 + t * 2;
#pragma unroll
                for (int hh = 0; hh < 2; hh++) {
                    float v0 = acc[mt][j][hh * 2 + 0];
                    float v1 = acc[mt][j][hh * 2 + 1];
                    __nv_bfloat16 h0 = __float2bfloat16(v0);
                    __nv_bfloat16 h1 = __float2bfloat16(v1);
                    size_t idx = (size_t)(rr + hh * 8) * Nn + cc;
                    *(uint32_t*)(Ch + idx) = pack_bf2(h0, h1);
                    *(uint32_t*)(Cl + idx) =
                        pack_bf2(__float2bfloat16(v0 - __bfloat162float(h0)),
                                 __float2bfloat16(v1 - __bfloat162float(h1)));
                }
            }
        }
    } else {
#pragma unroll
        for (int mt = 0; mt < 2; mt++) {
            int rr = row0 + wm * 32 + mt * 16 + g;
#pragma unroll
            for (int j = 0; j < 8; j++) {
                int cc = col0 + wn * 64 + j * 8 + t * 2;
                *(float2*)(C + (size_t)rr * Nn + cc) =
                    make_float2(acc[mt][j][0], acc[mt][j][1]);
                *(float2*)(C + (size_t)(rr + 8) * Nn + cc) =
                    make_float2(acc[mt][j][2], acc[mt][j][3]);
            }
        }
    }
}

// ---------------------------------------------------------------------------
// HMMA flash attention (R11) — sc_ reused for u; single-sync mainloop.
// ---------------------------------------------------------------------------
#define FSTR   144
#define FQH    0
#define FQL    18432
#define FKV    36864
#define FKVSTG 36864
#define FKH    0
#define FKL    9216
#define FVH    18432
#define FVL    27648
#define FSMEM  110592

__global__ __launch_bounds__(256, 2) void flash_mma(
    const __nv_bfloat16* __restrict__ qkvh,
    const __nv_bfloat16* __restrict__ qkvl,
    const int* __restrict__ mask_head,
    const int* __restrict__ mask_child,
    float* __restrict__ arc,
    __nv_bfloat16* __restrict__ hoh,
    __nv_bfloat16* __restrict__ hol)
{
    extern __shared__ char fsm[];
    uint32_t sb = smem_u32(fsm);

    int tid = threadIdx.x;
    int lane = tid & 31, w = tid >> 5;
    int g = lane >> 2, t = lane & 3;
    int qm = lane >> 3, rm = lane & 7;

    const int perm[8] = {0, 1, 2, 3, 7, 6, 5, 4};
    int qbx = perm[blockIdx.x];
    int qi0 = qbx * 128;
    int bhx = blockIdx.y;
    int b = bhx >> 4, h = bhx & 15;

    const int* maskp = ((h < 8) ? mask_head : mask_child) + (size_t)b * S_DIM * S_DIM;
    const __nv_bfloat16* qh_g = qkvh + (size_t)b * S_DIM * E3 + h * DH;
    const __nv_bfloat16* ql_g = qkvl + (size_t)b * S_DIM * E3 + h * DH;
    const char* kh_g = (const char*)(qh_g + E_DIM);
    const char* kl_g = (const char*)(ql_g + E_DIM);
    const char* vh_g = (const char*)(qh_g + 2 * E_DIM);
    const char* vl_g = (const char*)(ql_g + 2 * E_DIM);
    const size_t rowB = (size_t)E3 * 2;

    // Q load
    {
        int r = tid >> 1, hf = tid & 1;
        const char* sh = (const char*)(qh_g + (size_t)(qi0 + r) * E3) + hf * 64;
        const char* sl = (const char*)(ql_g + (size_t)(qi0 + r) * E3) + hf * 64;
        uint32_t d = sb + (uint32_t)(r * FSTR + hf * 64);
#pragma unroll
        for (int i = 0; i < 4; i++) {
            cpa16(d + i * 16, sh + i * 16);
            cpa16(d + FQL + i * 16, sl + i * 16);
        }
        asm volatile("cp.async.commit_group;");
    }

    int nT = 2 * qbx + 2;
    int r2 = tid >> 2, q4 = tid & 3;

    // KV tile 0 prefetch
    {
        size_t so = (size_t)r2 * rowB + q4 * 32;
        uint32_t d = sb + FKV + (uint32_t)(r2 * FSTR + q4 * 32);
        cpa16(d + FKH, kh_g + so);        cpa16(d + FKH + 16, kh_g + so + 16);
        cpa16(d + FKL, kl_g + so);        cpa16(d + FKL + 16, kl_g + so + 16);
        cpa16(d + FVH, vh_g + so);        cpa16(d + FVH + 16, vh_g + so + 16);
        cpa16(d + FVL, vl_g + so);        cpa16(d + FVL + 16, vl_g + so + 16);
        asm volatile("cp.async.commit_group;");
    }

    // zero-fill arc above causal diagonal
    float* arcw = arc + (size_t)bhx * S_DIM * S_DIM;
    {
        int zr = qi0 + (tid >> 1);
        int zc = (tid & 1) * 32;
        float4 z = make_float4(0.f, 0.f, 0.f, 0.f);
        for (int kj = nT; kj < S_DIM / 64; kj++) {
            float* p = arcw + (size_t)zr * S_DIM + kj * 64 + zc;
#pragma unroll
            for (int i = 0; i < 8; i++) *(float4*)(p + i * 4) = z;
        }
    }

    uint32_t aOff = (uint32_t)(((qm & 1) * 8 + rm) * FSTR + (qm >> 1) * 16);
    uint32_t bOff = (uint32_t)(((qm >> 1) * 8 + rm) * FSTR + (qm & 1) * 16);
    uint32_t qBase = sb + (uint32_t)(w * 16 * FSTR);

    float m0 = -1e30f, m1 = -1e30f, l0s = 0.f, l1s = 0.f;
    float oacc[8][4];
#pragma unroll
    for (int i = 0; i < 8; i++)
#pragma unroll
        for (int q = 0; q < 4; q++) oacc[i][q] = 0.f;

    int ig0 = qi0 + w * 16 + g;
    int ig1 = ig0 + 8;
    const int* mr0 = maskp + (size_t)ig0 * S_DIM;
    const int* mr1 = maskp + (size_t)ig1 * S_DIM;
    float* ar0 = arcw + (size_t)ig0 * S_DIM;
    float* ar1 = arcw + (size_t)ig1 * S_DIM;
    const float INV64 = 1.0f / 64.0f;

    for (int kj = 0; kj < nT; kj++) {
        int s = kj & 1;
        uint32_t kvb = sb + FKV + (uint32_t)(s * FKVSTG);

        asm volatile("cp.async.wait_group 0;");
        __syncthreads();   // all threads done reading stage s^1 (iter kj-1)

        if (kj + 1 < nT) {
            size_t so = (size_t)((kj + 1) * 64 + r2) * rowB + q4 * 32;
            uint32_t d = sb + FKV + (uint32_t)((s ^ 1) * FKVSTG)
                       + (uint32_t)(r2 * FSTR + q4 * 32);
            cpa16(d + FKH, kh_g + so);        cpa16(d + FKH + 16, kh_g + so + 16);
            cpa16(d + FKL, kl_g + so);        cpa16(d + FKL + 16, kl_g + so + 16);
            cpa16(d + FVH, vh_g + so);        cpa16(d + FVH + 16, vh_g + so + 16);
            cpa16(d + FVL, vl_g + so);        cpa16(d + FVL + 16, vl_g + so + 16);
            asm volatile("cp.async.commit_group;");
        }

        // ---- QK^T ----
        float sc_[8][4];
#pragma unroll
        for (int i = 0; i < 8; i++)
#pragma unroll
            for (int q = 0; q < 4; q++) sc_[i][q] = 0.f;

#pragma unroll
        for (int ks = 0; ks < 4; ks++) {
            uint32_t qa = qBase + (uint32_t)(ks * 32) + aOff;
            uint32_t qh_f[4], ql_f[4];
            ldsm4(qh_f, qa);
            ldsm4(ql_f, qa + FQL);
#pragma unroll
            for (int jj = 0; jj < 4; jj++) {
                uint32_t ka = kvb + (uint32_t)(jj * 16 * FSTR + ks * 32) + bOff;
                uint32_t kh_f[4], kl_f[4];
                ldsm4(kh_f, ka + FKH);
                ldsm4(kl_f, ka + FKL);
                int j0 = jj * 2, j1 = jj * 2 + 1;
                mma16816(sc_[j0], qh_f, kh_f[0], kh_f[1]);
                mma16816(sc_[j1], qh_f, kh_f[2], kh_f[3]);
                mma16816(sc_[j0], qh_f, kl_f[0], kl_f[1]);
                mma16816(sc_[j1], qh_f, kl_f[2], kl_f[3]);
                mma16816(sc_[j0], ql_f, kh_f[0], kh_f[1]);
                mma16816(sc_[j1], ql_f, kh_f[2], kh_f[3]);
            }
        }

        // ---- mask + sigmoid + u = exp(s), stored in-place into sc_ ----
        int j0b = kj * 64;
        float mt0 = -1e30f, mt1 = -1e30f;
#pragma unroll
        for (int tl = 0; tl < 8; tl++) {
            int jg = j0b + tl * 8 + t * 2;
            int2 mk0 = *(const int2*)(mr0 + jg);
            int2 mk1 = *(const int2*)(mr1 + jg);
            float s00 = sc_[tl][0] * INV64;
            float s01 = sc_[tl][1] * INV64;
            float s10 = sc_[tl][2] * INV64;
            float s11 = sc_[tl][3] * INV64;
            if (!((jg     <= ig0) && mk0.x)) s00 = -1e30f;
            if (!((jg + 1 <= ig0) && mk0.y)) s01 = -1e30f;
            if (!((jg     <= ig1) && mk1.x)) s10 = -1e30f;
            if (!((jg + 1 <= ig1) && mk1.y)) s11 = -1e30f;
            float u00 = __expf(s00), u01 = __expf(s01);
            float u10 = __expf(s10), u11 = __expf(s11);
            sc_[tl][0] = u00; sc_[tl][1] = u01;
            sc_[tl][2] = u10; sc_[tl][3] = u11;
            *(float2*)(ar0 + jg) = make_float2(__fdividef(u00, 1.f + u00),
                                               __fdividef(u01, 1.f + u01));
            *(float2*)(ar1 + jg) = make_float2(__fdividef(u10, 1.f + u10),
                                               __fdividef(u11, 1.f + u11));
            mt0 = fmaxf(mt0, fmaxf(s00, s01));
            mt1 = fmaxf(mt1, fmaxf(s10, s11));
        }
        mt0 = fmaxf(mt0, __shfl_xor_sync(0xffffffffu, mt0, 1));
        mt0 = fmaxf(mt0, __shfl_xor_sync(0xffffffffu, mt0, 2));
        mt1 = fmaxf(mt1, __shfl_xor_sync(0xffffffffu, mt1, 1));
        mt1 = fmaxf(mt1, __shfl_xor_sync(0xffffffffu, mt1, 2));

        float mn0 = fmaxf(fmaxf(m0, mt0), -80.f);
        float mn1 = fmaxf(fmaxf(m1, mt1), -80.f);
        float rc0 = __expf(m0 - mn0), rc1 = __expf(m1 - mn1);
        float ce0 = __expf(-mn0), ce1 = __expf(-mn1);

        float su0 = 0.f, su1 = 0.f;
#pragma unroll
        for (int tl = 0; tl < 8; tl++) {
            su0 += sc_[tl][0] + sc_[tl][1];
            su1 += sc_[tl][2] + sc_[tl][3];
        }
        su0 += __shfl_xor_sync(0xffffffffu, su0, 1);
        su0 += __shfl_xor_sync(0xffffffffu, su0, 2);
        su1 += __shfl_xor_sync(0xffffffffu, su1, 1);
        su1 += __shfl_xor_sync(0xffffffffu, su1, 2);

        l0s = l0s * rc0 + su0 * ce0;
        l1s = l1s * rc1 + su1 * ce1;
        m0 = mn0; m1 = mn1;
#pragma unroll
        for (int nt = 0; nt < 8; nt++) {
            oacc[nt][0] *= rc0; oacc[nt][1] *= rc0;
            oacc[nt][2] *= rc1; oacc[nt][3] *= rc1;
        }

        // ---- PV ----
#pragma unroll
        for (int kk = 0; kk < 4; kk++) {
            int ta = 2 * kk, tb = 2 * kk + 1;
            float pa0 = sc_[ta][0] * ce0, pa1 = sc_[ta][1] * ce0;
            float pa2 = sc_[ta][2] * ce1, pa3 = sc_[ta][3] * ce1;
            float pb0 = sc_[tb][0] * ce0, pb1 = sc_[tb][1] * ce0;
            float pb2 = sc_[tb][2] * ce1, pb3 = sc_[tb][3] * ce1;

            __nv_bfloat16 ha0 = __float2bfloat16(pa0), ha1 = __float2bfloat16(pa1);
            __nv_bfloat16 ha2 = __float2bfloat16(pa2), ha3 = __float2bfloat16(pa3);
            __nv_bfloat16 hb0 = __float2bfloat16(pb0), hb1 = __float2bfloat16(pb1);
            __nv_bfloat16 hb2 = __float2bfloat16(pb2), hb3 = __float2bfloat16(pb3);

            uint32_t aPh[4], aPl[4];
            aPh[0] = pack_bf2(ha0, ha1);
            aPh[1] = pack_bf2(ha2, ha3);
            aPh[2] = pack_bf2(hb0, hb1);
            aPh[3] = pack_bf2(hb2, hb3);
            aPl[0] = pack_bf2(__float2bfloat16(pa0 - __bfloat162float(ha0)),
                              __float2bfloat16(pa1 - __bfloat162float(ha1)));
            aPl[1] = pack_bf2(__float2bfloat16(pa2 - __bfloat162float(ha2)),
                              __float2bfloat16(pa3 - __bfloat162float(ha3)));
            aPl[2] = pack_bf2(__float2bfloat16(pb0 - __bfloat162float(hb0)),
                              __float2bfloat16(pb1 - __bfloat162float(hb1)));
            aPl[3] = pack_bf2(__float2bfloat16(pb2 - __bfloat162float(hb2)),
                              __float2bfloat16(pb3 - __bfloat162float(hb3)));

#pragma unroll
            for (int np = 0; np < 4; np++) {
                uint32_t va = kvb + (uint32_t)(kk * 16 * FSTR + np * 32) + aOff;
                uint32_t vh_f[4], vl_f[4];
                ldsm4t(vh_f, va + FVH);
                ldsm4t(vl_f, va + FVL);
                int n0 = np * 2, n1 = np * 2 + 1;
                mma16816(oacc[n0], aPh, vh_f[0], vh_f[1]);
                mma16816(oacc[n1], aPh, vh_f[2], vh_f[3]);
                mma16816(oacc[n0], aPh, vl_f[0], vl_f[1]);
                mma16816(oacc[n1], aPh, vl_f[2], vl_f[3]);
                mma16816(oacc[n0], aPl, vh_f[0], vh_f[1]);
                mma16816(oacc[n1], aPl, vh_f[2], vh_f[3]);
            }
        }
    }

    // ---- epilogue ----
    float i0 = (l0s > 0.f) ? (1.0f / l0s) : 0.f;
    float i1 = (l1s > 0.f) ? (1.0f / l1s) : 0.f;
#pragma unroll
    for (int nt = 0; nt < 8; nt++) {
        int col = h * DH + nt * 8 + t * 2;
        float o00 = oacc[nt][0] * i0, o01 = oacc[nt][1] * i0;
        float o10 = oacc[nt][2] * i1, o11 = oacc[nt][3] * i1;
        __nv_bfloat16 h00 = __float2bfloat16(o00), h01 = __float2bfloat16(o01);
        __nv_bfloat16 h10 = __float2bfloat16(o10), h11 = __float2bfloat16(o11);
        size_t idx0 = ((size_t)b * S_DIM + ig0) * E_DIM + col;
        size_t idx1 = ((size_t)b * S_DIM + ig1) * E_DIM + col;
        *(uint32_t*)(hoh + idx0) = pack_bf2(h00, h01);
        *(uint32_t*)(hoh + idx1) = pack_bf2(h10, h11);
        *(uint32_t*)(hol + idx0) =
            pack_bf2(__float2bfloat16(o00 - __bfloat162float(h00)),
                     __float2bfloat16(o01 - __bfloat162float(h01)));
        *(uint32_t*)(hol + idx1) =
            pack_bf2(__float2bfloat16(o10 - __bfloat162float(h10)),
                     __float2bfloat16(o11 - __bfloat162float(h11)));
    }
}

// ---------------------------------------------------------------------------
extern "C" void kernel_launch(void* const* d_in, const int* in_sizes, int n_in,
                              void* d_out, int out_size)
{
    const float* x       = (const float*)d_in[0];
    const float* w_qkv   = (const float*)d_in[1];
    const float* w_proj  = (const float*)d_in[2];
    const int* mask_head  = (const int*)d_in[3];
    const int* mask_child = (const int*)d_in[4];

    float* out = (float*)d_out;
    float* arc = out + (size_t)B_DIM * S_DIM * E_DIM;

    __nv_bfloat16 *qkvh, *qkvl, *xh, *xl, *wqh, *wql, *wph, *wpl, *hoh, *hol;
    cudaGetSymbolAddress((void**)&qkvh, g_qkvh);
    cudaGetSymbolAddress((void**)&qkvl, g_qkvl);
    cudaGetSymbolAddress((void**)&xh, g_xh);
    cudaGetSymbolAddress((void**)&xl, g_xl);
    cudaGetSymbolAddress((void**)&wqh, g_wqh);
    cudaGetSymbolAddress((void**)&wql, g_wql);
    cudaGetSymbolAddress((void**)&wph, g_wph);
    cudaGetSymbolAddress((void**)&wpl, g_wpl);
    cudaGetSymbolAddress((void**)&hoh, g_hoh);
    cudaGetSymbolAddress((void**)&hol, g_hol);

    const int gemm_smem = 2 * SSTG;
    cudaFuncSetAttribute(gemm_bf,
                         cudaFuncAttributeMaxDynamicSharedMemorySize, gemm_smem);
    cudaFuncSetAttribute(flash_mma,
                         cudaFuncAttributeMaxDynamicSharedMemorySize, FSMEM);

    // 0) pre-split inputs into bf16 hi/lo
    {
        int n4x = (B_DIM * S_DIM * E_DIM) / 4;
        split_kernel<<<(n4x + 255) / 256, 256>>>(x, xh, xl, n4x);
        int n4q = (E3 * E_DIM) / 4;
        split_kernel<<<(n4q + 255) / 256, 256>>>(w_qkv, wqh, wql, n4q);
        int n4p = (E_DIM * E_DIM) / 4;
        split_kernel<<<(n4p + 255) / 256, 256>>>(w_proj, wph, wpl, n4p);
    }

    // 1) qkv = x @ w_qkv^T -> bf16 hi/lo directly
    {
        dim3 grid(E3 / 128, (B_DIM * S_DIM) / 128);
        gemm_bf<<<grid, 256, gemm_smem>>>(xh, xl, wqh, wql,
                                          nullptr, qkvh, qkvl, E3, E_DIM);
    }

    // 2) HMMA flash attention + sigmoid side output + bf16 head-out
    {
        dim3 grid(S_DIM / 128, B_DIM * MH);
        flash_mma<<<grid, 256, FSMEM>>>(qkvh, qkvl, mask_head, mask_child,
                                        arc, hoh, hol);
    }

    // 3) out = headout @ w_proj^T  (fp32 final output)
    {
        dim3 grid(E_DIM / 128, (B_DIM * S_DIM) / 128);
        gemm_bf<<<grid, 256, gemm_smem>>>(hoh, hol, wph, wpl,
                                          out, nullptr, nullptr, E_DIM, E_DIM);
    }
}

// round 13
// speedup vs baseline: 2.6422x; 1.0333x over previous
#include <cuda_runtime.h>
#include <cuda_bf16.h>
#include <cstdint>

#define B_DIM 2
#define S_DIM 1024
#define E_DIM 1024
#define MH    16
#define DH    64
#define E3    3072

// Scratch (no cudaMalloc allowed)
__device__ __nv_bfloat16 g_qkvh[B_DIM * S_DIM * E3];     // qkv hi/lo
__device__ __nv_bfloat16 g_qkvl[B_DIM * S_DIM * E3];
__device__ __nv_bfloat16 g_xh[B_DIM * S_DIM * E_DIM];    // x hi/lo
__device__ __nv_bfloat16 g_xl[B_DIM * S_DIM * E_DIM];
__device__ __nv_bfloat16 g_wqh[E3 * E_DIM];              // w_qkv hi/lo
__device__ __nv_bfloat16 g_wql[E3 * E_DIM];
__device__ __nv_bfloat16 g_wph[E_DIM * E_DIM];           // w_proj hi/lo
__device__ __nv_bfloat16 g_wpl[E_DIM * E_DIM];
__device__ __nv_bfloat16 g_hoh[B_DIM * S_DIM * E_DIM];   // head-out hi/lo
__device__ __nv_bfloat16 g_hol[B_DIM * S_DIM * E_DIM];
__device__ float g_opart[2 * B_DIM * S_DIM * E_DIM];     // split-KV partial O
__device__ float g_pm[2 * 32 * S_DIM];                   // partial row max
__device__ float g_pl[2 * 32 * S_DIM];                   // partial row sum

__device__ __forceinline__ uint32_t smem_u32(const void* p) {
    uint32_t a;
    asm("{ .reg .u64 t; cvta.to.shared.u64 t, %1; cvt.u32.u64 %0, t; }"
        : "=r"(a) : "l"(p));
    return a;
}

__device__ __forceinline__ uint32_t pack_bf2(__nv_bfloat16 lo, __nv_bfloat16 hi) {
    return (uint32_t)__bfloat16_as_ushort(lo) | ((uint32_t)__bfloat16_as_ushort(hi) << 16);
}

__device__ __forceinline__ void mma16816(float* d, const uint32_t* a,
                                         uint32_t b0, uint32_t b1) {
    asm volatile(
        "mma.sync.aligned.m16n8k16.row.col.f32.bf16.bf16.f32 "
        "{%0,%1,%2,%3}, {%4,%5,%6,%7}, {%8,%9}, {%0,%1,%2,%3};"
        : "+f"(d[0]), "+f"(d[1]), "+f"(d[2]), "+f"(d[3])
        : "r"(a[0]), "r"(a[1]), "r"(a[2]), "r"(a[3]), "r"(b0), "r"(b1));
}

__device__ __forceinline__ void ldsm4(uint32_t* d, uint32_t addr) {
    asm volatile("ldmatrix.sync.aligned.m8n8.x4.shared.b16 {%0,%1,%2,%3}, [%4];"
        : "=r"(d[0]), "=r"(d[1]), "=r"(d[2]), "=r"(d[3]) : "r"(addr));
}

__device__ __forceinline__ void ldsm4t(uint32_t* d, uint32_t addr) {
    asm volatile("ldmatrix.sync.aligned.m8n8.x4.trans.shared.b16 {%0,%1,%2,%3}, [%4];"
        : "=r"(d[0]), "=r"(d[1]), "=r"(d[2]), "=r"(d[3]) : "r"(addr));
}

__device__ __forceinline__ void cpa16(uint32_t dst, const void* src) {
    asm volatile("cp.async.cg.shared.global [%0], [%1], 16;"
                 :: "r"(dst), "l"(src));
}

// ---------------------------------------------------------------------------
// Pre-pass: split fp32 -> bf16 hi/lo
// ---------------------------------------------------------------------------
__global__ void split_kernel(const float* __restrict__ in,
                             __nv_bfloat16* __restrict__ hi,
                             __nv_bfloat16* __restrict__ lo, int n4)
{
    int i = blockIdx.x * blockDim.x + threadIdx.x;
    if (i >= n4) return;
    float4 v = *(const float4*)(in + i * 4);
    __nv_bfloat16 h0 = __float2bfloat16(v.x);
    __nv_bfloat16 h1 = __float2bfloat16(v.y);
    __nv_bfloat16 h2 = __float2bfloat16(v.z);
    __nv_bfloat16 h3 = __float2bfloat16(v.w);
    __nv_bfloat16 l0 = __float2bfloat16(v.x - __bfloat162float(h0));
    __nv_bfloat16 l1 = __float2bfloat16(v.y - __bfloat162float(h1));
    __nv_bfloat16 l2 = __float2bfloat16(v.z - __bfloat162float(h2));
    __nv_bfloat16 l3 = __float2bfloat16(v.w - __bfloat162float(h3));
    *(uint2*)(hi + i * 4) = make_uint2(pack_bf2(h0, h1), pack_bf2(h2, h3));
    *(uint2*)(lo + i * 4) = make_uint2(pack_bf2(l0, l1), pack_bf2(l2, l3));
}

// ---------------------------------------------------------------------------
// HMMA GEMM on pre-split bf16 (R12, unchanged)
// ---------------------------------------------------------------------------
#define RSTR  80
#define TSZb  (128 * RSTR)
#define SSTG  (4 * TSZb)

__global__ __launch_bounds__(256, 2) void gemm_bf(
    const __nv_bfloat16* __restrict__ Ah_, const __nv_bfloat16* __restrict__ Al_,
    const __nv_bfloat16* __restrict__ Wh_, const __nv_bfloat16* __restrict__ Wl_,
    float* __restrict__ C,
    __nv_bfloat16* __restrict__ Ch, __nv_bfloat16* __restrict__ Cl,
    int Nn, int Kn)
{
    extern __shared__ char smem[];
    uint32_t sb = smem_u32(smem);

    int tid = threadIdx.x;
    int lane = tid & 31, wid = tid >> 5;
    int wm = wid >> 1, wn = wid & 1;
    int g = lane >> 2, t = lane & 3;
    int row0 = blockIdx.y * 128;
    int col0 = blockIdx.x * 128;

    int qm = lane >> 3, rm = lane & 7;
    uint32_t aOff = (uint32_t)(((qm & 1) * 8 + rm) * RSTR + (qm >> 1) * 16);
    uint32_t bOff = (uint32_t)(((qm >> 1) * 8 + rm) * RSTR + (qm & 1) * 16);

    float acc[2][8][4];
#pragma unroll
    for (int mt = 0; mt < 2; mt++)
#pragma unroll
        for (int j = 0; j < 8; j++)
#pragma unroll
            for (int q = 0; q < 4; q++) acc[mt][j][q] = 0.0f;

    int r = tid >> 1;
    int half = tid & 1;
    const char* srcAh = (const char*)(Ah_ + (size_t)(row0 + r) * Kn) + half * 32;
    const char* srcAl = (const char*)(Al_ + (size_t)(row0 + r) * Kn) + half * 32;
    const char* srcWh = (const char*)(Wh_ + (size_t)(col0 + r) * Kn) + half * 32;
    const char* srcWl = (const char*)(Wl_ + (size_t)(col0 + r) * Kn) + half * 32;
    uint32_t dstOff = (uint32_t)(r * RSTR + half * 32);

    uint32_t aRow0 = (uint32_t)((wm * 32) * RSTR);
    uint32_t bRow0 = (uint32_t)((wn * 64) * RSTR);

    int nChunks = Kn >> 5;

    {
        uint32_t base = sb + dstOff;
        cpa16(base, srcAh);               cpa16(base + 16, srcAh + 16);
        cpa16(base + TSZb, srcAl);        cpa16(base + TSZb + 16, srcAl + 16);
        cpa16(base + 2 * TSZb, srcWh);    cpa16(base + 2 * TSZb + 16, srcWh + 16);
        cpa16(base + 3 * TSZb, srcWl);    cpa16(base + 3 * TSZb + 16, srcWl + 16);
        asm volatile("cp.async.commit_group;");
    }

    for (int c = 0; c < nChunks; c++) {
        int s = c & 1;

        asm volatile("cp.async.wait_group 0;");
        __syncthreads();

        if (c + 1 < nChunks) {
            uint32_t base = sb + (uint32_t)((s ^ 1) * SSTG) + dstOff;
            int cb = (c + 1) * 64;
            cpa16(base, srcAh + cb);              cpa16(base + 16, srcAh + cb + 16);
            cpa16(base + TSZb, srcAl + cb);       cpa16(base + TSZb + 16, srcAl + cb + 16);
            cpa16(base + 2 * TSZb, srcWh + cb);   cpa16(base + 2 * TSZb + 16, srcWh + cb + 16);
            cpa16(base + 3 * TSZb, srcWl + cb);   cpa16(base + 3 * TSZb + 16, srcWl + cb + 16);
            asm volatile("cp.async.commit_group;");
        }

        uint32_t stg = sb + (uint32_t)(s * SSTG);

#pragma unroll
        for (int ks = 0; ks < 2; ks++) {
            uint32_t kb0 = (uint32_t)(ks * 32);

            uint32_t ah[2][4], al[2][4];
            ldsm4(ah[0], stg + aRow0 + kb0 + aOff);
            ldsm4(ah[1], stg + aRow0 + 16 * RSTR + kb0 + aOff);
            ldsm4(al[0], stg + TSZb + aRow0 + kb0 + aOff);
            ldsm4(al[1], stg + TSZb + aRow0 + 16 * RSTR + kb0 + aOff);

            uint32_t bh[4][4], bl[4][4];
#pragma unroll
            for (int jj = 0; jj < 4; jj++) {
                uint32_t bbase = stg + bRow0 + (uint32_t)(jj * 16 * RSTR) + kb0 + bOff;
                ldsm4(bh[jj], bbase + 2 * TSZb);
                ldsm4(bl[jj], bbase + 3 * TSZb);
            }

#pragma unroll
            for (int jj = 0; jj < 4; jj++) {
                int j0 = jj * 2, j1 = jj * 2 + 1;
                mma16816(acc[0][j0], ah[0], bh[jj][0], bh[jj][1]);
                mma16816(acc[1][j0], ah[1], bh[jj][0], bh[jj][1]);
                mma16816(acc[0][j1], ah[0], bh[jj][2], bh[jj][3]);
                mma16816(acc[1][j1], ah[1], bh[jj][2], bh[jj][3]);
            }
#pragma unroll
            for (int jj = 0; jj < 4; jj++) {
                int j0 = jj * 2, j1 = jj * 2 + 1;
                mma16816(acc[0][j0], ah[0], bl[jj][0], bl[jj][1]);
                mma16816(acc[1][j0], ah[1], bl[jj][0], bl[jj][1]);
                mma16816(acc[0][j1], ah[0], bl[jj][2], bl[jj][3]);
                mma16816(acc[1][j1], ah[1], bl[jj][2], bl[jj][3]);
            }
#pragma unroll
            for (int jj = 0; jj < 4; jj++) {
                int j0 = jj * 2, j1 = jj * 2 + 1;
                mma16816(acc[0][j0], al[0], bh[jj][0], bh[jj][1]);
                mma16816(acc[1][j0], al[1], bh[jj][0], bh[jj][1]);
                mma16816(acc[0][j1], al[0], bh[jj][2], bh[jj][3]);
                mma16816(acc[1][j1], al[1], bh[jj][2], bh[jj][3]);
            }
        }
    }

    if (Ch) {
#pragma unroll
        for (int mt = 0; mt < 2; mt++) {
            int rr = row0 + wm * 32 + mt * 16 + g;
#pragma unroll
            for (int j = 0; j < 8; j++) {
                int cc = col0 + wn * 64 + j * 8 + t * 2;
#pragma unroll
                for (int hh = 0; hh < 2; hh++) {
                    float v0 = acc[mt][j][hh * 2 + 0];
                    float v1 = acc[mt][j][hh * 2 + 1];
                    __nv_bfloat16 h0 = __float2bfloat16(v0);
                    __nv_bfloat16 h1 = __float2bfloat16(v1);
                    size_t idx = (size_t)(rr + hh * 8) * Nn + cc;
                    *(uint32_t*)(Ch + idx) = pack_bf2(h0, h1);
                    *(uint32_t*)(Cl + idx) =
                        pack_bf2(__float2bfloat16(v0 - __bfloat162float(h0)),
                                 __float2bfloat16(v1 - __bfloat162float(h1)));
                }
            }
        }
    } else {
#pragma unroll
        for (int mt = 0; mt < 2; mt++) {
            int rr = row0 + wm * 32 + mt * 16 + g;
#pragma unroll
            for (int j = 0; j < 8; j++) {
                int cc = col0 + wn * 64 + j * 8 + t * 2;
                *(float2*)(C + (size_t)rr * Nn + cc) =
                    make_float2(acc[mt][j][0], acc[mt][j][1]);
                *(float2*)(C + (size_t)(rr + 8) * Nn + cc) =
                    make_float2(acc[mt][j][2], acc[mt][j][3]);
            }
        }
    }
}

// ---------------------------------------------------------------------------
// Split-KV HMMA flash attention. Each (q-block, split) CTA processes half the
// causal key range (qb+1 tiles each) and writes partial O (fp32) + m + l.
// ---------------------------------------------------------------------------
#define FSTR   144
#define FQL    18432
#define FKV    36864
#define FKVSTG 36864
#define FKH    0
#define FKL    9216
#define FVH    18432
#define FVL    27648
#define FSMEM  110592

__global__ __launch_bounds__(256, 2) void flash_mma(
    const __nv_bfloat16* __restrict__ qkvh,
    const __nv_bfloat16* __restrict__ qkvl,
    const int* __restrict__ mask_head,
    const int* __restrict__ mask_child,
    float* __restrict__ arc,
    float* __restrict__ opart,
    float* __restrict__ pm,
    float* __restrict__ pl)
{
    extern __shared__ char fsm[];
    uint32_t sb = smem_u32(fsm);

    int tid = threadIdx.x;
    int lane = tid & 31, w = tid >> 5;
    int g = lane >> 2, t = lane & 3;
    int qm = lane >> 3, rm = lane & 7;

    int wrk = blockIdx.x;           // 0..15, heavy q-blocks first
    int split = wrk & 1;
    int qbx = 7 - (wrk >> 1);
    int qi0 = qbx * 128;
    int nT = 2 * qbx + 2;
    int t0 = split ? (qbx + 1) : 0;
    int t1 = split ? nT : (qbx + 1);

    int bhx = blockIdx.y;
    int b = bhx >> 4, h = bhx & 15;

    const int* maskp = ((h < 8) ? mask_head : mask_child) + (size_t)b * S_DIM * S_DIM;
    const __nv_bfloat16* qh_g = qkvh + (size_t)b * S_DIM * E3 + h * DH;
    const __nv_bfloat16* ql_g = qkvl + (size_t)b * S_DIM * E3 + h * DH;
    const char* kh_g = (const char*)(qh_g + E_DIM);
    const char* kl_g = (const char*)(ql_g + E_DIM);
    const char* vh_g = (const char*)(qh_g + 2 * E_DIM);
    const char* vl_g = (const char*)(ql_g + 2 * E_DIM);
    const size_t rowB = (size_t)E3 * 2;

    // Q load
    {
        int r = tid >> 1, hf = tid & 1;
        const char* sh = (const char*)(qh_g + (size_t)(qi0 + r) * E3) + hf * 64;
        const char* sl = (const char*)(ql_g + (size_t)(qi0 + r) * E3) + hf * 64;
        uint32_t d = sb + (uint32_t)(r * FSTR + hf * 64);
#pragma unroll
        for (int i = 0; i < 4; i++) {
            cpa16(d + i * 16, sh + i * 16);
            cpa16(d + FQL + i * 16, sl + i * 16);
        }
        asm volatile("cp.async.commit_group;");
    }

    int r2 = tid >> 2, q4 = tid & 3;

    // first KV tile prefetch
    {
        size_t so = (size_t)(t0 * 64 + r2) * rowB + q4 * 32;
        uint32_t d = sb + FKV + (uint32_t)(r2 * FSTR + q4 * 32);
        cpa16(d + FKH, kh_g + so);        cpa16(d + FKH + 16, kh_g + so + 16);
        cpa16(d + FKL, kl_g + so);        cpa16(d + FKL + 16, kl_g + so + 16);
        cpa16(d + FVH, vh_g + so);        cpa16(d + FVH + 16, vh_g + so + 16);
        cpa16(d + FVL, vl_g + so);        cpa16(d + FVL + 16, vl_g + so + 16);
        asm volatile("cp.async.commit_group;");
    }

    // zero-fill arc above causal diagonal (split 0 only)
    float* arcw = arc + (size_t)bhx * S_DIM * S_DIM;
    if (split == 0) {
        int zr = qi0 + (tid >> 1);
        int zc = (tid & 1) * 32;
        float4 z = make_float4(0.f, 0.f, 0.f, 0.f);
        for (int kj = nT; kj < S_DIM / 64; kj++) {
            float* p = arcw + (size_t)zr * S_DIM + kj * 64 + zc;
#pragma unroll
            for (int i = 0; i < 8; i++) *(float4*)(p + i * 4) = z;
        }
    }

    uint32_t aOff = (uint32_t)(((qm & 1) * 8 + rm) * FSTR + (qm >> 1) * 16);
    uint32_t bOff = (uint32_t)(((qm >> 1) * 8 + rm) * FSTR + (qm & 1) * 16);
    uint32_t qBase = sb + (uint32_t)(w * 16 * FSTR);

    float m0 = -1e30f, m1 = -1e30f, l0s = 0.f, l1s = 0.f;
    float oacc[8][4];
#pragma unroll
    for (int i = 0; i < 8; i++)
#pragma unroll
        for (int q = 0; q < 4; q++) oacc[i][q] = 0.f;

    int ig0 = qi0 + w * 16 + g;
    int ig1 = ig0 + 8;
    const int* mr0 = maskp + (size_t)ig0 * S_DIM;
    const int* mr1 = maskp + (size_t)ig1 * S_DIM;
    float* ar0 = arcw + (size_t)ig0 * S_DIM;
    float* ar1 = arcw + (size_t)ig1 * S_DIM;
    const float INV64 = 1.0f / 64.0f;

    for (int kj = t0; kj < t1; kj++) {
        int li = kj - t0;
        int s = li & 1;
        uint32_t kvb = sb + FKV + (uint32_t)(s * FKVSTG);

        asm volatile("cp.async.wait_group 0;");
        __syncthreads();

        if (kj + 1 < t1) {
            size_t so = (size_t)((kj + 1) * 64 + r2) * rowB + q4 * 32;
            uint32_t d = sb + FKV + (uint32_t)((s ^ 1) * FKVSTG)
                       + (uint32_t)(r2 * FSTR + q4 * 32);
            cpa16(d + FKH, kh_g + so);        cpa16(d + FKH + 16, kh_g + so + 16);
            cpa16(d + FKL, kl_g + so);        cpa16(d + FKL + 16, kl_g + so + 16);
            cpa16(d + FVH, vh_g + so);        cpa16(d + FVH + 16, vh_g + so + 16);
            cpa16(d + FVL, vl_g + so);        cpa16(d + FVL + 16, vl_g + so + 16);
            asm volatile("cp.async.commit_group;");
        }

        // ---- QK^T ----
        float sc_[8][4];
#pragma unroll
        for (int i = 0; i < 8; i++)
#pragma unroll
            for (int q = 0; q < 4; q++) sc_[i][q] = 0.f;

#pragma unroll
        for (int ks = 0; ks < 4; ks++) {
            uint32_t qa = qBase + (uint32_t)(ks * 32) + aOff;
            uint32_t qh_f[4], ql_f[4];
            ldsm4(qh_f, qa);
            ldsm4(ql_f, qa + FQL);
#pragma unroll
            for (int jj = 0; jj < 4; jj++) {
                uint32_t ka = kvb + (uint32_t)(jj * 16 * FSTR + ks * 32) + bOff;
                uint32_t kh_f[4], kl_f[4];
                ldsm4(kh_f, ka + FKH);
                ldsm4(kl_f, ka + FKL);
                int j0 = jj * 2, j1 = jj * 2 + 1;
                mma16816(sc_[j0], qh_f, kh_f[0], kh_f[1]);
                mma16816(sc_[j1], qh_f, kh_f[2], kh_f[3]);
                mma16816(sc_[j0], qh_f, kl_f[0], kl_f[1]);
                mma16816(sc_[j1], qh_f, kl_f[2], kl_f[3]);
                mma16816(sc_[j0], ql_f, kh_f[0], kh_f[1]);
                mma16816(sc_[j1], ql_f, kh_f[2], kh_f[3]);
            }
        }

        // ---- mask + sigmoid + u = exp(s) in-place ----
        int j0b = kj * 64;
        float mt0 = -1e30f, mt1 = -1e30f;
#pragma unroll
        for (int tl = 0; tl < 8; tl++) {
            int jg = j0b + tl * 8 + t * 2;
            int2 mk0 = *(const int2*)(mr0 + jg);
            int2 mk1 = *(const int2*)(mr1 + jg);
            float s00 = sc_[tl][0] * INV64;
            float s01 = sc_[tl][1] * INV64;
            float s10 = sc_[tl][2] * INV64;
            float s11 = sc_[tl][3] * INV64;
            if (!((jg     <= ig0) && mk0.x)) s00 = -1e30f;
            if (!((jg + 1 <= ig0) && mk0.y)) s01 = -1e30f;
            if (!((jg     <= ig1) && mk1.x)) s10 = -1e30f;
            if (!((jg + 1 <= ig1) && mk1.y)) s11 = -1e30f;
            float u00 = __expf(s00), u01 = __expf(s01);
            float u10 = __expf(s10), u11 = __expf(s11);
            sc_[tl][0] = u00; sc_[tl][1] = u01;
            sc_[tl][2] = u10; sc_[tl][3] = u11;
            *(float2*)(ar0 + jg) = make_float2(__fdividef(u00, 1.f + u00),
                                               __fdividef(u01, 1.f + u01));
            *(float2*)(ar1 + jg) = make_float2(__fdividef(u10, 1.f + u10),
                                               __fdividef(u11, 1.f + u11));
            mt0 = fmaxf(mt0, fmaxf(s00, s01));
            mt1 = fmaxf(mt1, fmaxf(s10, s11));
        }
        mt0 = fmaxf(mt0, __shfl_xor_sync(0xffffffffu, mt0, 1));
        mt0 = fmaxf(mt0, __shfl_xor_sync(0xffffffffu, mt0, 2));
        mt1 = fmaxf(mt1, __shfl_xor_sync(0xffffffffu, mt1, 1));
        mt1 = fmaxf(mt1, __shfl_xor_sync(0xffffffffu, mt1, 2));

        float mn0 = fmaxf(fmaxf(m0, mt0), -80.f);
        float mn1 = fmaxf(fmaxf(m1, mt1), -80.f);
        float rc0 = __expf(m0 - mn0), rc1 = __expf(m1 - mn1);
        float ce0 = __expf(-mn0), ce1 = __expf(-mn1);

        float su0 = 0.f, su1 = 0.f;
#pragma unroll
        for (int tl = 0; tl < 8; tl++) {
            su0 += sc_[tl][0] + sc_[tl][1];
            su1 += sc_[tl][2] + sc_[tl][3];
        }
        su0 += __shfl_xor_sync(0xffffffffu, su0, 1);
        su0 += __shfl_xor_sync(0xffffffffu, su0, 2);
        su1 += __shfl_xor_sync(0xffffffffu, su1, 1);
        su1 += __shfl_xor_sync(0xffffffffu, su1, 2);

        l0s = l0s * rc0 + su0 * ce0;
        l1s = l1s * rc1 + su1 * ce1;
        m0 = mn0; m1 = mn1;
#pragma unroll
        for (int nt = 0; nt < 8; nt++) {
            oacc[nt][0] *= rc0; oacc[nt][1] *= rc0;
            oacc[nt][2] *= rc1; oacc[nt][3] *= rc1;
        }

        // ---- PV ----
#pragma unroll
        for (int kk = 0; kk < 4; kk++) {
            int ta = 2 * kk, tb = 2 * kk + 1;
            float pa0 = sc_[ta][0] * ce0, pa1 = sc_[ta][1] * ce0;
            float pa2 = sc_[ta][2] * ce1, pa3 = sc_[ta][3] * ce1;
            float pb0 = sc_[tb][0] * ce0, pb1 = sc_[tb][1] * ce0;
            float pb2 = sc_[tb][2] * ce1, pb3 = sc_[tb][3] * ce1;

            __nv_bfloat16 ha0 = __float2bfloat16(pa0), ha1 = __float2bfloat16(pa1);
            __nv_bfloat16 ha2 = __float2bfloat16(pa2), ha3 = __float2bfloat16(pa3);
            __nv_bfloat16 hb0 = __float2bfloat16(pb0), hb1 = __float2bfloat16(pb1);
            __nv_bfloat16 hb2 = __float2bfloat16(pb2), hb3 = __float2bfloat16(pb3);

            uint32_t aPh[4], aPl[4];
            aPh[0] = pack_bf2(ha0, ha1);
            aPh[1] = pack_bf2(ha2, ha3);
            aPh[2] = pack_bf2(hb0, hb1);
            aPh[3] = pack_bf2(hb2, hb3);
            aPl[0] = pack_bf2(__float2bfloat16(pa0 - __bfloat162float(ha0)),
                              __float2bfloat16(pa1 - __bfloat162float(ha1)));
            aPl[1] = pack_bf2(__float2bfloat16(pa2 - __bfloat162float(ha2)),
                              __float2bfloat16(pa3 - __bfloat162float(ha3)));
            aPl[2] = pack_bf2(__float2bfloat16(pb0 - __bfloat162float(hb0)),
                              __float2bfloat16(pb1 - __bfloat162float(hb1)));
            aPl[3] = pack_bf2(__float2bfloat16(pb2 - __bfloat162float(hb2)),
                              __float2bfloat16(pb3 - __bfloat162float(hb3)));

#pragma unroll
            for (int np = 0; np < 4; np++) {
                uint32_t va = kvb + (uint32_t)(kk * 16 * FSTR + np * 32) + aOff;
                uint32_t vh_f[4], vl_f[4];
                ldsm4t(vh_f, va + FVH);
                ldsm4t(vl_f, va + FVL);
                int n0 = np * 2, n1 = np * 2 + 1;
                mma16816(oacc[n0], aPh, vh_f[0], vh_f[1]);
                mma16816(oacc[n1], aPh, vh_f[2], vh_f[3]);
                mma16816(oacc[n0], aPh, vl_f[0], vl_f[1]);
                mma16816(oacc[n1], aPh, vl_f[2], vl_f[3]);
                mma16816(oacc[n0], aPl, vh_f[0], vh_f[1]);
                mma16816(oacc[n1], aPl, vh_f[2], vl_f[3] * 0 + vh_f[3]);
            }
        }
    }

    // ---- epilogue: store partial O (fp32) + m + l ----
    float* obase = opart + (size_t)(split * B_DIM + b) * S_DIM * E_DIM;
#pragma unroll
    for (int nt = 0; nt < 8; nt++) {
        int col = h * DH + nt * 8 + t * 2;
        *(float2*)(obase + (size_t)ig0 * E_DIM + col) =
            make_float2(oacc[nt][0], oacc[nt][1]);
        *(float2*)(obase + (size_t)ig1 * E_DIM + col) =
            make_float2(oacc[nt][2], oacc[nt][3]);
    }
    if (t == 0) {
        int mi = (split * 32 + bhx) * S_DIM;
        pm[mi + ig0] = m0;  pm[mi + ig1] = m1;
        pl[mi + ig0] = l0s; pl[mi + ig1] = l1s;
    }
}

// ---------------------------------------------------------------------------
// Merge split-KV partials -> bf16 hi/lo head-out
// ---------------------------------------------------------------------------
__global__ void merge_kernel(const float* __restrict__ opart,
                             const float* __restrict__ pm,
                             const float* __restrict__ pl,
                             __nv_bfloat16* __restrict__ hoh,
                             __nv_bfloat16* __restrict__ hol)
{
    int i = blockIdx.x * blockDim.x + threadIdx.x;
    const int n4 = B_DIM * S_DIM * E_DIM / 4;
    if (i >= n4) return;
    int e4 = i * 4;
    int col = e4 & (E_DIM - 1);
    int s   = (e4 >> 10) & (S_DIM - 1);
    int b   = e4 >> 20;
    int h   = col >> 6;
    int mi  = ((b * 16 + h) << 10) + s;

    float m0 = pm[mi], m1 = pm[(32 << 10) + mi];
    float l0 = pl[mi], l1 = pl[(32 << 10) + mi];
    float m = fmaxf(m0, m1);
    float w0 = __expf(m0 - m), w1 = __expf(m1 - m);
    float l = l0 * w0 + l1 * w1;
    float inv = (l > 0.f) ? (1.0f / l) : 0.f;
    float s0 = w0 * inv, s1 = w1 * inv;

    size_t o0i = ((size_t)b * S_DIM + s) * E_DIM + col;
    float4 A = *(const float4*)(opart + o0i);
    float4 Bv = *(const float4*)(opart + (size_t)B_DIM * S_DIM * E_DIM + o0i);

    float o0 = A.x * s0 + Bv.x * s1;
    float o1 = A.y * s0 + Bv.y * s1;
    float o2 = A.z * s0 + Bv.z * s1;
    float o3 = A.w * s0 + Bv.w * s1;

    __nv_bfloat16 h0 = __float2bfloat16(o0);
    __nv_bfloat16 h1 = __float2bfloat16(o1);
    __nv_bfloat16 h2 = __float2bfloat16(o2);
    __nv_bfloat16 h3 = __float2bfloat16(o3);
    *(uint2*)(hoh + e4) = make_uint2(pack_bf2(h0, h1), pack_bf2(h2, h3));
    *(uint2*)(hol + e4) = make_uint2(
        pack_bf2(__float2bfloat16(o0 - __bfloat162float(h0)),
                 __float2bfloat16(o1 - __bfloat162float(h1))),
        pack_bf2(__float2bfloat16(o2 - __bfloat162float(h2)),
                 __float2bfloat16(o3 - __bfloat162float(h3))));
}

// ---------------------------------------------------------------------------
extern "C" void kernel_launch(void* const* d_in, const int* in_sizes, int n_in,
                              void* d_out, int out_size)
{
    const float* x       = (const float*)d_in[0];
    const float* w_qkv   = (const float*)d_in[1];
    const float* w_proj  = (const float*)d_in[2];
    const int* mask_head  = (const int*)d_in[3];
    const int* mask_child = (const int*)d_in[4];

    float* out = (float*)d_out;
    float* arc = out + (size_t)B_DIM * S_DIM * E_DIM;

    __nv_bfloat16 *qkvh, *qkvl, *xh, *xl, *wqh, *wql, *wph, *wpl, *hoh, *hol;
    float *opart, *pmv, *plv;
    cudaGetSymbolAddress((void**)&qkvh, g_qkvh);
    cudaGetSymbolAddress((void**)&qkvl, g_qkvl);
    cudaGetSymbolAddress((void**)&xh, g_xh);
    cudaGetSymbolAddress((void**)&xl, g_xl);
    cudaGetSymbolAddress((void**)&wqh, g_wqh);
    cudaGetSymbolAddress((void**)&wql, g_wql);
    cudaGetSymbolAddress((void**)&wph, g_wph);
    cudaGetSymbolAddress((void**)&wpl, g_wpl);
    cudaGetSymbolAddress((void**)&hoh, g_hoh);
    cudaGetSymbolAddress((void**)&hol, g_hol);
    cudaGetSymbolAddress((void**)&opart, g_opart);
    cudaGetSymbolAddress((void**)&pmv, g_pm);
    cudaGetSymbolAddress((void**)&plv, g_pl);

    const int gemm_smem = 2 * SSTG;
    cudaFuncSetAttribute(gemm_bf,
                         cudaFuncAttributeMaxDynamicSharedMemorySize, gemm_smem);
    cudaFuncSetAttribute(flash_mma,
                         cudaFuncAttributeMaxDynamicSharedMemorySize, FSMEM);

    // 0) pre-split inputs into bf16 hi/lo
    {
        int n4x = (B_DIM * S_DIM * E_DIM) / 4;
        split_kernel<<<(n4x + 255) / 256, 256>>>(x, xh, xl, n4x);
        int n4q = (E3 * E_DIM) / 4;
        split_kernel<<<(n4q + 255) / 256, 256>>>(w_qkv, wqh, wql, n4q);
        int n4p = (E_DIM * E_DIM) / 4;
        split_kernel<<<(n4p + 255) / 256, 256>>>(w_proj, wph, wpl, n4p);
    }

    // 1) qkv = x @ w_qkv^T -> bf16 hi/lo directly
    {
        dim3 grid(E3 / 128, (B_DIM * S_DIM) / 128);
        gemm_bf<<<grid, 256, gemm_smem>>>(xh, xl, wqh, wql,
                                          nullptr, qkvh, qkvl, E3, E_DIM);
    }

    // 2) split-KV HMMA flash attention
    {
        dim3 grid(16, B_DIM * MH);
        flash_mma<<<grid, 256, FSMEM>>>(qkvh, qkvl, mask_head, mask_child,
                                        arc, opart, pmv, plv);
    }

    // 2b) merge partials -> bf16 hi/lo head-out
    {
        int n4 = (B_DIM * S_DIM * E_DIM) / 4;
        merge_kernel<<<(n4 + 255) / 256, 256>>>(opart, pmv, plv, hoh, hol);
    }

    // 3) out = headout @ w_proj^T  (fp32 final output)
    {
        dim3 grid(E_DIM / 128, (B_DIM * S_DIM) / 128);
        gemm_bf<<<grid, 256, gemm_smem>>>(hoh, hol, wph, wpl,
                                          out, nullptr, nullptr, E_DIM, E_DIM);
    }
}

// round 14
// speedup vs baseline: 2.8397x; 1.0747x over previous
#include <cuda_runtime.h>
#include <cuda_fp16.h>
#include <cstdint>

#define B_DIM 2
#define S_DIM 1024
#define E_DIM 1024
#define MH    16
#define DH    64
#define E3    3072

// Scratch (no cudaMalloc allowed) — all splits now fp16 (11 mantissa bits)
__device__ __half g_qkvh[B_DIM * S_DIM * E3];
__device__ __half g_qkvl[B_DIM * S_DIM * E3];
__device__ __half g_xh[B_DIM * S_DIM * E_DIM];
__device__ __half g_xl[B_DIM * S_DIM * E_DIM];
__device__ __half g_wqh[E3 * E_DIM];
__device__ __half g_wql[E3 * E_DIM];
__device__ __half g_wph[E_DIM * E_DIM];
__device__ __half g_wpl[E_DIM * E_DIM];
__device__ __half g_hoh[B_DIM * S_DIM * E_DIM];
__device__ __half g_hol[B_DIM * S_DIM * E_DIM];
__device__ float g_opart[2 * B_DIM * S_DIM * E_DIM];
__device__ float g_pm[2 * 32 * S_DIM];
__device__ float g_pl[2 * 32 * S_DIM];

__device__ __forceinline__ uint32_t smem_u32(const void* p) {
    uint32_t a;
    asm("{ .reg .u64 t; cvta.to.shared.u64 t, %1; cvt.u32.u64 %0, t; }"
        : "=r"(a) : "l"(p));
    return a;
}

__device__ __forceinline__ uint32_t h2_bits(__half2 h) {
    return *reinterpret_cast<uint32_t*>(&h);
}

// split two floats -> packed fp16 hi + packed fp16 lo
__device__ __forceinline__ void split2(float a, float b,
                                       uint32_t& hi, uint32_t& lo) {
    __half2 h = __float22half2_rn(make_float2(a, b));
    float2 hf = __half22float2(h);
    __half2 l = __float22half2_rn(make_float2(a - hf.x, b - hf.y));
    hi = h2_bits(h);
    lo = h2_bits(l);
}

__device__ __forceinline__ void mma16816(float* d, const uint32_t* a,
                                         uint32_t b0, uint32_t b1) {
    asm volatile(
        "mma.sync.aligned.m16n8k16.row.col.f32.f16.f16.f32 "
        "{%0,%1,%2,%3}, {%4,%5,%6,%7}, {%8,%9}, {%0,%1,%2,%3};"
        : "+f"(d[0]), "+f"(d[1]), "+f"(d[2]), "+f"(d[3])
        : "r"(a[0]), "r"(a[1]), "r"(a[2]), "r"(a[3]), "r"(b0), "r"(b1));
}

__device__ __forceinline__ void ldsm4(uint32_t* d, uint32_t addr) {
    asm volatile("ldmatrix.sync.aligned.m8n8.x4.shared.b16 {%0,%1,%2,%3}, [%4];"
        : "=r"(d[0]), "=r"(d[1]), "=r"(d[2]), "=r"(d[3]) : "r"(addr));
}

__device__ __forceinline__ void ldsm4t(uint32_t* d, uint32_t addr) {
    asm volatile("ldmatrix.sync.aligned.m8n8.x4.trans.shared.b16 {%0,%1,%2,%3}, [%4];"
        : "=r"(d[0]), "=r"(d[1]), "=r"(d[2]), "=r"(d[3]) : "r"(addr));
}

__device__ __forceinline__ void cpa16(uint32_t dst, const void* src) {
    asm volatile("cp.async.cg.shared.global [%0], [%1], 16;"
                 :: "r"(dst), "l"(src));
}

// ---------------------------------------------------------------------------
// Pre-pass: split fp32 -> fp16 hi/lo
// ---------------------------------------------------------------------------
__global__ void split_kernel(const float* __restrict__ in,
                             __half* __restrict__ hi,
                             __half* __restrict__ lo, int n4)
{
    int i = blockIdx.x * blockDim.x + threadIdx.x;
    if (i >= n4) return;
    float4 v = *(const float4*)(in + i * 4);
    uint32_t h0, l0, h1, l1;
    split2(v.x, v.y, h0, l0);
    split2(v.z, v.w, h1, l1);
    *(uint2*)(hi + i * 4) = make_uint2(h0, h1);
    *(uint2*)(lo + i * 4) = make_uint2(l0, l1);
}

// ---------------------------------------------------------------------------
// HMMA GEMM on pre-split fp16 (3-product). Single-sync 2-stage pipeline.
// If Ch != nullptr, writes fp16 hi/lo output; else fp32 to C.
// ---------------------------------------------------------------------------
#define RSTR  80
#define TSZb  (128 * RSTR)
#define SSTG  (4 * TSZb)

__global__ __launch_bounds__(256, 2) void gemm_bf(
    const __half* __restrict__ Ah_, const __half* __restrict__ Al_,
    const __half* __restrict__ Wh_, const __half* __restrict__ Wl_,
    float* __restrict__ C,
    __half* __restrict__ Ch, __half* __restrict__ Cl,
    int Nn, int Kn)
{
    extern __shared__ char smem[];
    uint32_t sb = smem_u32(smem);

    int tid = threadIdx.x;
    int lane = tid & 31, wid = tid >> 5;
    int wm = wid >> 1, wn = wid & 1;
    int g = lane >> 2, t = lane & 3;
    int row0 = blockIdx.y * 128;
    int col0 = blockIdx.x * 128;

    int qm = lane >> 3, rm = lane & 7;
    uint32_t aOff = (uint32_t)(((qm & 1) * 8 + rm) * RSTR + (qm >> 1) * 16);
    uint32_t bOff = (uint32_t)(((qm >> 1) * 8 + rm) * RSTR + (qm & 1) * 16);

    float acc[2][8][4];
#pragma unroll
    for (int mt = 0; mt < 2; mt++)
#pragma unroll
        for (int j = 0; j < 8; j++)
#pragma unroll
            for (int q = 0; q < 4; q++) acc[mt][j][q] = 0.0f;

    int r = tid >> 1;
    int half_ = tid & 1;
    const char* srcAh = (const char*)(Ah_ + (size_t)(row0 + r) * Kn) + half_ * 32;
    const char* srcAl = (const char*)(Al_ + (size_t)(row0 + r) * Kn) + half_ * 32;
    const char* srcWh = (const char*)(Wh_ + (size_t)(col0 + r) * Kn) + half_ * 32;
    const char* srcWl = (const char*)(Wl_ + (size_t)(col0 + r) * Kn) + half_ * 32;
    uint32_t dstOff = (uint32_t)(r * RSTR + half_ * 32);

    uint32_t aRow0 = (uint32_t)((wm * 32) * RSTR);
    uint32_t bRow0 = (uint32_t)((wn * 64) * RSTR);

    int nChunks = Kn >> 5;

    {
        uint32_t base = sb + dstOff;
        cpa16(base, srcAh);               cpa16(base + 16, srcAh + 16);
        cpa16(base + TSZb, srcAl);        cpa16(base + TSZb + 16, srcAl + 16);
        cpa16(base + 2 * TSZb, srcWh);    cpa16(base + 2 * TSZb + 16, srcWh + 16);
        cpa16(base + 3 * TSZb, srcWl);    cpa16(base + 3 * TSZb + 16, srcWl + 16);
        asm volatile("cp.async.commit_group;");
    }

    for (int c = 0; c < nChunks; c++) {
        int s = c & 1;

        asm volatile("cp.async.wait_group 0;");
        __syncthreads();

        if (c + 1 < nChunks) {
            uint32_t base = sb + (uint32_t)((s ^ 1) * SSTG) + dstOff;
            int cb = (c + 1) * 64;
            cpa16(base, srcAh + cb);              cpa16(base + 16, srcAh + cb + 16);
            cpa16(base + TSZb, srcAl + cb);       cpa16(base + TSZb + 16, srcAl + cb + 16);
            cpa16(base + 2 * TSZb, srcWh + cb);   cpa16(base + 2 * TSZb + 16, srcWh + cb + 16);
            cpa16(base + 3 * TSZb, srcWl + cb);   cpa16(base + 3 * TSZb + 16, srcWl + cb + 16);
            asm volatile("cp.async.commit_group;");
        }

        uint32_t stg = sb + (uint32_t)(s * SSTG);

#pragma unroll
        for (int ks = 0; ks < 2; ks++) {
            uint32_t kb0 = (uint32_t)(ks * 32);

            uint32_t ah[2][4], al[2][4];
            ldsm4(ah[0], stg + aRow0 + kb0 + aOff);
            ldsm4(ah[1], stg + aRow0 + 16 * RSTR + kb0 + aOff);
            ldsm4(al[0], stg + TSZb + aRow0 + kb0 + aOff);
            ldsm4(al[1], stg + TSZb + aRow0 + 16 * RSTR + kb0 + aOff);

            uint32_t bh[4][4], bl[4][4];
#pragma unroll
            for (int jj = 0; jj < 4; jj++) {
                uint32_t bbase = stg + bRow0 + (uint32_t)(jj * 16 * RSTR) + kb0 + bOff;
                ldsm4(bh[jj], bbase + 2 * TSZb);
                ldsm4(bl[jj], bbase + 3 * TSZb);
            }

#pragma unroll
            for (int jj = 0; jj < 4; jj++) {
                int j0 = jj * 2, j1 = jj * 2 + 1;
                mma16816(acc[0][j0], ah[0], bh[jj][0], bh[jj][1]);
                mma16816(acc[1][j0], ah[1], bh[jj][0], bh[jj][1]);
                mma16816(acc[0][j1], ah[0], bh[jj][2], bh[jj][3]);
                mma16816(acc[1][j1], ah[1], bh[jj][2], bh[jj][3]);
            }
#pragma unroll
            for (int jj = 0; jj < 4; jj++) {
                int j0 = jj * 2, j1 = jj * 2 + 1;
                mma16816(acc[0][j0], ah[0], bl[jj][0], bl[jj][1]);
                mma16816(acc[1][j0], ah[1], bl[jj][0], bl[jj][1]);
                mma16816(acc[0][j1], ah[0], bl[jj][2], bl[jj][3]);
                mma16816(acc[1][j1], ah[1], bl[jj][2], bl[jj][3]);
            }
#pragma unroll
            for (int jj = 0; jj < 4; jj++) {
                int j0 = jj * 2, j1 = jj * 2 + 1;
                mma16816(acc[0][j0], al[0], bh[jj][0], bh[jj][1]);
                mma16816(acc[1][j0], al[1], bh[jj][0], bh[jj][1]);
                mma16816(acc[0][j1], al[0], bh[jj][2], bh[jj][3]);
                mma16816(acc[1][j1], al[1], bh[jj][2], bh[jj][3]);
            }
        }
    }

    if (Ch) {
#pragma unroll
        for (int mt = 0; mt < 2; mt++) {
            int rr = row0 + wm * 32 + mt * 16 + g;
#pragma unroll
            for (int j = 0; j < 8; j++) {
                int cc = col0 + wn * 64 + j * 8 + t * 2;
#pragma unroll
                for (int hh = 0; hh < 2; hh++) {
                    uint32_t hb, lb;
                    split2(acc[mt][j][hh * 2 + 0], acc[mt][j][hh * 2 + 1], hb, lb);
                    size_t idx = (size_t)(rr + hh * 8) * Nn + cc;
                    *(uint32_t*)(Ch + idx) = hb;
                    *(uint32_t*)(Cl + idx) = lb;
                }
            }
        }
    } else {
#pragma unroll
        for (int mt = 0; mt < 2; mt++) {
            int rr = row0 + wm * 32 + mt * 16 + g;
#pragma unroll
            for (int j = 0; j < 8; j++) {
                int cc = col0 + wn * 64 + j * 8 + t * 2;
                *(float2*)(C + (size_t)rr * Nn + cc) =
                    make_float2(acc[mt][j][0], acc[mt][j][1]);
                *(float2*)(C + (size_t)(rr + 8) * Nn + cc) =
                    make_float2(acc[mt][j][2], acc[mt][j][3]);
            }
        }
    }
}

// ---------------------------------------------------------------------------
// Split-KV HMMA flash attention, fp16.
// QK^T: 3-product fp16 split (error ~2^-22). PV: single fp16 product.
// ---------------------------------------------------------------------------
#define FSTR   144
#define FQL    18432
#define FKV    36864
#define FKVSTG 27648
#define FKH    0
#define FKL    9216
#define FVH    18432
#define FSMEM  (36864 + 2 * 27648)   /* 92160 */

__global__ __launch_bounds__(256, 2) void flash_mma(
    const __half* __restrict__ qkvh,
    const __half* __restrict__ qkvl,
    const int* __restrict__ mask_head,
    const int* __restrict__ mask_child,
    float* __restrict__ arc,
    float* __restrict__ opart,
    float* __restrict__ pm,
    float* __restrict__ pl)
{
    extern __shared__ char fsm[];
    uint32_t sb = smem_u32(fsm);

    int tid = threadIdx.x;
    int lane = tid & 31, w = tid >> 5;
    int g = lane >> 2, t = lane & 3;
    int qm = lane >> 3, rm = lane & 7;

    int wrk = blockIdx.x;           // 0..15, heavy q-blocks first
    int split = wrk & 1;
    int qbx = 7 - (wrk >> 1);
    int qi0 = qbx * 128;
    int nT = 2 * qbx + 2;
    int t0 = split ? (qbx + 1) : 0;
    int t1 = split ? nT : (qbx + 1);

    int bhx = blockIdx.y;
    int b = bhx >> 4, h = bhx & 15;

    const int* maskp = ((h < 8) ? mask_head : mask_child) + (size_t)b * S_DIM * S_DIM;
    const __half* qh_g = qkvh + (size_t)b * S_DIM * E3 + h * DH;
    const __half* ql_g = qkvl + (size_t)b * S_DIM * E3 + h * DH;
    const char* kh_g = (const char*)(qh_g + E_DIM);
    const char* kl_g = (const char*)(ql_g + E_DIM);
    const char* vh_g = (const char*)(qh_g + 2 * E_DIM);
    const size_t rowB = (size_t)E3 * 2;

    // Q load (hi + lo)
    {
        int r = tid >> 1, hf = tid & 1;
        const char* sh = (const char*)(qh_g + (size_t)(qi0 + r) * E3) + hf * 64;
        const char* sl = (const char*)(ql_g + (size_t)(qi0 + r) * E3) + hf * 64;
        uint32_t d = sb + (uint32_t)(r * FSTR + hf * 64);
#pragma unroll
        for (int i = 0; i < 4; i++) {
            cpa16(d + i * 16, sh + i * 16);
            cpa16(d + FQL + i * 16, sl + i * 16);
        }
        asm volatile("cp.async.commit_group;");
    }

    int r2 = tid >> 2, q4 = tid & 3;

    // first KV tile prefetch: Kh, Kl, Vh (no Vl)
    {
        size_t so = (size_t)(t0 * 64 + r2) * rowB + q4 * 32;
        uint32_t d = sb + FKV + (uint32_t)(r2 * FSTR + q4 * 32);
        cpa16(d + FKH, kh_g + so);        cpa16(d + FKH + 16, kh_g + so + 16);
        cpa16(d + FKL, kl_g + so);        cpa16(d + FKL + 16, kl_g + so + 16);
        cpa16(d + FVH, vh_g + so);        cpa16(d + FVH + 16, vh_g + so + 16);
        asm volatile("cp.async.commit_group;");
    }

    // zero-fill arc above causal diagonal (split 0 only)
    float* arcw = arc + (size_t)bhx * S_DIM * S_DIM;
    if (split == 0) {
        int zr = qi0 + (tid >> 1);
        int zc = (tid & 1) * 32;
        float4 z = make_float4(0.f, 0.f, 0.f, 0.f);
        for (int kj = nT; kj < S_DIM / 64; kj++) {
            float* p = arcw + (size_t)zr * S_DIM + kj * 64 + zc;
#pragma unroll
            for (int i = 0; i < 8; i++) *(float4*)(p + i * 4) = z;
        }
    }

    uint32_t aOff = (uint32_t)(((qm & 1) * 8 + rm) * FSTR + (qm >> 1) * 16);
    uint32_t bOff = (uint32_t)(((qm >> 1) * 8 + rm) * FSTR + (qm & 1) * 16);
    uint32_t qBase = sb + (uint32_t)(w * 16 * FSTR);

    float m0 = -1e30f, m1 = -1e30f, l0s = 0.f, l1s = 0.f;
    float oacc[8][4];
#pragma unroll
    for (int i = 0; i < 8; i++)
#pragma unroll
        for (int q = 0; q < 4; q++) oacc[i][q] = 0.f;

    int ig0 = qi0 + w * 16 + g;
    int ig1 = ig0 + 8;
    const int* mr0 = maskp + (size_t)ig0 * S_DIM;
    const int* mr1 = maskp + (size_t)ig1 * S_DIM;
    float* ar0 = arcw + (size_t)ig0 * S_DIM;
    float* ar1 = arcw + (size_t)ig1 * S_DIM;
    const float INV64 = 1.0f / 64.0f;

    for (int kj = t0; kj < t1; kj++) {
        int li = kj - t0;
        int s = li & 1;
        uint32_t kvb = sb + FKV + (uint32_t)(s * FKVSTG);

        asm volatile("cp.async.wait_group 0;");
        __syncthreads();

        if (kj + 1 < t1) {
            size_t so = (size_t)((kj + 1) * 64 + r2) * rowB + q4 * 32;
            uint32_t d = sb + FKV + (uint32_t)((s ^ 1) * FKVSTG)
                       + (uint32_t)(r2 * FSTR + q4 * 32);
            cpa16(d + FKH, kh_g + so);        cpa16(d + FKH + 16, kh_g + so + 16);
            cpa16(d + FKL, kl_g + so);        cpa16(d + FKL + 16, kl_g + so + 16);
            cpa16(d + FVH, vh_g + so);        cpa16(d + FVH + 16, vh_g + so + 16);
            asm volatile("cp.async.commit_group;");
        }

        // ---- QK^T: 3-product fp16 ----
        float sc_[8][4];
#pragma unroll
        for (int i = 0; i < 8; i++)
#pragma unroll
            for (int q = 0; q < 4; q++) sc_[i][q] = 0.f;

#pragma unroll
        for (int ks = 0; ks < 4; ks++) {
            uint32_t qa = qBase + (uint32_t)(ks * 32) + aOff;
            uint32_t qh_f[4], ql_f[4];
            ldsm4(qh_f, qa);
            ldsm4(ql_f, qa + FQL);
#pragma unroll
            for (int jj = 0; jj < 4; jj++) {
                uint32_t ka = kvb + (uint32_t)(jj * 16 * FSTR + ks * 32) + bOff;
                uint32_t kh_f[4], kl_f[4];
                ldsm4(kh_f, ka + FKH);
                ldsm4(kl_f, ka + FKL);
                int j0 = jj * 2, j1 = jj * 2 + 1;
                mma16816(sc_[j0], qh_f, kh_f[0], kh_f[1]);
                mma16816(sc_[j1], qh_f, kh_f[2], kh_f[3]);
                mma16816(sc_[j0], qh_f, kl_f[0], kl_f[1]);
                mma16816(sc_[j1], qh_f, kl_f[2], kl_f[3]);
                mma16816(sc_[j0], ql_f, kh_f[0], kh_f[1]);
                mma16816(sc_[j1], ql_f, kh_f[2], kh_f[3]);
            }
        }

        // ---- mask + sigmoid + u = exp(s) in-place ----
        int j0b = kj * 64;
        float mt0 = -1e30f, mt1 = -1e30f;
#pragma unroll
        for (int tl = 0; tl < 8; tl++) {
            int jg = j0b + tl * 8 + t * 2;
            int2 mk0 = *(const int2*)(mr0 + jg);
            int2 mk1 = *(const int2*)(mr1 + jg);
            float s00 = sc_[tl][0] * INV64;
            float s01 = sc_[tl][1] * INV64;
            float s10 = sc_[tl][2] * INV64;
            float s11 = sc_[tl][3] * INV64;
            if (!((jg     <= ig0) && mk0.x)) s00 = -1e30f;
            if (!((jg + 1 <= ig0) && mk0.y)) s01 = -1e30f;
            if (!((jg     <= ig1) && mk1.x)) s10 = -1e30f;
            if (!((jg + 1 <= ig1) && mk1.y)) s11 = -1e30f;
            float u00 = __expf(s00), u01 = __expf(s01);
            float u10 = __expf(s10), u11 = __expf(s11);
            sc_[tl][0] = u00; sc_[tl][1] = u01;
            sc_[tl][2] = u10; sc_[tl][3] = u11;
            *(float2*)(ar0 + jg) = make_float2(__fdividef(u00, 1.f + u00),
                                               __fdividef(u01, 1.f + u01));
            *(float2*)(ar1 + jg) = make_float2(__fdividef(u10, 1.f + u10),
                                               __fdividef(u11, 1.f + u11));
            mt0 = fmaxf(mt0, fmaxf(s00, s01));
            mt1 = fmaxf(mt1, fmaxf(s10, s11));
        }
        mt0 = fmaxf(mt0, __shfl_xor_sync(0xffffffffu, mt0, 1));
        mt0 = fmaxf(mt0, __shfl_xor_sync(0xffffffffu, mt0, 2));
        mt1 = fmaxf(mt1, __shfl_xor_sync(0xffffffffu, mt1, 1));
        mt1 = fmaxf(mt1, __shfl_xor_sync(0xffffffffu, mt1, 2));

        float mn0 = fmaxf(fmaxf(m0, mt0), -80.f);
        float mn1 = fmaxf(fmaxf(m1, mt1), -80.f);
        float rc0 = __expf(m0 - mn0), rc1 = __expf(m1 - mn1);
        float ce0 = __expf(-mn0), ce1 = __expf(-mn1);

        float su0 = 0.f, su1 = 0.f;
#pragma unroll
        for (int tl = 0; tl < 8; tl++) {
            su0 += sc_[tl][0] + sc_[tl][1];
            su1 += sc_[tl][2] + sc_[tl][3];
        }
        su0 += __shfl_xor_sync(0xffffffffu, su0, 1);
        su0 += __shfl_xor_sync(0xffffffffu, su0, 2);
        su1 += __shfl_xor_sync(0xffffffffu, su1, 1);
        su1 += __shfl_xor_sync(0xffffffffu, su1, 2);

        l0s = l0s * rc0 + su0 * ce0;
        l1s = l1s * rc1 + su1 * ce1;
        m0 = mn0; m1 = mn1;
#pragma unroll
        for (int nt = 0; nt < 8; nt++) {
            oacc[nt][0] *= rc0; oacc[nt][1] *= rc0;
            oacc[nt][2] *= rc1; oacc[nt][3] *= rc1;
        }

        // ---- PV: single fp16 product ----
#pragma unroll
        for (int kk = 0; kk < 4; kk++) {
            int ta = 2 * kk, tb = 2 * kk + 1;
            uint32_t aP[4];
            aP[0] = h2_bits(__float22half2_rn(
                        make_float2(sc_[ta][0] * ce0, sc_[ta][1] * ce0)));
            aP[1] = h2_bits(__float22half2_rn(
                        make_float2(sc_[ta][2] * ce1, sc_[ta][3] * ce1)));
            aP[2] = h2_bits(__float22half2_rn(
                        make_float2(sc_[tb][0] * ce0, sc_[tb][1] * ce0)));
            aP[3] = h2_bits(__float22half2_rn(
                        make_float2(sc_[tb][2] * ce1, sc_[tb][3] * ce1)));

#pragma unroll
            for (int np = 0; np < 4; np++) {
                uint32_t va = kvb + (uint32_t)(kk * 16 * FSTR + np * 32) + aOff;
                uint32_t vh_f[4];
                ldsm4t(vh_f, va + FVH);
                int n0 = np * 2, n1 = np * 2 + 1;
                mma16816(oacc[n0], aP, vh_f[0], vh_f[1]);
                mma16816(oacc[n1], aP, vh_f[2], vh_f[3]);
            }
        }
    }

    // ---- epilogue: store partial O (fp32) + m + l ----
    float* obase = opart + (size_t)(split * B_DIM + b) * S_DIM * E_DIM;
#pragma unroll
    for (int nt = 0; nt < 8; nt++) {
        int col = h * DH + nt * 8 + t * 2;
        *(float2*)(obase + (size_t)ig0 * E_DIM + col) =
            make_float2(oacc[nt][0], oacc[nt][1]);
        *(float2*)(obase + (size_t)ig1 * E_DIM + col) =
            make_float2(oacc[nt][2], oacc[nt][3]);
    }
    if (t == 0) {
        int mi = (split * 32 + bhx) * S_DIM;
        pm[mi + ig0] = m0;  pm[mi + ig1] = m1;
        pl[mi + ig0] = l0s; pl[mi + ig1] = l1s;
    }
}

// ---------------------------------------------------------------------------
// Merge split-KV partials -> fp16 hi/lo head-out
// ---------------------------------------------------------------------------
__global__ void merge_kernel(const float* __restrict__ opart,
                             const float* __restrict__ pm,
                             const float* __restrict__ pl,
                             __half* __restrict__ hoh,
                             __half* __restrict__ hol)
{
    int i = blockIdx.x * blockDim.x + threadIdx.x;
    const int n4 = B_DIM * S_DIM * E_DIM / 4;
    if (i >= n4) return;
    int e4 = i * 4;
    int col = e4 & (E_DIM - 1);
    int s   = (e4 >> 10) & (S_DIM - 1);
    int b   = e4 >> 20;
    int h   = col >> 6;
    int mi  = ((b * 16 + h) << 10) + s;

    float m0 = pm[mi], m1 = pm[(32 << 10) + mi];
    float l0 = pl[mi], l1 = pl[(32 << 10) + mi];
    float m = fmaxf(m0, m1);
    float w0 = __expf(m0 - m), w1 = __expf(m1 - m);
    float l = l0 * w0 + l1 * w1;
    float inv = (l > 0.f) ? (1.0f / l) : 0.f;
    float s0 = w0 * inv, s1 = w1 * inv;

    size_t o0i = ((size_t)b * S_DIM + s) * E_DIM + col;
    float4 A = *(const float4*)(opart + o0i);
    float4 Bv = *(const float4*)(opart + (size_t)B_DIM * S_DIM * E_DIM + o0i);

    float o0 = A.x * s0 + Bv.x * s1;
    float o1 = A.y * s0 + Bv.y * s1;
    float o2 = A.z * s0 + Bv.z * s1;
    float o3 = A.w * s0 + Bv.w * s1;

    uint32_t h0, l0b, h1, l1b;
    split2(o0, o1, h0, l0b);
    split2(o2, o3, h1, l1b);
    *(uint2*)(hoh + e4) = make_uint2(h0, h1);
    *(uint2*)(hol + e4) = make_uint2(l0b, l1b);
}

// ---------------------------------------------------------------------------
extern "C" void kernel_launch(void* const* d_in, const int* in_sizes, int n_in,
                              void* d_out, int out_size)
{
    const float* x       = (const float*)d_in[0];
    const float* w_qkv   = (const float*)d_in[1];
    const float* w_proj  = (const float*)d_in[2];
    const int* mask_head  = (const int*)d_in[3];
    const int* mask_child = (const int*)d_in[4];

    float* out = (float*)d_out;
    float* arc = out + (size_t)B_DIM * S_DIM * E_DIM;

    __half *qkvh, *qkvl, *xh, *xl, *wqh, *wql, *wph, *wpl, *hoh, *hol;
    float *opart, *pmv, *plv;
    cudaGetSymbolAddress((void**)&qkvh, g_qkvh);
    cudaGetSymbolAddress((void**)&qkvl, g_qkvl);
    cudaGetSymbolAddress((void**)&xh, g_xh);
    cudaGetSymbolAddress((void**)&xl, g_xl);
    cudaGetSymbolAddress((void**)&wqh, g_wqh);
    cudaGetSymbolAddress((void**)&wql, g_wql);
    cudaGetSymbolAddress((void**)&wph, g_wph);
    cudaGetSymbolAddress((void**)&wpl, g_wpl);
    cudaGetSymbolAddress((void**)&hoh, g_hoh);
    cudaGetSymbolAddress((void**)&hol, g_hol);
    cudaGetSymbolAddress((void**)&opart, g_opart);
    cudaGetSymbolAddress((void**)&pmv, g_pm);
    cudaGetSymbolAddress((void**)&plv, g_pl);

    const int gemm_smem = 2 * SSTG;
    cudaFuncSetAttribute(gemm_bf,
                         cudaFuncAttributeMaxDynamicSharedMemorySize, gemm_smem);
    cudaFuncSetAttribute(flash_mma,
                         cudaFuncAttributeMaxDynamicSharedMemorySize, FSMEM);

    // 0) pre-split inputs into fp16 hi/lo
    {
        int n4x = (B_DIM * S_DIM * E_DIM) / 4;
        split_kernel<<<(n4x + 255) / 256, 256>>>(x, xh, xl, n4x);
        int n4q = (E3 * E_DIM) / 4;
        split_kernel<<<(n4q + 255) / 256, 256>>>(w_qkv, wqh, wql, n4q);
        int n4p = (E_DIM * E_DIM) / 4;
        split_kernel<<<(n4p + 255) / 256, 256>>>(w_proj, wph, wpl, n4p);
    }

    // 1) qkv = x @ w_qkv^T -> fp16 hi/lo directly
    {
        dim3 grid(E3 / 128, (B_DIM * S_DIM) / 128);
        gemm_bf<<<grid, 256, gemm_smem>>>(xh, xl, wqh, wql,
                                          nullptr, qkvh, qkvl, E3, E_DIM);
    }

    // 2) split-KV fp16 flash attention
    {
        dim3 grid(16, B_DIM * MH);
        flash_mma<<<grid, 256, FSMEM>>>(qkvh, qkvl, mask_head, mask_child,
                                        arc, opart, pmv, plv);
    }

    // 2b) merge partials -> fp16 hi/lo head-out
    {
        int n4 = (B_DIM * S_DIM * E_DIM) / 4;
        merge_kernel<<<(n4 + 255) / 256, 256>>>(opart, pmv, plv, hoh, hol);
    }

    // 3) out = headout @ w_proj^T  (fp32 final output)
    {
        dim3 grid(E_DIM / 128, (B_DIM * S_DIM) / 128);
        gemm_bf<<<grid, 256, gemm_smem>>>(hoh, hol, wph, wpl,
                                          out, nullptr, nullptr, E_DIM, E_DIM);
    }
}